// round 13
// baseline (speedup 1.0000x reference)
#include <cuda_runtime.h>
#include <cuda_fp16.h>
#include <math.h>
#include <stdint.h>

// ---------------------------------------------------------------------------
// Problem constants
// ---------------------------------------------------------------------------
#define BDIM   8192
#define DDIM   1024
#define HDIM   2048
#define H2DIM  1024
#define CDIM   1000
#define KDIM   128
#define EDIM   8
#define TOPK   2
#define MAXROWS (BDIM * TOPK)

// ---------------------------------------------------------------------------
// Scratch (device globals — no allocation allowed)
// ---------------------------------------------------------------------------
__device__ __half g_xhi  [(size_t)BDIM * DDIM];
__device__ __half g_xlo  [(size_t)BDIM * DDIM];
__device__ __half g_hhi  [(size_t)BDIM * HDIM];
__device__ __half g_hlo  [(size_t)BDIM * HDIM];
__device__ __half g_featshi[(size_t)BDIM * HDIM];
__device__ float  g_pk   [(size_t)BDIM * KDIM];
__device__ float  g_keysn[EDIM * KDIM];
__device__ float  g_sim  [BDIM * EDIM];
__device__ float  g_weights[BDIM * EDIM];
__device__ float  g_wslot[BDIM * TOPK];
__device__ int    g_topi [BDIM * TOPK];
__device__ int    g_counts[EDIM];
__device__ int    g_offsets[EDIM + 1];
__device__ int    g_cursor[EDIM];
__device__ int    g_list [MAXROWS];
__device__ int    g_pos  [BDIM * TOPK];
__device__ __half g_h1h  [(size_t)MAXROWS * HDIM];
__device__ __half g_h2h  [(size_t)MAXROWS * H2DIM];
__device__ float  g_eout [(size_t)MAXROWS * CDIM];
// converted weights
__device__ __half g_fw1hi[(size_t)HDIM * DDIM];   // fw1^T split  [H][D]
__device__ __half g_fw1lo[(size_t)HDIM * DDIM];
__device__ __half g_fw2h [(size_t)HDIM * HDIM];   // fw2^T single [Hout][Hin]
__device__ __half g_fw2nhi[(size_t)HDIM * HDIM];  // fw2 natural split [Hin][Hout]
__device__ __half g_fw2nlo[(size_t)HDIM * HDIM];
__device__ __half g_kwhi [(size_t)KDIM * HDIM];   // kw^T split   [K][H]
__device__ __half g_kwlo [(size_t)KDIM * HDIM];
__device__ __half g_wphi [(size_t)KDIM * HDIM];   // W'^T split   [K][H]
__device__ __half g_wplo [(size_t)KDIM * HDIM];
__device__ float  g_bp   [KDIM];                  // b' = fb2@kw + kb
__device__ float  g_zbias[HDIM];                  // zeros (static init)
__device__ __half g_ew1h [(size_t)EDIM * HDIM  * HDIM];
__device__ __half g_ew2h [(size_t)EDIM * H2DIM * HDIM];
__device__ __half g_ew3h [(size_t)EDIM * CDIM  * H2DIM];

#define LO_SCALE 4096.0f
#define LO_INV   (1.0f / 4096.0f)

// ---------------------------------------------------------------------------
// helpers
// ---------------------------------------------------------------------------
__device__ __forceinline__ void mma_f16(float c[4],
                                        const uint32_t a[4],
                                        const uint32_t b[2]) {
    asm volatile(
        "mma.sync.aligned.m16n8k16.row.col.f32.f16.f16.f32 "
        "{%0,%1,%2,%3}, {%4,%5,%6,%7}, {%8,%9}, {%0,%1,%2,%3};"
        : "+f"(c[0]), "+f"(c[1]), "+f"(c[2]), "+f"(c[3])
        : "r"(a[0]), "r"(a[1]), "r"(a[2]), "r"(a[3]),
          "r"(b[0]), "r"(b[1]));
}
__device__ __forceinline__ void cp16(void* dst, const void* src, bool valid) {
    uint32_t d = (uint32_t)__cvta_generic_to_shared(dst);
    int sz = valid ? 16 : 0;
    asm volatile("cp.async.cg.shared.global [%0], [%1], 16, %2;"
                 :: "r"(d), "l"(src), "r"(sz));
}
__device__ __forceinline__ void split_f32(float v, __half& hi, __half& lo) {
    hi = __float2half(v);
    lo = __float2half((v - __half2float(hi)) * LO_SCALE);
}

// ---------------------------------------------------------------------------
// One-time conversions (R12-verbatim, minus the wconv launches now fused)
// ---------------------------------------------------------------------------
__global__ void natsplit_k(const float* __restrict__ W,
                           __half* __restrict__ Whi, __half* __restrict__ Wlo)
{
    size_t i = ((size_t)blockIdx.x * 256 + threadIdx.x) * 4;
    float4 v = *(const float4*)(W + i);
    __half h0, l0, h1, l1, h2, l2, h3, l3;
    split_f32(v.x, h0, l0); split_f32(v.y, h1, l1);
    split_f32(v.z, h2, l2); split_f32(v.w, h3, l3);
    *(__half2*)&Whi[i]     = __halves2half2(h0, h1);
    *(__half2*)&Whi[i + 2] = __halves2half2(h2, h3);
    *(__half2*)&Wlo[i]     = __halves2half2(l0, l1);
    *(__half2*)&Wlo[i + 2] = __halves2half2(l2, l3);
}

__global__ void wsplit_k(const float* __restrict__ W,
                         __half* __restrict__ Whi, __half* __restrict__ Wlo,
                         int K, int N)
{
    __shared__ float t[32][33];
    int k0 = blockIdx.y * 32;
    int n0 = blockIdx.x * 32;
#pragma unroll
    for (int j = 0; j < 4; j++)
        t[threadIdx.y + j * 8][threadIdx.x] =
            W[(size_t)(k0 + threadIdx.y + j * 8) * N + n0 + threadIdx.x];
    __syncthreads();
#pragma unroll
    for (int j = 0; j < 4; j++) {
        int n = n0 + threadIdx.y + j * 8;
        int k = k0 + threadIdx.x;
        float val = t[threadIdx.x][threadIdx.y + j * 8];
        __half hi, lo;
        split_f32(val, hi, lo);
        Whi[(size_t)n * K + k] = hi;
        Wlo[(size_t)n * K + k] = lo;
    }
}

__global__ void bprime_k(const float* __restrict__ fb2,
                         const float* __restrict__ kw,
                         const float* __restrict__ kb)
{
    int j = blockIdx.x;
    float s = 0.f;
    for (int m = threadIdx.x; m < HDIM; m += 256)
        s += fb2[m] * kw[(size_t)m * KDIM + j];
    __shared__ float red[8];
#pragma unroll
    for (int o = 16; o; o >>= 1) s += __shfl_xor_sync(0xffffffffu, s, o);
    if ((threadIdx.x & 31) == 0) red[threadIdx.x >> 5] = s;
    __syncthreads();
    if (threadIdx.x == 0) {
        float t = 0.f;
#pragma unroll
        for (int w = 0; w < 8; w++) t += red[w];
        g_bp[j] = t + kb[j];
    }
}

// ---------------------------------------------------------------------------
// Transpose-convert one 32x32 tile: W[K][N] fp32 -> Wt[N][K] half.
// Verbatim R12 wconv tile body (flat 256-thread block, ly=tid>>5, lx=tid&31).
// Trailing __syncthreads allows reuse of the shared buffer across tiles.
// ---------------------------------------------------------------------------
__device__ __forceinline__ void conv_tile(const float* __restrict__ W,
                                          __half* __restrict__ Wt,
                                          int K, int N, int k0, int n0,
                                          float (*t)[33])
{
    int lx = threadIdx.x & 31;
    int ly = threadIdx.x >> 5;
#pragma unroll
    for (int j = 0; j < 4; j++) {
        int n = n0 + lx;
        if (n < N) t[ly + j * 8][lx] = W[(size_t)(k0 + ly + j * 8) * N + n];
    }
    __syncthreads();
#pragma unroll
    for (int j = 0; j < 4; j++) {
        int n = n0 + ly + j * 8;
        int k = k0 + lx;
        if (n < N) Wt[(size_t)n * K + k] = __float2half(t[lx][ly + j * 8]);
    }
    __syncthreads();
}

// ---------------------------------------------------------------------------
// fp16 2-term-split GEMM (R12-verbatim; STAGE 7 only now)
// ---------------------------------------------------------------------------
#define SBK 32

template<int STAGE, bool RELU>
__global__ __launch_bounds__(256) void sgemm_k(const __half* __restrict__ Whi,
                                               const __half* __restrict__ Wlo,
                                               const float* __restrict__ Bias,
                                               int N, int Kd)
{
    extern __shared__ __half sms[];
    __half (*S)[2][128][40] = (__half(*)[2][128][40])sms;

    const __half *Ahi, *Alo;
    if (STAGE == 0)      { Ahi = g_xhi;  Alo = g_xlo;  }
    else if (STAGE == 2) { Ahi = g_hhi;  Alo = g_hlo;  }
    else                 { Ahi = g_kwhi; Alo = g_kwlo; }

    const int tileM = blockIdx.y * 128;
    const int tileN = blockIdx.x * 128;

    const int tid  = threadIdx.x;
    const int lane = tid & 31;
    const int wid  = tid >> 5;
    const int g    = lane >> 2;
    const int tig  = lane & 3;
    const int warpM = wid & 1;
    const int warpN = wid >> 1;

    const int rr = tid >> 2;
    const int cc = (tid & 3) * 8;

    const size_t aoff = (size_t)(tileM + rr) * Kd + cc;
    const size_t boff = (size_t)(tileN + rr) * Kd + cc;
    const size_t rstep = (size_t)64 * Kd;

    float acc [4][4][4];
    float accx[4][4][4];
#pragma unroll
    for (int i = 0; i < 4; i++)
#pragma unroll
        for (int j = 0; j < 4; j++)
#pragma unroll
            for (int r = 0; r < 4; r++) { acc[i][j][r] = 0.f; accx[i][j][r] = 0.f; }

    const int KT = Kd / SBK;

    auto load_tile = [&](int k0, int buf) {
#pragma unroll
        for (int it = 0; it < 2; it++) {
            cp16(&S[0][buf][rr + it * 64][cc], Ahi + aoff + it * rstep + k0, true);
            cp16(&S[1][buf][rr + it * 64][cc], Alo + aoff + it * rstep + k0, true);
            cp16(&S[2][buf][rr + it * 64][cc], Whi + boff + it * rstep + k0, true);
            cp16(&S[3][buf][rr + it * 64][cc], Wlo + boff + it * rstep + k0, true);
        }
        asm volatile("cp.async.commit_group;");
    };

    load_tile(0, 0);

    for (int kt = 0; kt < KT; kt++) {
        const int buf = kt & 1;
        if (kt + 1 < KT) {
            load_tile((kt + 1) * SBK, (kt + 1) & 1);
            asm volatile("cp.async.wait_group 1;");
        } else {
            asm volatile("cp.async.wait_group 0;");
        }
        __syncthreads();

#pragma unroll
        for (int ks = 0; ks < 2; ks++) {
            const int k16 = ks * 16;
            uint32_t bh[4][2], bl[4][2];
#pragma unroll
            for (int nf = 0; nf < 4; nf++) {
                int n = warpN * 32 + nf * 8 + g;
                bh[nf][0] = *(const uint32_t*)&S[2][buf][n][k16 + 2 * tig    ];
                bh[nf][1] = *(const uint32_t*)&S[2][buf][n][k16 + 2 * tig + 8];
                bl[nf][0] = *(const uint32_t*)&S[3][buf][n][k16 + 2 * tig    ];
                bl[nf][1] = *(const uint32_t*)&S[3][buf][n][k16 + 2 * tig + 8];
            }
#pragma unroll
            for (int mf = 0; mf < 4; mf++) {
                int m = warpM * 64 + mf * 16 + g;
                uint32_t ah[4], al[4];
                ah[0] = *(const uint32_t*)&S[0][buf][m    ][k16 + 2 * tig    ];
                ah[1] = *(const uint32_t*)&S[0][buf][m + 8][k16 + 2 * tig    ];
                ah[2] = *(const uint32_t*)&S[0][buf][m    ][k16 + 2 * tig + 8];
                ah[3] = *(const uint32_t*)&S[0][buf][m + 8][k16 + 2 * tig + 8];
                al[0] = *(const uint32_t*)&S[1][buf][m    ][k16 + 2 * tig    ];
                al[1] = *(const uint32_t*)&S[1][buf][m + 8][k16 + 2 * tig    ];
                al[2] = *(const uint32_t*)&S[1][buf][m    ][k16 + 2 * tig + 8];
                al[3] = *(const uint32_t*)&S[1][buf][m + 8][k16 + 2 * tig + 8];
#pragma unroll
                for (int nf = 0; nf < 4; nf++) {
                    mma_f16(acc [mf][nf], ah, bh[nf]);
                    mma_f16(accx[mf][nf], ah, bl[nf]);
                    mma_f16(accx[mf][nf], al, bh[nf]);
                }
            }
        }
        __syncthreads();
    }

#pragma unroll
    for (int mf = 0; mf < 4; mf++) {
        int row0 = tileM + warpM * 64 + mf * 16 + g;
        int row1 = row0 + 8;
#pragma unroll
        for (int nf = 0; nf < 4; nf++) {
            int col0 = tileN + warpN * 32 + nf * 8 + tig * 2;
            int col1 = col0 + 1;
            float b0 = Bias[col0];
            float b1 = Bias[col1];
            float v00 = acc[mf][nf][0] + accx[mf][nf][0] * LO_INV + b0;
            float v01 = acc[mf][nf][1] + accx[mf][nf][1] * LO_INV + b1;
            float v10 = acc[mf][nf][2] + accx[mf][nf][2] * LO_INV + b0;
            float v11 = acc[mf][nf][3] + accx[mf][nf][3] * LO_INV + b1;
            if (RELU) {
                v00 = fmaxf(v00, 0.f); v01 = fmaxf(v01, 0.f);
                v10 = fmaxf(v10, 0.f); v11 = fmaxf(v11, 0.f);
            }
            if (STAGE == 2) {
                g_pk[(size_t)row0 * N + col0] = v00;
                g_pk[(size_t)row0 * N + col1] = v01;
                g_pk[(size_t)row1 * N + col0] = v10;
                g_pk[(size_t)row1 * N + col1] = v11;
            } else {
                __half* Hi = (STAGE == 0) ? g_hhi : g_wphi;
                __half* Lo = (STAGE == 0) ? g_hlo : g_wplo;
                __half h, l;
                split_f32(v00, h, l);
                Hi[(size_t)row0 * N + col0] = h; Lo[(size_t)row0 * N + col0] = l;
                split_f32(v01, h, l);
                Hi[(size_t)row0 * N + col1] = h; Lo[(size_t)row0 * N + col1] = l;
                split_f32(v10, h, l);
                Hi[(size_t)row1 * N + col0] = h; Lo[(size_t)row1 * N + col0] = l;
                split_f32(v11, h, l);
                Hi[(size_t)row1 * N + col1] = h; Lo[(size_t)row1 * N + col1] = l;
            }
        }
    }
}

// ---------------------------------------------------------------------------
// NEW: stage0 GEMM + fused conversions (ew1 + fw2h) as blockIdx.z==1 plane.
//   z==0 (16x64 blocks) : verbatim R12 sgemm_k<0,true> body
//   z==1 (16x64 blocks) : 36 conversion tiles each
//                         tiles [0,32768) = ew1, [32768,36864) = fw2^T
// ---------------------------------------------------------------------------
__global__ __launch_bounds__(256) void stage0c_k(const __half* __restrict__ Whi,
                                                 const __half* __restrict__ Wlo,
                                                 const float* __restrict__ fb1,
                                                 const float* __restrict__ ew1,
                                                 const float* __restrict__ fw2)
{
    extern __shared__ __half sms[];

    if (blockIdx.z == 1) {
        __shared__ float tbuf[32][33];
        int b = blockIdx.y * 16 + blockIdx.x;       // 0..1023
#pragma unroll 1
        for (int ti = 0; ti < 36; ti++) {
            int gidx = b * 36 + ti;                 // 0..36863
            if (gidx < 32768) {
                int z = gidx >> 12;                 // expert
                int tile = gidx & 4095;             // 64x64 tiles
                int n0 = (tile & 63) * 32;
                int k0 = (tile >> 6) * 32;
                conv_tile(ew1 + (size_t)z * HDIM * HDIM,
                          g_ew1h + (size_t)z * HDIM * HDIM,
                          HDIM, HDIM, k0, n0, tbuf);
            } else {
                int tile = gidx - 32768;            // 64x64 tiles
                int n0 = (tile & 63) * 32;
                int k0 = (tile >> 6) * 32;
                conv_tile(fw2, g_fw2h, HDIM, HDIM, k0, n0, tbuf);
            }
        }
        return;
    }

    // ----- z==0: stage0 GEMM (R12 sgemm STAGE=0 verbatim) -----
    __half (*S)[2][128][40] = (__half(*)[2][128][40])sms;
    const __half* Ahi = g_xhi;
    const __half* Alo = g_xlo;
    const int N  = HDIM;
    const int Kd = DDIM;

    const int tileM = blockIdx.y * 128;
    const int tileN = blockIdx.x * 128;

    const int tid  = threadIdx.x;
    const int lane = tid & 31;
    const int wid  = tid >> 5;
    const int g    = lane >> 2;
    const int tig  = lane & 3;
    const int warpM = wid & 1;
    const int warpN = wid >> 1;

    const int rr = tid >> 2;
    const int cc = (tid & 3) * 8;

    const size_t aoff = (size_t)(tileM + rr) * Kd + cc;
    const size_t boff = (size_t)(tileN + rr) * Kd + cc;
    const size_t rstep = (size_t)64 * Kd;

    float acc [4][4][4];
    float accx[4][4][4];
#pragma unroll
    for (int i = 0; i < 4; i++)
#pragma unroll
        for (int j = 0; j < 4; j++)
#pragma unroll
            for (int r = 0; r < 4; r++) { acc[i][j][r] = 0.f; accx[i][j][r] = 0.f; }

    const int KT = Kd / SBK;

    auto load_tile = [&](int k0, int buf) {
#pragma unroll
        for (int it = 0; it < 2; it++) {
            cp16(&S[0][buf][rr + it * 64][cc], Ahi + aoff + it * rstep + k0, true);
            cp16(&S[1][buf][rr + it * 64][cc], Alo + aoff + it * rstep + k0, true);
            cp16(&S[2][buf][rr + it * 64][cc], Whi + boff + it * rstep + k0, true);
            cp16(&S[3][buf][rr + it * 64][cc], Wlo + boff + it * rstep + k0, true);
        }
        asm volatile("cp.async.commit_group;");
    };

    load_tile(0, 0);

    for (int kt = 0; kt < KT; kt++) {
        const int buf = kt & 1;
        if (kt + 1 < KT) {
            load_tile((kt + 1) * SBK, (kt + 1) & 1);
            asm volatile("cp.async.wait_group 1;");
        } else {
            asm volatile("cp.async.wait_group 0;");
        }
        __syncthreads();

#pragma unroll
        for (int ks = 0; ks < 2; ks++) {
            const int k16 = ks * 16;
            uint32_t bh[4][2], bl[4][2];
#pragma unroll
            for (int nf = 0; nf < 4; nf++) {
                int n = warpN * 32 + nf * 8 + g;
                bh[nf][0] = *(const uint32_t*)&S[2][buf][n][k16 + 2 * tig    ];
                bh[nf][1] = *(const uint32_t*)&S[2][buf][n][k16 + 2 * tig + 8];
                bl[nf][0] = *(const uint32_t*)&S[3][buf][n][k16 + 2 * tig    ];
                bl[nf][1] = *(const uint32_t*)&S[3][buf][n][k16 + 2 * tig + 8];
            }
#pragma unroll
            for (int mf = 0; mf < 4; mf++) {
                int m = warpM * 64 + mf * 16 + g;
                uint32_t ah[4], al[4];
                ah[0] = *(const uint32_t*)&S[0][buf][m    ][k16 + 2 * tig    ];
                ah[1] = *(const uint32_t*)&S[0][buf][m + 8][k16 + 2 * tig    ];
                ah[2] = *(const uint32_t*)&S[0][buf][m    ][k16 + 2 * tig + 8];
                ah[3] = *(const uint32_t*)&S[0][buf][m + 8][k16 + 2 * tig + 8];
                al[0] = *(const uint32_t*)&S[1][buf][m    ][k16 + 2 * tig    ];
                al[1] = *(const uint32_t*)&S[1][buf][m + 8][k16 + 2 * tig    ];
                al[2] = *(const uint32_t*)&S[1][buf][m    ][k16 + 2 * tig + 8];
                al[3] = *(const uint32_t*)&S[1][buf][m + 8][k16 + 2 * tig + 8];
#pragma unroll
                for (int nf = 0; nf < 4; nf++) {
                    mma_f16(acc [mf][nf], ah, bh[nf]);
                    mma_f16(accx[mf][nf], ah, bl[nf]);
                    mma_f16(accx[mf][nf], al, bh[nf]);
                }
            }
        }
        __syncthreads();
    }

#pragma unroll
    for (int mf = 0; mf < 4; mf++) {
        int row0 = tileM + warpM * 64 + mf * 16 + g;
        int row1 = row0 + 8;
#pragma unroll
        for (int nf = 0; nf < 4; nf++) {
            int col0 = tileN + warpN * 32 + nf * 8 + tig * 2;
            int col1 = col0 + 1;
            float b0 = fb1[col0];
            float b1 = fb1[col1];
            float v00 = fmaxf(acc[mf][nf][0] + accx[mf][nf][0] * LO_INV + b0, 0.f);
            float v01 = fmaxf(acc[mf][nf][1] + accx[mf][nf][1] * LO_INV + b1, 0.f);
            float v10 = fmaxf(acc[mf][nf][2] + accx[mf][nf][2] * LO_INV + b0, 0.f);
            float v11 = fmaxf(acc[mf][nf][3] + accx[mf][nf][3] * LO_INV + b1, 0.f);
            __half h, l;
            split_f32(v00, h, l);
            g_hhi[(size_t)row0 * N + col0] = h; g_hlo[(size_t)row0 * N + col0] = l;
            split_f32(v01, h, l);
            g_hhi[(size_t)row0 * N + col1] = h; g_hlo[(size_t)row0 * N + col1] = l;
            split_f32(v10, h, l);
            g_hhi[(size_t)row1 * N + col0] = h; g_hlo[(size_t)row1 * N + col0] = l;
            split_f32(v11, h, l);
            g_hhi[(size_t)row1 * N + col1] = h; g_hlo[(size_t)row1 * N + col1] = l;
        }
    }
}

// ---------------------------------------------------------------------------
// Pure fp16 GEMM (R12-verbatim; expert stages 3/4/5)
// ---------------------------------------------------------------------------
#define HBK 64

template<int STAGE, bool RELU>
__global__ __launch_bounds__(256) void hgemm_k(const __half* __restrict__ Wt,
                                               const float* __restrict__ Biasg,
                                               int N, int Kd)
{
    extern __shared__ __half smh[];
    __half (*Ah)[128][72] = (__half(*)[128][72])smh;
    __half (*Bh)[128][72] = (__half(*)[128][72])(smh + 2 * 128 * 72);

    int M;
    const __half* B;
    const float* Bias;
    const __half* A;
    __half* Ch = nullptr;
    float*  Cf = nullptr;
    const int* gather = nullptr;

    {
        int e  = blockIdx.z;
        int m0 = g_offsets[e];
        M = g_offsets[e + 1] - m0;
        B    = Wt    + (size_t)e * N * Kd;
        Bias = Biasg + (size_t)e * N;
        if (STAGE == 3)      { A = g_featshi; gather = g_list + m0; Ch = g_h1h + (size_t)m0 * N; }
        else if (STAGE == 4) { A = g_h1h + (size_t)m0 * Kd;         Ch = g_h2h + (size_t)m0 * N; }
        else                 { A = g_h2h + (size_t)m0 * Kd;         Cf = g_eout + (size_t)m0 * N; }
    }

    const int tileM = blockIdx.y * 128;
    if (tileM >= M) return;
    const int tileN = blockIdx.x * 128;

    const int tid  = threadIdx.x;
    const int lane = tid & 31;
    const int wid  = tid >> 5;
    const int g    = lane >> 2;
    const int tig  = lane & 3;
    const int warpM = wid & 1;
    const int warpN = wid >> 1;

    const __half* aptr[4];
    bool av[4];
#pragma unroll
    for (int it = 0; it < 4; it++) {
        int r = (tid >> 3) + it * 32;
        int grow = tileM + r;
        av[it] = (grow < M);
        size_t arow = 0;
        if (av[it]) arow = (STAGE == 3) ? (size_t)gather[grow] : (size_t)grow;
        aptr[it] = A + arow * Kd + (tid & 7) * 8;
    }
    const __half* bptr[4];
    bool bvv[4];
#pragma unroll
    for (int it = 0; it < 4; it++) {
        int r = (tid >> 3) + it * 32;
        int gn = tileN + r;
        bvv[it] = (gn < N);
        bptr[it] = B + (size_t)(bvv[it] ? gn : 0) * Kd + (tid & 7) * 8;
    }

    float acc[4][4][4];
#pragma unroll
    for (int i = 0; i < 4; i++)
#pragma unroll
        for (int j = 0; j < 4; j++)
#pragma unroll
            for (int r = 0; r < 4; r++) acc[i][j][r] = 0.f;

    const int KT = Kd / HBK;

    auto load_tile = [&](int k0, int buf) {
#pragma unroll
        for (int it = 0; it < 4; it++) {
            int r = (tid >> 3) + it * 32;
            cp16(&Ah[buf][r][(tid & 7) * 8], aptr[it] + k0, av[it]);
        }
#pragma unroll
        for (int it = 0; it < 4; it++) {
            int r = (tid >> 3) + it * 32;
            cp16(&Bh[buf][r][(tid & 7) * 8], bptr[it] + k0, bvv[it]);
        }
        asm volatile("cp.async.commit_group;");
    };

    load_tile(0, 0);

    for (int kt = 0; kt < KT; kt++) {
        const int buf = kt & 1;
        if (kt + 1 < KT) {
            load_tile((kt + 1) * HBK, (kt + 1) & 1);
            asm volatile("cp.async.wait_group 1;");
        } else {
            asm volatile("cp.async.wait_group 0;");
        }
        __syncthreads();

#pragma unroll
        for (int ks = 0; ks < 4; ks++) {
            const int k16 = ks * 16;
            uint32_t bf[4][2];
#pragma unroll
            for (int nf = 0; nf < 4; nf++) {
                int n = warpN * 32 + nf * 8 + g;
                bf[nf][0] = *(const uint32_t*)&Bh[buf][n][k16 + 2 * tig    ];
                bf[nf][1] = *(const uint32_t*)&Bh[buf][n][k16 + 2 * tig + 8];
            }
#pragma unroll
            for (int mf = 0; mf < 4; mf++) {
                int m = warpM * 64 + mf * 16 + g;
                uint32_t af[4];
                af[0] = *(const uint32_t*)&Ah[buf][m    ][k16 + 2 * tig    ];
                af[1] = *(const uint32_t*)&Ah[buf][m + 8][k16 + 2 * tig    ];
                af[2] = *(const uint32_t*)&Ah[buf][m    ][k16 + 2 * tig + 8];
                af[3] = *(const uint32_t*)&Ah[buf][m + 8][k16 + 2 * tig + 8];
#pragma unroll
                for (int nf = 0; nf < 4; nf++)
                    mma_f16(acc[mf][nf], af, bf[nf]);
            }
        }
        __syncthreads();
    }

#pragma unroll
    for (int mf = 0; mf < 4; mf++) {
        int row0 = tileM + warpM * 64 + mf * 16 + g;
        int row1 = row0 + 8;
#pragma unroll
        for (int nf = 0; nf < 4; nf++) {
            int col0 = tileN + warpN * 32 + nf * 8 + tig * 2;
            int col1 = col0 + 1;
            float b0 = (col0 < N) ? Bias[col0] : 0.f;
            float b1 = (col1 < N) ? Bias[col1] : 0.f;
            float v00 = acc[mf][nf][0] + b0;
            float v01 = acc[mf][nf][1] + b1;
            float v10 = acc[mf][nf][2] + b0;
            float v11 = acc[mf][nf][3] + b1;
            if (RELU) {
                v00 = fmaxf(v00, 0.f); v01 = fmaxf(v01, 0.f);
                v10 = fmaxf(v10, 0.f); v11 = fmaxf(v11, 0.f);
            }
            if (STAGE == 5) {
                if (row0 < M) {
                    if (col0 < N) Cf[(size_t)row0 * N + col0] = v00;
                    if (col1 < N) Cf[(size_t)row0 * N + col1] = v01;
                }
                if (row1 < M) {
                    if (col0 < N) Cf[(size_t)row1 * N + col0] = v10;
                    if (col1 < N) Cf[(size_t)row1 * N + col1] = v11;
                }
            } else {
                if (row0 < M) {
                    if (col0 < N) Ch[(size_t)row0 * N + col0] = __float2half(v00);
                    if (col1 < N) Ch[(size_t)row0 * N + col1] = __float2half(v01);
                }
                if (row1 < M) {
                    if (col0 < N) Ch[(size_t)row1 * N + col0] = __float2half(v10);
                    if (col1 < N) Ch[(size_t)row1 * N + col1] = __float2half(v11);
                }
            }
        }
    }
}

// ---------------------------------------------------------------------------
// stage1 + stage2 fused (R12-verbatim) + NEW z==1 conversion plane (ew2, ew3)
// Grid (17, 64, 2). z==1: 1088 blocks x 23 tiles; [0,16384)=ew2, then ew3.
// ---------------------------------------------------------------------------
__global__ __launch_bounds__(256) void fused12_k(const float* __restrict__ fb2,
                                                 const float* __restrict__ ew2,
                                                 const float* __restrict__ ew3)
{
    extern __shared__ __half smf[];

    if (blockIdx.z == 1) {
        __shared__ float tbuf[32][33];
        int b = blockIdx.y * 17 + blockIdx.x;       // 0..1087
#pragma unroll 1
        for (int ti = 0; ti < 23; ti++) {
            int gidx = b * 23 + ti;
            if (gidx >= 24576) break;
            if (gidx < 16384) {                     // ew2: K=2048, N=1024, 32x64 tiles
                int z = gidx >> 11;
                int tile = gidx & 2047;
                int n0 = (tile & 31) * 32;
                int k0 = (tile >> 5) * 32;
                conv_tile(ew2 + (size_t)z * HDIM * H2DIM,
                          g_ew2h + (size_t)z * H2DIM * HDIM,
                          HDIM, H2DIM, k0, n0, tbuf);
            } else {                                // ew3: K=1024, N=1000, 32x32 tiles
                int g2 = gidx - 16384;
                int z = g2 >> 10;
                int tile = g2 & 1023;
                int n0 = (tile & 31) * 32;
                int k0 = (tile >> 5) * 32;
                conv_tile(ew3 + (size_t)z * H2DIM * CDIM,
                          g_ew3h + (size_t)z * CDIM * H2DIM,
                          H2DIM, CDIM, k0, n0, tbuf);
            }
        }
        return;
    }

    const int tid  = threadIdx.x;
    const int lane = tid & 31;
    const int wid  = tid >> 5;
    const int g    = lane >> 2;
    const int tig  = lane & 3;
    const int warpM = wid & 1;
    const int warpN = wid >> 1;

    if (blockIdx.x == 0) {
        // ----- stage2: split GEMM, tileN=0, N=KDIM, Kd=HDIM -----
        __half (*S)[2][128][40] = (__half(*)[2][128][40])smf;
        const __half* Ahi = g_hhi;
        const __half* Alo = g_hlo;
        const __half* Whi = g_wphi;
        const __half* Wlo = g_wplo;
        const int N  = KDIM;
        const int Kd = HDIM;
        const int tileM = blockIdx.y * 128;
        const int tileN = 0;

        const int rr = tid >> 2;
        const int cc = (tid & 3) * 8;
        const size_t aoff = (size_t)(tileM + rr) * Kd + cc;
        const size_t boff = (size_t)(tileN + rr) * Kd + cc;
        const size_t rstep = (size_t)64 * Kd;

        float acc [4][4][4];
        float accx[4][4][4];
#pragma unroll
        for (int i = 0; i < 4; i++)
#pragma unroll
            for (int j = 0; j < 4; j++)
#pragma unroll
                for (int r = 0; r < 4; r++) { acc[i][j][r] = 0.f; accx[i][j][r] = 0.f; }

        const int KT = Kd / SBK;

        auto load_tile = [&](int k0, int buf) {
#pragma unroll
            for (int it = 0; it < 2; it++) {
                cp16(&S[0][buf][rr + it * 64][cc], Ahi + aoff + it * rstep + k0, true);
                cp16(&S[1][buf][rr + it * 64][cc], Alo + aoff + it * rstep + k0, true);
                cp16(&S[2][buf][rr + it * 64][cc], Whi + boff + it * rstep + k0, true);
                cp16(&S[3][buf][rr + it * 64][cc], Wlo + boff + it * rstep + k0, true);
            }
            asm volatile("cp.async.commit_group;");
        };

        load_tile(0, 0);

        for (int kt = 0; kt < KT; kt++) {
            const int buf = kt & 1;
            if (kt + 1 < KT) {
                load_tile((kt + 1) * SBK, (kt + 1) & 1);
                asm volatile("cp.async.wait_group 1;");
            } else {
                asm volatile("cp.async.wait_group 0;");
            }
            __syncthreads();

#pragma unroll
            for (int ks = 0; ks < 2; ks++) {
                const int k16 = ks * 16;
                uint32_t bh[4][2], bl[4][2];
#pragma unroll
                for (int nf = 0; nf < 4; nf++) {
                    int n = warpN * 32 + nf * 8 + g;
                    bh[nf][0] = *(const uint32_t*)&S[2][buf][n][k16 + 2 * tig    ];
                    bh[nf][1] = *(const uint32_t*)&S[2][buf][n][k16 + 2 * tig + 8];
                    bl[nf][0] = *(const uint32_t*)&S[3][buf][n][k16 + 2 * tig    ];
                    bl[nf][1] = *(const uint32_t*)&S[3][buf][n][k16 + 2 * tig + 8];
                }
#pragma unroll
                for (int mf = 0; mf < 4; mf++) {
                    int m = warpM * 64 + mf * 16 + g;
                    uint32_t ah[4], al[4];
                    ah[0] = *(const uint32_t*)&S[0][buf][m    ][k16 + 2 * tig    ];
                    ah[1] = *(const uint32_t*)&S[0][buf][m + 8][k16 + 2 * tig    ];
                    ah[2] = *(const uint32_t*)&S[0][buf][m    ][k16 + 2 * tig + 8];
                    ah[3] = *(const uint32_t*)&S[0][buf][m + 8][k16 + 2 * tig + 8];
                    al[0] = *(const uint32_t*)&S[1][buf][m    ][k16 + 2 * tig    ];
                    al[1] = *(const uint32_t*)&S[1][buf][m + 8][k16 + 2 * tig    ];
                    al[2] = *(const uint32_t*)&S[1][buf][m    ][k16 + 2 * tig + 8];
                    al[3] = *(const uint32_t*)&S[1][buf][m + 8][k16 + 2 * tig + 8];
#pragma unroll
                    for (int nf = 0; nf < 4; nf++) {
                        mma_f16(acc [mf][nf], ah, bh[nf]);
                        mma_f16(accx[mf][nf], ah, bl[nf]);
                        mma_f16(accx[mf][nf], al, bh[nf]);
                    }
                }
            }
            __syncthreads();
        }

#pragma unroll
        for (int mf = 0; mf < 4; mf++) {
            int row0 = tileM + warpM * 64 + mf * 16 + g;
            int row1 = row0 + 8;
#pragma unroll
            for (int nf = 0; nf < 4; nf++) {
                int col0 = tileN + warpN * 32 + nf * 8 + tig * 2;
                int col1 = col0 + 1;
                float b0 = g_bp[col0];
                float b1 = g_bp[col1];
                g_pk[(size_t)row0 * N + col0] = acc[mf][nf][0] + accx[mf][nf][0] * LO_INV + b0;
                g_pk[(size_t)row0 * N + col1] = acc[mf][nf][1] + accx[mf][nf][1] * LO_INV + b1;
                g_pk[(size_t)row1 * N + col0] = acc[mf][nf][2] + accx[mf][nf][2] * LO_INV + b0;
                g_pk[(size_t)row1 * N + col1] = acc[mf][nf][3] + accx[mf][nf][3] * LO_INV + b1;
            }
        }
    } else {
        // ----- stage1: fp16 GEMM h @ fw2 -> g_featshi -----
        __half (*Ah)[128][72] = (__half(*)[128][72])smf;
        __half (*Bh)[128][72] = (__half(*)[128][72])(smf + 2 * 128 * 72);

        const __half* A = g_hhi;
        const __half* B = g_fw2h;
        const int N  = HDIM;
        const int Kd = HDIM;
        const int tileM = blockIdx.y * 128;
        const int tileN = (blockIdx.x - 1) * 128;

        const __half* aptr[4];
#pragma unroll
        for (int it = 0; it < 4; it++) {
            int r = (tid >> 3) + it * 32;
            aptr[it] = A + (size_t)(tileM + r) * Kd + (tid & 7) * 8;
        }
        const __half* bptr[4];
#pragma unroll
        for (int it = 0; it < 4; it++) {
            int r = (tid >> 3) + it * 32;
            bptr[it] = B + (size_t)(tileN + r) * Kd + (tid & 7) * 8;
        }

        float acc[4][4][4];
#pragma unroll
        for (int i = 0; i < 4; i++)
#pragma unroll
            for (int j = 0; j < 4; j++)
#pragma unroll
                for (int r = 0; r < 4; r++) acc[i][j][r] = 0.f;

        const int KT = Kd / HBK;

        auto load_tile = [&](int k0, int buf) {
#pragma unroll
            for (int it = 0; it < 4; it++) {
                int r = (tid >> 3) + it * 32;
                cp16(&Ah[buf][r][(tid & 7) * 8], aptr[it] + k0, true);
            }
#pragma unroll
            for (int it = 0; it < 4; it++) {
                int r = (tid >> 3) + it * 32;
                cp16(&Bh[buf][r][(tid & 7) * 8], bptr[it] + k0, true);
            }
            asm volatile("cp.async.commit_group;");
        };

        load_tile(0, 0);

        for (int kt = 0; kt < KT; kt++) {
            const int buf = kt & 1;
            if (kt + 1 < KT) {
                load_tile((kt + 1) * HBK, (kt + 1) & 1);
                asm volatile("cp.async.wait_group 1;");
            } else {
                asm volatile("cp.async.wait_group 0;");
            }
            __syncthreads();

#pragma unroll
            for (int ks = 0; ks < 4; ks++) {
                const int k16 = ks * 16;
                uint32_t bf[4][2];
#pragma unroll
                for (int nf = 0; nf < 4; nf++) {
                    int n = warpN * 32 + nf * 8 + g;
                    bf[nf][0] = *(const uint32_t*)&Bh[buf][n][k16 + 2 * tig    ];
                    bf[nf][1] = *(const uint32_t*)&Bh[buf][n][k16 + 2 * tig + 8];
                }
#pragma unroll
                for (int mf = 0; mf < 4; mf++) {
                    int m = warpM * 64 + mf * 16 + g;
                    uint32_t af[4];
                    af[0] = *(const uint32_t*)&Ah[buf][m    ][k16 + 2 * tig    ];
                    af[1] = *(const uint32_t*)&Ah[buf][m + 8][k16 + 2 * tig    ];
                    af[2] = *(const uint32_t*)&Ah[buf][m    ][k16 + 2 * tig + 8];
                    af[3] = *(const uint32_t*)&Ah[buf][m + 8][k16 + 2 * tig + 8];
#pragma unroll
                    for (int nf = 0; nf < 4; nf++)
                        mma_f16(acc[mf][nf], af, bf[nf]);
                }
            }
            __syncthreads();
        }

#pragma unroll
        for (int mf = 0; mf < 4; mf++) {
            int row0 = tileM + warpM * 64 + mf * 16 + g;
            int row1 = row0 + 8;
#pragma unroll
            for (int nf = 0; nf < 4; nf++) {
                int col0 = tileN + warpN * 32 + nf * 8 + tig * 2;
                int col1 = col0 + 1;
                float b0 = fb2[col0];
                float b1 = fb2[col1];
                g_featshi[(size_t)row0 * N + col0] = __float2half(acc[mf][nf][0] + b0);
                g_featshi[(size_t)row0 * N + col1] = __float2half(acc[mf][nf][1] + b1);
                g_featshi[(size_t)row1 * N + col0] = __float2half(acc[mf][nf][2] + b0);
                g_featshi[(size_t)row1 * N + col1] = __float2half(acc[mf][nf][3] + b1);
            }
        }
    }
}

// ---------------------------------------------------------------------------
// keys normalization / routing / grouping / combine (R12-verbatim)
// ---------------------------------------------------------------------------
__global__ void keysn_kernel(const float* __restrict__ keys)
{
    int e    = threadIdx.x >> 5;
    int lane = threadIdx.x & 31;
    if (e >= EDIM) return;
    float4 v = *(const float4*)(keys + e * KDIM + lane * 4);
    float ss = v.x * v.x + v.y * v.y + v.z * v.z + v.w * v.w;
#pragma unroll
    for (int o = 16; o; o >>= 1) ss += __shfl_xor_sync(0xffffffffu, ss, o);
    float inv = 1.f / fmaxf(sqrtf(ss), 1e-12f);
    float4 o4 = make_float4(v.x * inv, v.y * inv, v.z * inv, v.w * inv);
    *(float4*)(g_keysn + e * KDIM + lane * 4) = o4;
}

__global__ void zero_counts_kernel()
{
    if (threadIdx.x < EDIM) g_counts[threadIdx.x] = 0;
}

__global__ void router_kernel()
{
    int warp = threadIdx.x >> 5;
    int lane = threadIdx.x & 31;
    int t = blockIdx.x * 8 + warp;
    if (t >= BDIM) return;

    float4 v = *(const float4*)(g_pk + (size_t)t * KDIM + lane * 4);
    float ss = v.x * v.x + v.y * v.y + v.z * v.z + v.w * v.w;
#pragma unroll
    for (int o = 16; o; o >>= 1) ss += __shfl_xor_sync(0xffffffffu, ss, o);
    float inv = 1.f / fmaxf(sqrtf(ss), 1e-12f);

    float sims[EDIM];
#pragma unroll
    for (int e = 0; e < EDIM; e++) {
        float4 kv = *(const float4*)(g_keysn + e * KDIM + lane * 4);
        float d = v.x * kv.x + v.y * kv.y + v.z * kv.z + v.w * kv.w;
#pragma unroll
        for (int o = 16; o; o >>= 1) d += __shfl_xor_sync(0xffffffffu, d, o);
        sims[e] = d * inv;
    }

    if (lane == 0) {
        int i0 = 0; float v0 = sims[0];
#pragma unroll
        for (int e = 1; e < EDIM; e++) if (sims[e] > v0) { v0 = sims[e]; i0 = e; }
        int i1 = -1; float v1 = -1e30f;
#pragma unroll
        for (int e = 0; e < EDIM; e++) if (e != i0 && sims[e] > v1) { v1 = sims[e]; i1 = e; }

        float e1 = expf(v1 - v0);
        float s  = 1.f + e1;
        float w0 = 1.f / s;
        float w1 = e1 / s;

#pragma unroll
        for (int e = 0; e < EDIM; e++) {
            g_sim[t * EDIM + e] = sims[e];
            g_weights[t * EDIM + e] = (e == i0) ? w0 : ((e == i1) ? w1 : 0.f);
        }
        g_topi[t * TOPK + 0] = i0;
        g_topi[t * TOPK + 1] = i1;
        g_wslot[t * TOPK + 0] = w0;
        g_wslot[t * TOPK + 1] = w1;
        atomicAdd(&g_counts[i0], 1);
        atomicAdd(&g_counts[i1], 1);
    }
}

__global__ void scan_kernel()
{
    if (threadIdx.x == 0) {
        int off = 0;
        for (int e = 0; e < EDIM; e++) {
            g_offsets[e] = off;
            g_cursor[e]  = off;
            off += g_counts[e];
        }
        g_offsets[EDIM] = off;
    }
}

__global__ void scatter_kernel()
{
    int t = blockIdx.x * blockDim.x + threadIdx.x;
    if (t >= BDIM) return;
#pragma unroll
    for (int s = 0; s < TOPK; s++) {
        int e = g_topi[t * TOPK + s];
        int pos = atomicAdd(&g_cursor[e], 1);
        g_list[pos] = t;
        g_pos[t * TOPK + s] = pos;
    }
}

__global__ void combine_kernel(float* __restrict__ out)
{
    int t = blockIdx.x;
    float w0 = g_wslot[t * TOPK + 0];
    float w1 = g_wslot[t * TOPK + 1];
    size_t p0 = (size_t)g_pos[t * TOPK + 0];
    size_t p1 = (size_t)g_pos[t * TOPK + 1];
    for (int c = threadIdx.x; c < CDIM; c += blockDim.x)
        out[(size_t)t * CDIM + c] =
            w0 * g_eout[p0 * CDIM + c] + w1 * g_eout[p1 * CDIM + c];
}

__global__ void tail_writer_kernel(float* __restrict__ out, long long out_size)
{
    long long i = (long long)blockIdx.x * blockDim.x + threadIdx.x;
    const long long base_w = (long long)BDIM * CDIM;
    const long long n_w = BDIM * EDIM;
    const long long base_t = base_w + n_w;
    const long long n_t = BDIM * TOPK;
    const long long base_s = base_t + n_t;
    const long long n_s = BDIM * EDIM;
    if (i < n_w && base_w + i < out_size) out[base_w + i] = g_weights[i];
    if (i < n_t && base_t + i < out_size) out[base_t + i] = (float)g_topi[i];
    if (i < n_s && base_s + i < out_size) out[base_s + i] = g_sim[i];
}

// ---------------------------------------------------------------------------
// Launch
// ---------------------------------------------------------------------------
#define SG_SMEM (4 * 2 * 128 * 40 * (int)sizeof(__half))   // 81920 B
#define HG_SMEM (2 * 2 * 128 * 72 * (int)sizeof(__half))   // 73728 B

extern "C" void kernel_launch(void* const* d_in, const int* in_sizes, int n_in,
                              void* d_out, int out_size)
{
    const float* x    = (const float*)d_in[0];
    const float* fw1  = (const float*)d_in[1];
    const float* fb1  = (const float*)d_in[2];
    const float* fw2  = (const float*)d_in[3];
    const float* fb2  = (const float*)d_in[4];
    const float* kw   = (const float*)d_in[5];
    const float* kb   = (const float*)d_in[6];
    const float* keys = (const float*)d_in[7];
    const float* ew1  = (const float*)d_in[8];
    const float* eb1  = (const float*)d_in[9];
    const float* ew2  = (const float*)d_in[10];
    const float* eb2  = (const float*)d_in[11];
    const float* ew3  = (const float*)d_in[12];
    const float* eb3  = (const float*)d_in[13];
    float* out = (float*)d_out;

    cudaFuncSetAttribute(sgemm_k<7, false>, cudaFuncAttributeMaxDynamicSharedMemorySize, SG_SMEM);
    cudaFuncSetAttribute(stage0c_k,         cudaFuncAttributeMaxDynamicSharedMemorySize, SG_SMEM);
    cudaFuncSetAttribute(fused12_k,         cudaFuncAttributeMaxDynamicSharedMemorySize, SG_SMEM);
    cudaFuncSetAttribute(hgemm_k<3, true >, cudaFuncAttributeMaxDynamicSharedMemorySize, HG_SMEM);
    cudaFuncSetAttribute(hgemm_k<4, true >, cudaFuncAttributeMaxDynamicSharedMemorySize, HG_SMEM);
    cudaFuncSetAttribute(hgemm_k<5, false>, cudaFuncAttributeMaxDynamicSharedMemorySize, HG_SMEM);

    dim3 blk(256);
    dim3 tblk(32, 8);

    __half *xhi, *xlo, *fw1hi, *fw1lo, *fw2nhi, *fw2nlo, *kwhi, *kwlo;
    __half *ew1h, *ew2h, *ew3h;
    float  *zbias;
    cudaGetSymbolAddress((void**)&xhi,    g_xhi);
    cudaGetSymbolAddress((void**)&xlo,    g_xlo);
    cudaGetSymbolAddress((void**)&fw1hi,  g_fw1hi);
    cudaGetSymbolAddress((void**)&fw1lo,  g_fw1lo);
    cudaGetSymbolAddress((void**)&fw2nhi, g_fw2nhi);
    cudaGetSymbolAddress((void**)&fw2nlo, g_fw2nlo);
    cudaGetSymbolAddress((void**)&kwhi,   g_kwhi);
    cudaGetSymbolAddress((void**)&kwlo,   g_kwlo);
    cudaGetSymbolAddress((void**)&ew1h,   g_ew1h);
    cudaGetSymbolAddress((void**)&ew2h,   g_ew2h);
    cudaGetSymbolAddress((void**)&ew3h,   g_ew3h);
    cudaGetSymbolAddress((void**)&zbias,  g_zbias);

    // pre-stage0 conversions (needed by stage0/stage7 GEMMs)
    natsplit_k<<<BDIM * DDIM / 4 / 256, 256>>>(x, xhi, xlo);
    natsplit_k<<<HDIM * HDIM / 4 / 256, 256>>>(fw2, fw2nhi, fw2nlo);
    wsplit_k<<<dim3(HDIM / 32, DDIM / 32), tblk>>>(fw1, fw1hi, fw1lo, DDIM, HDIM);
    wsplit_k<<<dim3(KDIM / 32, HDIM / 32), tblk>>>(kw,  kwhi,  kwlo,  HDIM, KDIM);
    bprime_k<<<KDIM, 256>>>(fb2, kw, kb);

    // W'^T = kw^T @ fw2 (fp32-grade split output)
    sgemm_k<7, false><<<dim3(HDIM / 128, 1), blk, SG_SMEM>>>(fw2nhi, fw2nlo, zbias, HDIM, HDIM);

    keysn_kernel<<<1, 256>>>(keys);
    zero_counts_kernel<<<1, 32>>>();

    // stage0 GEMM + (ew1, fw2^T) conversions hidden in the same wave
    stage0c_k<<<dim3(HDIM / 128, BDIM / 128, 2), blk, SG_SMEM>>>(fw1hi, fw1lo, fb1, ew1, fw2);

    // stage1 + stage2 GEMMs + (ew2, ew3) conversions hidden in the same wave
    fused12_k<<<dim3(HDIM / 128 + 1, BDIM / 128, 2), blk, SG_SMEM>>>(fb2, ew2, ew3);

    router_kernel<<<BDIM / 8, 256>>>();
    scan_kernel<<<1, 32>>>();
    scatter_kernel<<<(BDIM + 255) / 256, 256>>>();

    // expert MLPs: pure fp16 tensor-core GEMMs on grouped rows
    hgemm_k<3, true ><<<dim3(HDIM / 128,         BDIM / 128, EDIM), blk, HG_SMEM>>>(ew1h, eb1, HDIM,  HDIM);
    hgemm_k<4, true ><<<dim3(H2DIM / 128,        BDIM / 128, EDIM), blk, HG_SMEM>>>(ew2h, eb2, H2DIM, HDIM);
    hgemm_k<5, false><<<dim3((CDIM + 127) / 128, BDIM / 128, EDIM), blk, HG_SMEM>>>(ew3h, eb3, CDIM,  H2DIM);

    combine_kernel<<<BDIM, 256>>>(out);
    tail_writer_kernel<<<(BDIM * EDIM + 255) / 256, 256>>>(out, (long long)out_size);
}

// round 14
// speedup vs baseline: 1.1915x; 1.1915x over previous
#include <cuda_runtime.h>
#include <cuda_fp16.h>
#include <math.h>
#include <stdint.h>

// ---------------------------------------------------------------------------
// Problem constants
// ---------------------------------------------------------------------------
#define BDIM   8192
#define DDIM   1024
#define HDIM   2048
#define H2DIM  1024
#define CDIM   1000
#define KDIM   128
#define EDIM   8
#define TOPK   2
#define MAXROWS (BDIM * TOPK)

// ---------------------------------------------------------------------------
// Scratch (device globals — no allocation allowed)
// ---------------------------------------------------------------------------
__device__ __half g_xhi  [(size_t)BDIM * DDIM];
__device__ __half g_xlo  [(size_t)BDIM * DDIM];
__device__ __half g_hhi  [(size_t)BDIM * HDIM];
__device__ __half g_hlo  [(size_t)BDIM * HDIM];
__device__ __half g_featshi[(size_t)BDIM * HDIM];
__device__ float  g_pk   [(size_t)BDIM * KDIM];
__device__ float  g_keysn[EDIM * KDIM];
__device__ float  g_sim  [BDIM * EDIM];
__device__ float  g_weights[BDIM * EDIM];
__device__ float  g_wslot[BDIM * TOPK];
__device__ int    g_topi [BDIM * TOPK];
__device__ int    g_counts[EDIM];
__device__ int    g_offsets[EDIM + 1];
__device__ int    g_cursor[EDIM];
__device__ int    g_list [MAXROWS];
__device__ int    g_pos  [BDIM * TOPK];
__device__ __half g_h1h  [(size_t)MAXROWS * HDIM];
__device__ __half g_h2h  [(size_t)MAXROWS * H2DIM];
__device__ float  g_eout [(size_t)MAXROWS * CDIM];
// converted weights
__device__ __half g_fw1hi[(size_t)HDIM * DDIM];   // fw1^T split  [H][D]
__device__ __half g_fw1lo[(size_t)HDIM * DDIM];
__device__ __half g_fw2h [(size_t)HDIM * HDIM];   // fw2^T single [Hout][Hin]
__device__ __half g_fw2nhi[(size_t)HDIM * HDIM];  // fw2 natural split [Hin][Hout]
__device__ __half g_fw2nlo[(size_t)HDIM * HDIM];
__device__ __half g_kwhi [(size_t)KDIM * HDIM];   // kw^T split   [K][H]
__device__ __half g_kwlo [(size_t)KDIM * HDIM];
__device__ __half g_wphi [(size_t)KDIM * HDIM];   // W'^T split   [K][H]
__device__ __half g_wplo [(size_t)KDIM * HDIM];
__device__ float  g_bp   [KDIM];                  // b' = fb2@kw + kb
__device__ float  g_zbias[HDIM];                  // zeros (static init)
__device__ __half g_ew1h [(size_t)EDIM * HDIM  * HDIM];
__device__ __half g_ew2h [(size_t)EDIM * H2DIM * HDIM];
__device__ __half g_ew3h [(size_t)EDIM * CDIM  * H2DIM];

#define LO_SCALE 4096.0f
#define LO_INV   (1.0f / 4096.0f)

// ---------------------------------------------------------------------------
// helpers
// ---------------------------------------------------------------------------
__device__ __forceinline__ void mma_f16(float c[4],
                                        const uint32_t a[4],
                                        const uint32_t b[2]) {
    asm volatile(
        "mma.sync.aligned.m16n8k16.row.col.f32.f16.f16.f32 "
        "{%0,%1,%2,%3}, {%4,%5,%6,%7}, {%8,%9}, {%0,%1,%2,%3};"
        : "+f"(c[0]), "+f"(c[1]), "+f"(c[2]), "+f"(c[3])
        : "r"(a[0]), "r"(a[1]), "r"(a[2]), "r"(a[3]),
          "r"(b[0]), "r"(b[1]));
}
__device__ __forceinline__ void cp16(void* dst, const void* src, bool valid) {
    uint32_t d = (uint32_t)__cvta_generic_to_shared(dst);
    int sz = valid ? 16 : 0;
    asm volatile("cp.async.cg.shared.global [%0], [%1], 16, %2;"
                 :: "r"(d), "l"(src), "r"(sz));
}
__device__ __forceinline__ void split_f32(float v, __half& hi, __half& lo) {
    hi = __float2half(v);
    lo = __float2half((v - __half2float(hi)) * LO_SCALE);
}

// ---------------------------------------------------------------------------
// One-time conversions (R12-verbatim)
// ---------------------------------------------------------------------------
__global__ void natsplit_k(const float* __restrict__ W,
                           __half* __restrict__ Whi, __half* __restrict__ Wlo)
{
    size_t i = ((size_t)blockIdx.x * 256 + threadIdx.x) * 4;
    float4 v = *(const float4*)(W + i);
    __half h0, l0, h1, l1, h2, l2, h3, l3;
    split_f32(v.x, h0, l0); split_f32(v.y, h1, l1);
    split_f32(v.z, h2, l2); split_f32(v.w, h3, l3);
    *(__half2*)&Whi[i]     = __halves2half2(h0, h1);
    *(__half2*)&Whi[i + 2] = __halves2half2(h2, h3);
    *(__half2*)&Wlo[i]     = __halves2half2(l0, l1);
    *(__half2*)&Wlo[i + 2] = __halves2half2(l2, l3);
}

__global__ void wsplit_k(const float* __restrict__ W,
                         __half* __restrict__ Whi, __half* __restrict__ Wlo,
                         int K, int N)
{
    __shared__ float t[32][33];
    int k0 = blockIdx.y * 32;
    int n0 = blockIdx.x * 32;
#pragma unroll
    for (int j = 0; j < 4; j++)
        t[threadIdx.y + j * 8][threadIdx.x] =
            W[(size_t)(k0 + threadIdx.y + j * 8) * N + n0 + threadIdx.x];
    __syncthreads();
#pragma unroll
    for (int j = 0; j < 4; j++) {
        int n = n0 + threadIdx.y + j * 8;
        int k = k0 + threadIdx.x;
        float val = t[threadIdx.x][threadIdx.y + j * 8];
        __half hi, lo;
        split_f32(val, hi, lo);
        Whi[(size_t)n * K + k] = hi;
        Wlo[(size_t)n * K + k] = lo;
    }
}

__global__ void wconv_k(const float* __restrict__ Wg, __half* __restrict__ Wtg,
                        int K, int N)
{
    const float* W  = Wg  + (size_t)blockIdx.z * K * N;
    __half*      Wt = Wtg + (size_t)blockIdx.z * N * K;
    __shared__ float t[32][33];
    int k0 = blockIdx.y * 32;
    int n0 = blockIdx.x * 32;
#pragma unroll
    for (int j = 0; j < 4; j++) {
        int n = n0 + threadIdx.x;
        if (n < N) t[threadIdx.y + j * 8][threadIdx.x] =
            W[(size_t)(k0 + threadIdx.y + j * 8) * N + n];
    }
    __syncthreads();
#pragma unroll
    for (int j = 0; j < 4; j++) {
        int n = n0 + threadIdx.y + j * 8;
        int k = k0 + threadIdx.x;
        if (n < N) Wt[(size_t)n * K + k] =
            __float2half(t[threadIdx.x][threadIdx.y + j * 8]);
    }
}

__global__ void bprime_k(const float* __restrict__ fb2,
                         const float* __restrict__ kw,
                         const float* __restrict__ kb)
{
    int j = blockIdx.x;
    float s = 0.f;
    for (int m = threadIdx.x; m < HDIM; m += 256)
        s += fb2[m] * kw[(size_t)m * KDIM + j];
    __shared__ float red[8];
#pragma unroll
    for (int o = 16; o; o >>= 1) s += __shfl_xor_sync(0xffffffffu, s, o);
    if ((threadIdx.x & 31) == 0) red[threadIdx.x >> 5] = s;
    __syncthreads();
    if (threadIdx.x == 0) {
        float t = 0.f;
#pragma unroll
        for (int w = 0; w < 8; w++) t += red[w];
        g_bp[j] = t + kb[j];
    }
}

// ---------------------------------------------------------------------------
// fp16 2-term-split GEMM (R12-verbatim; STAGE 0 and 7)
// ---------------------------------------------------------------------------
#define SBK 32

template<int STAGE, bool RELU>
__global__ __launch_bounds__(256) void sgemm_k(const __half* __restrict__ Whi,
                                               const __half* __restrict__ Wlo,
                                               const float* __restrict__ Bias,
                                               int N, int Kd)
{
    extern __shared__ __half sms[];
    __half (*S)[2][128][40] = (__half(*)[2][128][40])sms;

    const __half *Ahi, *Alo;
    if (STAGE == 0)      { Ahi = g_xhi;  Alo = g_xlo;  }
    else if (STAGE == 2) { Ahi = g_hhi;  Alo = g_hlo;  }
    else                 { Ahi = g_kwhi; Alo = g_kwlo; }

    const int tileM = blockIdx.y * 128;
    const int tileN = blockIdx.x * 128;

    const int tid  = threadIdx.x;
    const int lane = tid & 31;
    const int wid  = tid >> 5;
    const int g    = lane >> 2;
    const int tig  = lane & 3;
    const int warpM = wid & 1;
    const int warpN = wid >> 1;

    const int rr = tid >> 2;
    const int cc = (tid & 3) * 8;

    const size_t aoff = (size_t)(tileM + rr) * Kd + cc;
    const size_t boff = (size_t)(tileN + rr) * Kd + cc;
    const size_t rstep = (size_t)64 * Kd;

    float acc [4][4][4];
    float accx[4][4][4];
#pragma unroll
    for (int i = 0; i < 4; i++)
#pragma unroll
        for (int j = 0; j < 4; j++)
#pragma unroll
            for (int r = 0; r < 4; r++) { acc[i][j][r] = 0.f; accx[i][j][r] = 0.f; }

    const int KT = Kd / SBK;

    auto load_tile = [&](int k0, int buf) {
#pragma unroll
        for (int it = 0; it < 2; it++) {
            cp16(&S[0][buf][rr + it * 64][cc], Ahi + aoff + it * rstep + k0, true);
            cp16(&S[1][buf][rr + it * 64][cc], Alo + aoff + it * rstep + k0, true);
            cp16(&S[2][buf][rr + it * 64][cc], Whi + boff + it * rstep + k0, true);
            cp16(&S[3][buf][rr + it * 64][cc], Wlo + boff + it * rstep + k0, true);
        }
        asm volatile("cp.async.commit_group;");
    };

    load_tile(0, 0);

    for (int kt = 0; kt < KT; kt++) {
        const int buf = kt & 1;
        if (kt + 1 < KT) {
            load_tile((kt + 1) * SBK, (kt + 1) & 1);
            asm volatile("cp.async.wait_group 1;");
        } else {
            asm volatile("cp.async.wait_group 0;");
        }
        __syncthreads();

#pragma unroll
        for (int ks = 0; ks < 2; ks++) {
            const int k16 = ks * 16;
            uint32_t bh[4][2], bl[4][2];
#pragma unroll
            for (int nf = 0; nf < 4; nf++) {
                int n = warpN * 32 + nf * 8 + g;
                bh[nf][0] = *(const uint32_t*)&S[2][buf][n][k16 + 2 * tig    ];
                bh[nf][1] = *(const uint32_t*)&S[2][buf][n][k16 + 2 * tig + 8];
                bl[nf][0] = *(const uint32_t*)&S[3][buf][n][k16 + 2 * tig    ];
                bl[nf][1] = *(const uint32_t*)&S[3][buf][n][k16 + 2 * tig + 8];
            }
#pragma unroll
            for (int mf = 0; mf < 4; mf++) {
                int m = warpM * 64 + mf * 16 + g;
                uint32_t ah[4], al[4];
                ah[0] = *(const uint32_t*)&S[0][buf][m    ][k16 + 2 * tig    ];
                ah[1] = *(const uint32_t*)&S[0][buf][m + 8][k16 + 2 * tig    ];
                ah[2] = *(const uint32_t*)&S[0][buf][m    ][k16 + 2 * tig + 8];
                ah[3] = *(const uint32_t*)&S[0][buf][m + 8][k16 + 2 * tig + 8];
                al[0] = *(const uint32_t*)&S[1][buf][m    ][k16 + 2 * tig    ];
                al[1] = *(const uint32_t*)&S[1][buf][m + 8][k16 + 2 * tig    ];
                al[2] = *(const uint32_t*)&S[1][buf][m    ][k16 + 2 * tig + 8];
                al[3] = *(const uint32_t*)&S[1][buf][m + 8][k16 + 2 * tig + 8];
#pragma unroll
                for (int nf = 0; nf < 4; nf++) {
                    mma_f16(acc [mf][nf], ah, bh[nf]);
                    mma_f16(accx[mf][nf], ah, bl[nf]);
                    mma_f16(accx[mf][nf], al, bh[nf]);
                }
            }
        }
        __syncthreads();
    }

#pragma unroll
    for (int mf = 0; mf < 4; mf++) {
        int row0 = tileM + warpM * 64 + mf * 16 + g;
        int row1 = row0 + 8;
#pragma unroll
        for (int nf = 0; nf < 4; nf++) {
            int col0 = tileN + warpN * 32 + nf * 8 + tig * 2;
            int col1 = col0 + 1;
            float b0 = Bias[col0];
            float b1 = Bias[col1];
            float v00 = acc[mf][nf][0] + accx[mf][nf][0] * LO_INV + b0;
            float v01 = acc[mf][nf][1] + accx[mf][nf][1] * LO_INV + b1;
            float v10 = acc[mf][nf][2] + accx[mf][nf][2] * LO_INV + b0;
            float v11 = acc[mf][nf][3] + accx[mf][nf][3] * LO_INV + b1;
            if (RELU) {
                v00 = fmaxf(v00, 0.f); v01 = fmaxf(v01, 0.f);
                v10 = fmaxf(v10, 0.f); v11 = fmaxf(v11, 0.f);
            }
            if (STAGE == 2) {
                g_pk[(size_t)row0 * N + col0] = v00;
                g_pk[(size_t)row0 * N + col1] = v01;
                g_pk[(size_t)row1 * N + col0] = v10;
                g_pk[(size_t)row1 * N + col1] = v11;
            } else {
                __half* Hi = (STAGE == 0) ? g_hhi : g_wphi;
                __half* Lo = (STAGE == 0) ? g_hlo : g_wplo;
                __half h, l;
                split_f32(v00, h, l);
                Hi[(size_t)row0 * N + col0] = h; Lo[(size_t)row0 * N + col0] = l;
                split_f32(v01, h, l);
                Hi[(size_t)row0 * N + col1] = h; Lo[(size_t)row0 * N + col1] = l;
                split_f32(v10, h, l);
                Hi[(size_t)row1 * N + col0] = h; Lo[(size_t)row1 * N + col0] = l;
                split_f32(v11, h, l);
                Hi[(size_t)row1 * N + col1] = h; Lo[(size_t)row1 * N + col1] = l;
            }
        }
    }
}

// ---------------------------------------------------------------------------
// Pure fp16 GEMM (expert stages 3/4/5).
// ONLY change vs R12: __launch_bounds__(256, 2) — cap regs at 128 so two
// CTAs co-reside per SM (SMEM 2x73728 = 147456 < 228KB; regs 2x256x128 = 64K).
// ---------------------------------------------------------------------------
#define HBK 64

template<int STAGE, bool RELU>
__global__ __launch_bounds__(256, 2) void hgemm_k(const __half* __restrict__ Wt,
                                                  const float* __restrict__ Biasg,
                                                  int N, int Kd)
{
    extern __shared__ __half smh[];
    __half (*Ah)[128][72] = (__half(*)[128][72])smh;
    __half (*Bh)[128][72] = (__half(*)[128][72])(smh + 2 * 128 * 72);

    int M;
    const __half* B;
    const float* Bias;
    const __half* A;
    __half* Ch = nullptr;
    float*  Cf = nullptr;
    const int* gather = nullptr;

    {
        int e  = blockIdx.z;
        int m0 = g_offsets[e];
        M = g_offsets[e + 1] - m0;
        B    = Wt    + (size_t)e * N * Kd;
        Bias = Biasg + (size_t)e * N;
        if (STAGE == 3)      { A = g_featshi; gather = g_list + m0; Ch = g_h1h + (size_t)m0 * N; }
        else if (STAGE == 4) { A = g_h1h + (size_t)m0 * Kd;         Ch = g_h2h + (size_t)m0 * N; }
        else                 { A = g_h2h + (size_t)m0 * Kd;         Cf = g_eout + (size_t)m0 * N; }
    }

    const int tileM = blockIdx.y * 128;
    if (tileM >= M) return;
    const int tileN = blockIdx.x * 128;

    const int tid  = threadIdx.x;
    const int lane = tid & 31;
    const int wid  = tid >> 5;
    const int g    = lane >> 2;
    const int tig  = lane & 3;
    const int warpM = wid & 1;
    const int warpN = wid >> 1;

    const __half* aptr[4];
    bool av[4];
#pragma unroll
    for (int it = 0; it < 4; it++) {
        int r = (tid >> 3) + it * 32;
        int grow = tileM + r;
        av[it] = (grow < M);
        size_t arow = 0;
        if (av[it]) arow = (STAGE == 3) ? (size_t)gather[grow] : (size_t)grow;
        aptr[it] = A + arow * Kd + (tid & 7) * 8;
    }
    const __half* bptr[4];
    bool bvv[4];
#pragma unroll
    for (int it = 0; it < 4; it++) {
        int r = (tid >> 3) + it * 32;
        int gn = tileN + r;
        bvv[it] = (gn < N);
        bptr[it] = B + (size_t)(bvv[it] ? gn : 0) * Kd + (tid & 7) * 8;
    }

    float acc[4][4][4];
#pragma unroll
    for (int i = 0; i < 4; i++)
#pragma unroll
        for (int j = 0; j < 4; j++)
#pragma unroll
            for (int r = 0; r < 4; r++) acc[i][j][r] = 0.f;

    const int KT = Kd / HBK;

    auto load_tile = [&](int k0, int buf) {
#pragma unroll
        for (int it = 0; it < 4; it++) {
            int r = (tid >> 3) + it * 32;
            cp16(&Ah[buf][r][(tid & 7) * 8], aptr[it] + k0, av[it]);
        }
#pragma unroll
        for (int it = 0; it < 4; it++) {
            int r = (tid >> 3) + it * 32;
            cp16(&Bh[buf][r][(tid & 7) * 8], bptr[it] + k0, bvv[it]);
        }
        asm volatile("cp.async.commit_group;");
    };

    load_tile(0, 0);

    for (int kt = 0; kt < KT; kt++) {
        const int buf = kt & 1;
        if (kt + 1 < KT) {
            load_tile((kt + 1) * HBK, (kt + 1) & 1);
            asm volatile("cp.async.wait_group 1;");
        } else {
            asm volatile("cp.async.wait_group 0;");
        }
        __syncthreads();

#pragma unroll
        for (int ks = 0; ks < 4; ks++) {
            const int k16 = ks * 16;
            uint32_t bf[4][2];
#pragma unroll
            for (int nf = 0; nf < 4; nf++) {
                int n = warpN * 32 + nf * 8 + g;
                bf[nf][0] = *(const uint32_t*)&Bh[buf][n][k16 + 2 * tig    ];
                bf[nf][1] = *(const uint32_t*)&Bh[buf][n][k16 + 2 * tig + 8];
            }
#pragma unroll
            for (int mf = 0; mf < 4; mf++) {
                int m = warpM * 64 + mf * 16 + g;
                uint32_t af[4];
                af[0] = *(const uint32_t*)&Ah[buf][m    ][k16 + 2 * tig    ];
                af[1] = *(const uint32_t*)&Ah[buf][m + 8][k16 + 2 * tig    ];
                af[2] = *(const uint32_t*)&Ah[buf][m    ][k16 + 2 * tig + 8];
                af[3] = *(const uint32_t*)&Ah[buf][m + 8][k16 + 2 * tig + 8];
#pragma unroll
                for (int nf = 0; nf < 4; nf++)
                    mma_f16(acc[mf][nf], af, bf[nf]);
            }
        }
        __syncthreads();
    }

#pragma unroll
    for (int mf = 0; mf < 4; mf++) {
        int row0 = tileM + warpM * 64 + mf * 16 + g;
        int row1 = row0 + 8;
#pragma unroll
        for (int nf = 0; nf < 4; nf++) {
            int col0 = tileN + warpN * 32 + nf * 8 + tig * 2;
            int col1 = col0 + 1;
            float b0 = (col0 < N) ? Bias[col0] : 0.f;
            float b1 = (col1 < N) ? Bias[col1] : 0.f;
            float v00 = acc[mf][nf][0] + b0;
            float v01 = acc[mf][nf][1] + b1;
            float v10 = acc[mf][nf][2] + b0;
            float v11 = acc[mf][nf][3] + b1;
            if (RELU) {
                v00 = fmaxf(v00, 0.f); v01 = fmaxf(v01, 0.f);
                v10 = fmaxf(v10, 0.f); v11 = fmaxf(v11, 0.f);
            }
            if (STAGE == 5) {
                if (row0 < M) {
                    if (col0 < N) Cf[(size_t)row0 * N + col0] = v00;
                    if (col1 < N) Cf[(size_t)row0 * N + col1] = v01;
                }
                if (row1 < M) {
                    if (col0 < N) Cf[(size_t)row1 * N + col0] = v10;
                    if (col1 < N) Cf[(size_t)row1 * N + col1] = v11;
                }
            } else {
                if (row0 < M) {
                    if (col0 < N) Ch[(size_t)row0 * N + col0] = __float2half(v00);
                    if (col1 < N) Ch[(size_t)row0 * N + col1] = __float2half(v01);
                }
                if (row1 < M) {
                    if (col0 < N) Ch[(size_t)row1 * N + col0] = __float2half(v10);
                    if (col1 < N) Ch[(size_t)row1 * N + col1] = __float2half(v11);
                }
            }
        }
    }
}

// ---------------------------------------------------------------------------
// stage1 + stage2 fused (R12-verbatim)
// ---------------------------------------------------------------------------
__global__ __launch_bounds__(256) void fused12_k(const float* __restrict__ fb2)
{
    extern __shared__ __half smf[];
    const int tid  = threadIdx.x;
    const int lane = tid & 31;
    const int wid  = tid >> 5;
    const int g    = lane >> 2;
    const int tig  = lane & 3;
    const int warpM = wid & 1;
    const int warpN = wid >> 1;

    if (blockIdx.x == 0) {
        // ----- stage2: split GEMM, tileN=0, N=KDIM, Kd=HDIM -----
        __half (*S)[2][128][40] = (__half(*)[2][128][40])smf;
        const __half* Ahi = g_hhi;
        const __half* Alo = g_hlo;
        const __half* Whi = g_wphi;
        const __half* Wlo = g_wplo;
        const int N  = KDIM;
        const int Kd = HDIM;
        const int tileM = blockIdx.y * 128;
        const int tileN = 0;

        const int rr = tid >> 2;
        const int cc = (tid & 3) * 8;
        const size_t aoff = (size_t)(tileM + rr) * Kd + cc;
        const size_t boff = (size_t)(tileN + rr) * Kd + cc;
        const size_t rstep = (size_t)64 * Kd;

        float acc [4][4][4];
        float accx[4][4][4];
#pragma unroll
        for (int i = 0; i < 4; i++)
#pragma unroll
            for (int j = 0; j < 4; j++)
#pragma unroll
                for (int r = 0; r < 4; r++) { acc[i][j][r] = 0.f; accx[i][j][r] = 0.f; }

        const int KT = Kd / SBK;

        auto load_tile = [&](int k0, int buf) {
#pragma unroll
            for (int it = 0; it < 2; it++) {
                cp16(&S[0][buf][rr + it * 64][cc], Ahi + aoff + it * rstep + k0, true);
                cp16(&S[1][buf][rr + it * 64][cc], Alo + aoff + it * rstep + k0, true);
                cp16(&S[2][buf][rr + it * 64][cc], Whi + boff + it * rstep + k0, true);
                cp16(&S[3][buf][rr + it * 64][cc], Wlo + boff + it * rstep + k0, true);
            }
            asm volatile("cp.async.commit_group;");
        };

        load_tile(0, 0);

        for (int kt = 0; kt < KT; kt++) {
            const int buf = kt & 1;
            if (kt + 1 < KT) {
                load_tile((kt + 1) * SBK, (kt + 1) & 1);
                asm volatile("cp.async.wait_group 1;");
            } else {
                asm volatile("cp.async.wait_group 0;");
            }
            __syncthreads();

#pragma unroll
            for (int ks = 0; ks < 2; ks++) {
                const int k16 = ks * 16;
                uint32_t bh[4][2], bl[4][2];
#pragma unroll
                for (int nf = 0; nf < 4; nf++) {
                    int n = warpN * 32 + nf * 8 + g;
                    bh[nf][0] = *(const uint32_t*)&S[2][buf][n][k16 + 2 * tig    ];
                    bh[nf][1] = *(const uint32_t*)&S[2][buf][n][k16 + 2 * tig + 8];
                    bl[nf][0] = *(const uint32_t*)&S[3][buf][n][k16 + 2 * tig    ];
                    bl[nf][1] = *(const uint32_t*)&S[3][buf][n][k16 + 2 * tig + 8];
                }
#pragma unroll
                for (int mf = 0; mf < 4; mf++) {
                    int m = warpM * 64 + mf * 16 + g;
                    uint32_t ah[4], al[4];
                    ah[0] = *(const uint32_t*)&S[0][buf][m    ][k16 + 2 * tig    ];
                    ah[1] = *(const uint32_t*)&S[0][buf][m + 8][k16 + 2 * tig    ];
                    ah[2] = *(const uint32_t*)&S[0][buf][m    ][k16 + 2 * tig + 8];
                    ah[3] = *(const uint32_t*)&S[0][buf][m + 8][k16 + 2 * tig + 8];
                    al[0] = *(const uint32_t*)&S[1][buf][m    ][k16 + 2 * tig    ];
                    al[1] = *(const uint32_t*)&S[1][buf][m + 8][k16 + 2 * tig    ];
                    al[2] = *(const uint32_t*)&S[1][buf][m    ][k16 + 2 * tig + 8];
                    al[3] = *(const uint32_t*)&S[1][buf][m + 8][k16 + 2 * tig + 8];
#pragma unroll
                    for (int nf = 0; nf < 4; nf++) {
                        mma_f16(acc [mf][nf], ah, bh[nf]);
                        mma_f16(accx[mf][nf], ah, bl[nf]);
                        mma_f16(accx[mf][nf], al, bh[nf]);
                    }
                }
            }
            __syncthreads();
        }

#pragma unroll
        for (int mf = 0; mf < 4; mf++) {
            int row0 = tileM + warpM * 64 + mf * 16 + g;
            int row1 = row0 + 8;
#pragma unroll
            for (int nf = 0; nf < 4; nf++) {
                int col0 = tileN + warpN * 32 + nf * 8 + tig * 2;
                int col1 = col0 + 1;
                float b0 = g_bp[col0];
                float b1 = g_bp[col1];
                g_pk[(size_t)row0 * N + col0] = acc[mf][nf][0] + accx[mf][nf][0] * LO_INV + b0;
                g_pk[(size_t)row0 * N + col1] = acc[mf][nf][1] + accx[mf][nf][1] * LO_INV + b1;
                g_pk[(size_t)row1 * N + col0] = acc[mf][nf][2] + accx[mf][nf][2] * LO_INV + b0;
                g_pk[(size_t)row1 * N + col1] = acc[mf][nf][3] + accx[mf][nf][3] * LO_INV + b1;
            }
        }
    } else {
        // ----- stage1: fp16 GEMM h @ fw2 -> g_featshi -----
        __half (*Ah)[128][72] = (__half(*)[128][72])smf;
        __half (*Bh)[128][72] = (__half(*)[128][72])(smf + 2 * 128 * 72);

        const __half* A = g_hhi;
        const __half* B = g_fw2h;
        const int N  = HDIM;
        const int Kd = HDIM;
        const int tileM = blockIdx.y * 128;
        const int tileN = (blockIdx.x - 1) * 128;

        const __half* aptr[4];
#pragma unroll
        for (int it = 0; it < 4; it++) {
            int r = (tid >> 3) + it * 32;
            aptr[it] = A + (size_t)(tileM + r) * Kd + (tid & 7) * 8;
        }
        const __half* bptr[4];
#pragma unroll
        for (int it = 0; it < 4; it++) {
            int r = (tid >> 3) + it * 32;
            bptr[it] = B + (size_t)(tileN + r) * Kd + (tid & 7) * 8;
        }

        float acc[4][4][4];
#pragma unroll
        for (int i = 0; i < 4; i++)
#pragma unroll
            for (int j = 0; j < 4; j++)
#pragma unroll
                for (int r = 0; r < 4; r++) acc[i][j][r] = 0.f;

        const int KT = Kd / HBK;

        auto load_tile = [&](int k0, int buf) {
#pragma unroll
            for (int it = 0; it < 4; it++) {
                int r = (tid >> 3) + it * 32;
                cp16(&Ah[buf][r][(tid & 7) * 8], aptr[it] + k0, true);
            }
#pragma unroll
            for (int it = 0; it < 4; it++) {
                int r = (tid >> 3) + it * 32;
                cp16(&Bh[buf][r][(tid & 7) * 8], bptr[it] + k0, true);
            }
            asm volatile("cp.async.commit_group;");
        };

        load_tile(0, 0);

        for (int kt = 0; kt < KT; kt++) {
            const int buf = kt & 1;
            if (kt + 1 < KT) {
                load_tile((kt + 1) * HBK, (kt + 1) & 1);
                asm volatile("cp.async.wait_group 1;");
            } else {
                asm volatile("cp.async.wait_group 0;");
            }
            __syncthreads();

#pragma unroll
            for (int ks = 0; ks < 4; ks++) {
                const int k16 = ks * 16;
                uint32_t bf[4][2];
#pragma unroll
                for (int nf = 0; nf < 4; nf++) {
                    int n = warpN * 32 + nf * 8 + g;
                    bf[nf][0] = *(const uint32_t*)&Bh[buf][n][k16 + 2 * tig    ];
                    bf[nf][1] = *(const uint32_t*)&Bh[buf][n][k16 + 2 * tig + 8];
                }
#pragma unroll
                for (int mf = 0; mf < 4; mf++) {
                    int m = warpM * 64 + mf * 16 + g;
                    uint32_t af[4];
                    af[0] = *(const uint32_t*)&Ah[buf][m    ][k16 + 2 * tig    ];
                    af[1] = *(const uint32_t*)&Ah[buf][m + 8][k16 + 2 * tig    ];
                    af[2] = *(const uint32_t*)&Ah[buf][m    ][k16 + 2 * tig + 8];
                    af[3] = *(const uint32_t*)&Ah[buf][m + 8][k16 + 2 * tig + 8];
#pragma unroll
                    for (int nf = 0; nf < 4; nf++)
                        mma_f16(acc[mf][nf], af, bf[nf]);
                }
            }
            __syncthreads();
        }

#pragma unroll
        for (int mf = 0; mf < 4; mf++) {
            int row0 = tileM + warpM * 64 + mf * 16 + g;
            int row1 = row0 + 8;
#pragma unroll
            for (int nf = 0; nf < 4; nf++) {
                int col0 = tileN + warpN * 32 + nf * 8 + tig * 2;
                int col1 = col0 + 1;
                float b0 = fb2[col0];
                float b1 = fb2[col1];
                g_featshi[(size_t)row0 * N + col0] = __float2half(acc[mf][nf][0] + b0);
                g_featshi[(size_t)row0 * N + col1] = __float2half(acc[mf][nf][1] + b1);
                g_featshi[(size_t)row1 * N + col0] = __float2half(acc[mf][nf][2] + b0);
                g_featshi[(size_t)row1 * N + col1] = __float2half(acc[mf][nf][3] + b1);
            }
        }
    }
}

// ---------------------------------------------------------------------------
// keys normalization / routing / grouping / combine (R12-verbatim)
// ---------------------------------------------------------------------------
__global__ void keysn_kernel(const float* __restrict__ keys)
{
    int e    = threadIdx.x >> 5;
    int lane = threadIdx.x & 31;
    if (e >= EDIM) return;
    float4 v = *(const float4*)(keys + e * KDIM + lane * 4);
    float ss = v.x * v.x + v.y * v.y + v.z * v.z + v.w * v.w;
#pragma unroll
    for (int o = 16; o; o >>= 1) ss += __shfl_xor_sync(0xffffffffu, ss, o);
    float inv = 1.f / fmaxf(sqrtf(ss), 1e-12f);
    float4 o4 = make_float4(v.x * inv, v.y * inv, v.z * inv, v.w * inv);
    *(float4*)(g_keysn + e * KDIM + lane * 4) = o4;
}

__global__ void zero_counts_kernel()
{
    if (threadIdx.x < EDIM) g_counts[threadIdx.x] = 0;
}

__global__ void router_kernel()
{
    int warp = threadIdx.x >> 5;
    int lane = threadIdx.x & 31;
    int t = blockIdx.x * 8 + warp;
    if (t >= BDIM) return;

    float4 v = *(const float4*)(g_pk + (size_t)t * KDIM + lane * 4);
    float ss = v.x * v.x + v.y * v.y + v.z * v.z + v.w * v.w;
#pragma unroll
    for (int o = 16; o; o >>= 1) ss += __shfl_xor_sync(0xffffffffu, ss, o);
    float inv = 1.f / fmaxf(sqrtf(ss), 1e-12f);

    float sims[EDIM];
#pragma unroll
    for (int e = 0; e < EDIM; e++) {
        float4 kv = *(const float4*)(g_keysn + e * KDIM + lane * 4);
        float d = v.x * kv.x + v.y * kv.y + v.z * kv.z + v.w * kv.w;
#pragma unroll
        for (int o = 16; o; o >>= 1) d += __shfl_xor_sync(0xffffffffu, d, o);
        sims[e] = d * inv;
    }

    if (lane == 0) {
        int i0 = 0; float v0 = sims[0];
#pragma unroll
        for (int e = 1; e < EDIM; e++) if (sims[e] > v0) { v0 = sims[e]; i0 = e; }
        int i1 = -1; float v1 = -1e30f;
#pragma unroll
        for (int e = 0; e < EDIM; e++) if (e != i0 && sims[e] > v1) { v1 = sims[e]; i1 = e; }

        float e1 = expf(v1 - v0);
        float s  = 1.f + e1;
        float w0 = 1.f / s;
        float w1 = e1 / s;

#pragma unroll
        for (int e = 0; e < EDIM; e++) {
            g_sim[t * EDIM + e] = sims[e];
            g_weights[t * EDIM + e] = (e == i0) ? w0 : ((e == i1) ? w1 : 0.f);
        }
        g_topi[t * TOPK + 0] = i0;
        g_topi[t * TOPK + 1] = i1;
        g_wslot[t * TOPK + 0] = w0;
        g_wslot[t * TOPK + 1] = w1;
        atomicAdd(&g_counts[i0], 1);
        atomicAdd(&g_counts[i1], 1);
    }
}

__global__ void scan_kernel()
{
    if (threadIdx.x == 0) {
        int off = 0;
        for (int e = 0; e < EDIM; e++) {
            g_offsets[e] = off;
            g_cursor[e]  = off;
            off += g_counts[e];
        }
        g_offsets[EDIM] = off;
    }
}

__global__ void scatter_kernel()
{
    int t = blockIdx.x * blockDim.x + threadIdx.x;
    if (t >= BDIM) return;
#pragma unroll
    for (int s = 0; s < TOPK; s++) {
        int e = g_topi[t * TOPK + s];
        int pos = atomicAdd(&g_cursor[e], 1);
        g_list[pos] = t;
        g_pos[t * TOPK + s] = pos;
    }
}

__global__ void combine_kernel(float* __restrict__ out)
{
    int t = blockIdx.x;
    float w0 = g_wslot[t * TOPK + 0];
    float w1 = g_wslot[t * TOPK + 1];
    size_t p0 = (size_t)g_pos[t * TOPK + 0];
    size_t p1 = (size_t)g_pos[t * TOPK + 1];
    for (int c = threadIdx.x; c < CDIM; c += blockDim.x)
        out[(size_t)t * CDIM + c] =
            w0 * g_eout[p0 * CDIM + c] + w1 * g_eout[p1 * CDIM + c];
}

__global__ void tail_writer_kernel(float* __restrict__ out, long long out_size)
{
    long long i = (long long)blockIdx.x * blockDim.x + threadIdx.x;
    const long long base_w = (long long)BDIM * CDIM;
    const long long n_w = BDIM * EDIM;
    const long long base_t = base_w + n_w;
    const long long n_t = BDIM * TOPK;
    const long long base_s = base_t + n_t;
    const long long n_s = BDIM * EDIM;
    if (i < n_w && base_w + i < out_size) out[base_w + i] = g_weights[i];
    if (i < n_t && base_t + i < out_size) out[base_t + i] = (float)g_topi[i];
    if (i < n_s && base_s + i < out_size) out[base_s + i] = g_sim[i];
}

// ---------------------------------------------------------------------------
// Launch
// ---------------------------------------------------------------------------
#define SG_SMEM (4 * 2 * 128 * 40 * (int)sizeof(__half))   // 81920 B
#define HG_SMEM (2 * 2 * 128 * 72 * (int)sizeof(__half))   // 73728 B

extern "C" void kernel_launch(void* const* d_in, const int* in_sizes, int n_in,
                              void* d_out, int out_size)
{
    const float* x    = (const float*)d_in[0];
    const float* fw1  = (const float*)d_in[1];
    const float* fb1  = (const float*)d_in[2];
    const float* fw2  = (const float*)d_in[3];
    const float* fb2  = (const float*)d_in[4];
    const float* kw   = (const float*)d_in[5];
    const float* kb   = (const float*)d_in[6];
    const float* keys = (const float*)d_in[7];
    const float* ew1  = (const float*)d_in[8];
    const float* eb1  = (const float*)d_in[9];
    const float* ew2  = (const float*)d_in[10];
    const float* eb2  = (const float*)d_in[11];
    const float* ew3  = (const float*)d_in[12];
    const float* eb3  = (const float*)d_in[13];
    float* out = (float*)d_out;

    cudaFuncSetAttribute(sgemm_k<0, true >, cudaFuncAttributeMaxDynamicSharedMemorySize, SG_SMEM);
    cudaFuncSetAttribute(sgemm_k<7, false>, cudaFuncAttributeMaxDynamicSharedMemorySize, SG_SMEM);
    cudaFuncSetAttribute(fused12_k,         cudaFuncAttributeMaxDynamicSharedMemorySize, SG_SMEM);
    cudaFuncSetAttribute(hgemm_k<3, true >, cudaFuncAttributeMaxDynamicSharedMemorySize, HG_SMEM);
    cudaFuncSetAttribute(hgemm_k<4, true >, cudaFuncAttributeMaxDynamicSharedMemorySize, HG_SMEM);
    cudaFuncSetAttribute(hgemm_k<5, false>, cudaFuncAttributeMaxDynamicSharedMemorySize, HG_SMEM);

    dim3 blk(256);
    dim3 tblk(32, 8);

    __half *xhi, *xlo, *fw1hi, *fw1lo, *fw2h, *fw2nhi, *fw2nlo, *kwhi, *kwlo;
    __half *wphi, *wplo, *ew1h, *ew2h, *ew3h;
    float  *zbias;
    cudaGetSymbolAddress((void**)&xhi,    g_xhi);
    cudaGetSymbolAddress((void**)&xlo,    g_xlo);
    cudaGetSymbolAddress((void**)&fw1hi,  g_fw1hi);
    cudaGetSymbolAddress((void**)&fw1lo,  g_fw1lo);
    cudaGetSymbolAddress((void**)&fw2h,   g_fw2h);
    cudaGetSymbolAddress((void**)&fw2nhi, g_fw2nhi);
    cudaGetSymbolAddress((void**)&fw2nlo, g_fw2nlo);
    cudaGetSymbolAddress((void**)&kwhi,   g_kwhi);
    cudaGetSymbolAddress((void**)&kwlo,   g_kwlo);
    cudaGetSymbolAddress((void**)&wphi,   g_wphi);
    cudaGetSymbolAddress((void**)&wplo,   g_wplo);
    cudaGetSymbolAddress((void**)&ew1h,   g_ew1h);
    cudaGetSymbolAddress((void**)&ew2h,   g_ew2h);
    cudaGetSymbolAddress((void**)&ew3h,   g_ew3h);
    cudaGetSymbolAddress((void**)&zbias,  g_zbias);

    // one-time conversions (R12-verbatim)
    natsplit_k<<<BDIM * DDIM / 4 / 256, 256>>>(x, xhi, xlo);
    natsplit_k<<<HDIM * HDIM / 4 / 256, 256>>>(fw2, fw2nhi, fw2nlo);
    wsplit_k<<<dim3(HDIM / 32, DDIM / 32), tblk>>>(fw1, fw1hi, fw1lo, DDIM, HDIM);
    wsplit_k<<<dim3(KDIM / 32, HDIM / 32), tblk>>>(kw,  kwhi,  kwlo,  HDIM, KDIM);
    wconv_k<<<dim3(HDIM / 32,        HDIM / 32,  1   ), tblk>>>(fw2, fw2h, HDIM,  HDIM);
    wconv_k<<<dim3(HDIM / 32,        HDIM / 32,  EDIM), tblk>>>(ew1, ew1h, HDIM,  HDIM);
    wconv_k<<<dim3(H2DIM / 32,       HDIM / 32,  EDIM), tblk>>>(ew2, ew2h, HDIM,  H2DIM);
    wconv_k<<<dim3((CDIM + 31) / 32, H2DIM / 32, EDIM), tblk>>>(ew3, ew3h, H2DIM, CDIM);
    bprime_k<<<KDIM, 256>>>(fb2, kw, kb);

    // W'^T = kw^T @ fw2 (fp32-grade split output)
    sgemm_k<7, false><<<dim3(HDIM / 128, 1), blk, SG_SMEM>>>(fw2nhi, fw2nlo, zbias, HDIM, HDIM);

    keysn_kernel<<<1, 256>>>(keys);
    zero_counts_kernel<<<1, 32>>>();

    // stage0: x @ fw1 -> h split (fp32-grade, relu)
    sgemm_k<0, true ><<<dim3(HDIM / 128, BDIM / 128), blk, SG_SMEM>>>(fw1hi, fw1lo, fb1, HDIM, DDIM);

    // stage1 (feats fp16) + stage2 (pk fp32) fused into one wave
    fused12_k<<<dim3(HDIM / 128 + 1, BDIM / 128), blk, SG_SMEM>>>(fb2);

    router_kernel<<<BDIM / 8, 256>>>();
    scan_kernel<<<1, 32>>>();
    scatter_kernel<<<(BDIM + 255) / 256, 256>>>();

    // expert MLPs: fp16 HMMA, now 2 CTAs/SM via launch bounds
    hgemm_k<3, true ><<<dim3(HDIM / 128,         BDIM / 128, EDIM), blk, HG_SMEM>>>(ew1h, eb1, HDIM,  HDIM);
    hgemm_k<4, true ><<<dim3(H2DIM / 128,        BDIM / 128, EDIM), blk, HG_SMEM>>>(ew2h, eb2, H2DIM, HDIM);
    hgemm_k<5, false><<<dim3((CDIM + 127) / 128, BDIM / 128, EDIM), blk, HG_SMEM>>>(ew3h, eb3, CDIM,  H2DIM);

    combine_kernel<<<BDIM, 256>>>(out);
    tail_writer_kernel<<<(BDIM * EDIM + 255) / 256, 256>>>(out, (long long)out_size);
}

// round 15
// speedup vs baseline: 1.2460x; 1.0458x over previous
#include <cuda_runtime.h>
#include <cuda_fp16.h>
#include <math.h>
#include <stdint.h>

// ---------------------------------------------------------------------------
// Problem constants
// ---------------------------------------------------------------------------
#define BDIM   8192
#define DDIM   1024
#define HDIM   2048
#define H2DIM  1024
#define CDIM   1000
#define KDIM   128
#define EDIM   8
#define TOPK   2
#define MAXROWS (BDIM * TOPK)

// ---------------------------------------------------------------------------
// Scratch (device globals — no allocation allowed)
// ---------------------------------------------------------------------------
__device__ __half g_xhi  [(size_t)BDIM * DDIM];
__device__ __half g_xlo  [(size_t)BDIM * DDIM];
__device__ __half g_hhi  [(size_t)BDIM * HDIM];
__device__ __half g_hlo  [(size_t)BDIM * HDIM];
__device__ __half g_featshi[(size_t)BDIM * HDIM];
__device__ float  g_pk   [(size_t)BDIM * KDIM];
__device__ float  g_pk2  [(size_t)BDIM * KDIM];
__device__ float  g_keysn[EDIM * KDIM];
__device__ float  g_sim  [BDIM * EDIM];
__device__ float  g_weights[BDIM * EDIM];
__device__ float  g_wslot[BDIM * TOPK];
__device__ int    g_topi [BDIM * TOPK];
__device__ int    g_counts[EDIM];
__device__ int    g_offsets[EDIM + 1];
__device__ int    g_cursor[EDIM];
__device__ int    g_list [MAXROWS];
__device__ int    g_pos  [BDIM * TOPK];
__device__ __half g_h1h  [(size_t)MAXROWS * HDIM];
__device__ __half g_h2h  [(size_t)MAXROWS * H2DIM];
__device__ float  g_eout [(size_t)MAXROWS * CDIM];
// converted weights
__device__ __half g_fw1hi[(size_t)HDIM * DDIM];   // fw1^T split  [H][D]
__device__ __half g_fw1lo[(size_t)HDIM * DDIM];
__device__ __half g_fw2h [(size_t)HDIM * HDIM];   // fw2^T single [Hout][Hin]
__device__ __half g_fw2nhi[(size_t)HDIM * HDIM];  // fw2 natural split [Hin][Hout]
__device__ __half g_fw2nlo[(size_t)HDIM * HDIM];
__device__ __half g_kwhi [(size_t)KDIM * HDIM];   // kw^T split   [K][H]
__device__ __half g_kwlo [(size_t)KDIM * HDIM];
__device__ __half g_wphi [(size_t)KDIM * HDIM];   // W'^T split   [K][H]
__device__ __half g_wplo [(size_t)KDIM * HDIM];
__device__ float  g_bp   [KDIM];                  // b' = fb2@kw + kb
__device__ float  g_zbias[HDIM];                  // zeros (static init)
__device__ __half g_ew1h [(size_t)EDIM * HDIM  * HDIM];
__device__ __half g_ew2h [(size_t)EDIM * H2DIM * HDIM];
__device__ __half g_ew3h [(size_t)EDIM * CDIM  * H2DIM];

#define LO_SCALE 4096.0f
#define LO_INV   (1.0f / 4096.0f)

// ---------------------------------------------------------------------------
// helpers
// ---------------------------------------------------------------------------
__device__ __forceinline__ void mma_f16(float c[4],
                                        const uint32_t a[4],
                                        const uint32_t b[2]) {
    asm volatile(
        "mma.sync.aligned.m16n8k16.row.col.f32.f16.f16.f32 "
        "{%0,%1,%2,%3}, {%4,%5,%6,%7}, {%8,%9}, {%0,%1,%2,%3};"
        : "+f"(c[0]), "+f"(c[1]), "+f"(c[2]), "+f"(c[3])
        : "r"(a[0]), "r"(a[1]), "r"(a[2]), "r"(a[3]),
          "r"(b[0]), "r"(b[1]));
}
__device__ __forceinline__ void cp16(void* dst, const void* src, bool valid) {
    uint32_t d = (uint32_t)__cvta_generic_to_shared(dst);
    int sz = valid ? 16 : 0;
    asm volatile("cp.async.cg.shared.global [%0], [%1], 16, %2;"
                 :: "r"(d), "l"(src), "r"(sz));
}
__device__ __forceinline__ void split_f32(float v, __half& hi, __half& lo) {
    hi = __float2half(v);
    lo = __float2half((v - __half2float(hi)) * LO_SCALE);
}

// ---------------------------------------------------------------------------
// One-time conversions (R14-verbatim)
// ---------------------------------------------------------------------------
__global__ void natsplit_k(const float* __restrict__ W,
                           __half* __restrict__ Whi, __half* __restrict__ Wlo)
{
    size_t i = ((size_t)blockIdx.x * 256 + threadIdx.x) * 4;
    float4 v = *(const float4*)(W + i);
    __half h0, l0, h1, l1, h2, l2, h3, l3;
    split_f32(v.x, h0, l0); split_f32(v.y, h1, l1);
    split_f32(v.z, h2, l2); split_f32(v.w, h3, l3);
    *(__half2*)&Whi[i]     = __halves2half2(h0, h1);
    *(__half2*)&Whi[i + 2] = __halves2half2(h2, h3);
    *(__half2*)&Wlo[i]     = __halves2half2(l0, l1);
    *(__half2*)&Wlo[i + 2] = __halves2half2(l2, l3);
}

__global__ void wsplit_k(const float* __restrict__ W,
                         __half* __restrict__ Whi, __half* __restrict__ Wlo,
                         int K, int N)
{
    __shared__ float t[32][33];
    int k0 = blockIdx.y * 32;
    int n0 = blockIdx.x * 32;
#pragma unroll
    for (int j = 0; j < 4; j++)
        t[threadIdx.y + j * 8][threadIdx.x] =
            W[(size_t)(k0 + threadIdx.y + j * 8) * N + n0 + threadIdx.x];
    __syncthreads();
#pragma unroll
    for (int j = 0; j < 4; j++) {
        int n = n0 + threadIdx.y + j * 8;
        int k = k0 + threadIdx.x;
        float val = t[threadIdx.x][threadIdx.y + j * 8];
        __half hi, lo;
        split_f32(val, hi, lo);
        Whi[(size_t)n * K + k] = hi;
        Wlo[(size_t)n * K + k] = lo;
    }
}

__global__ void wconv_k(const float* __restrict__ Wg, __half* __restrict__ Wtg,
                        int K, int N)
{
    const float* W  = Wg  + (size_t)blockIdx.z * K * N;
    __half*      Wt = Wtg + (size_t)blockIdx.z * N * K;
    __shared__ float t[32][33];
    int k0 = blockIdx.y * 32;
    int n0 = blockIdx.x * 32;
#pragma unroll
    for (int j = 0; j < 4; j++) {
        int n = n0 + threadIdx.x;
        if (n < N) t[threadIdx.y + j * 8][threadIdx.x] =
            W[(size_t)(k0 + threadIdx.y + j * 8) * N + n];
    }
    __syncthreads();
#pragma unroll
    for (int j = 0; j < 4; j++) {
        int n = n0 + threadIdx.y + j * 8;
        int k = k0 + threadIdx.x;
        if (n < N) Wt[(size_t)n * K + k] =
            __float2half(t[threadIdx.x][threadIdx.y + j * 8]);
    }
}

__global__ void bprime_k(const float* __restrict__ fb2,
                         const float* __restrict__ kw,
                         const float* __restrict__ kb)
{
    int j = blockIdx.x;
    float s = 0.f;
    for (int m = threadIdx.x; m < HDIM; m += 256)
        s += fb2[m] * kw[(size_t)m * KDIM + j];
    __shared__ float red[8];
#pragma unroll
    for (int o = 16; o; o >>= 1) s += __shfl_xor_sync(0xffffffffu, s, o);
    if ((threadIdx.x & 31) == 0) red[threadIdx.x >> 5] = s;
    __syncthreads();
    if (threadIdx.x == 0) {
        float t = 0.f;
#pragma unroll
        for (int w = 0; w < 8; w++) t += red[w];
        g_bp[j] = t + kb[j];
    }
}

// ---------------------------------------------------------------------------
// fp16 2-term-split GEMM (R14-verbatim; STAGE 0 and 7)
// ---------------------------------------------------------------------------
#define SBK 32

template<int STAGE, bool RELU>
__global__ __launch_bounds__(256) void sgemm_k(const __half* __restrict__ Whi,
                                               const __half* __restrict__ Wlo,
                                               const float* __restrict__ Bias,
                                               int N, int Kd)
{
    extern __shared__ __half sms[];
    __half (*S)[2][128][40] = (__half(*)[2][128][40])sms;

    const __half *Ahi, *Alo;
    if (STAGE == 0)      { Ahi = g_xhi;  Alo = g_xlo;  }
    else                 { Ahi = g_kwhi; Alo = g_kwlo; }

    const int tileM = blockIdx.y * 128;
    const int tileN = blockIdx.x * 128;

    const int tid  = threadIdx.x;
    const int lane = tid & 31;
    const int wid  = tid >> 5;
    const int g    = lane >> 2;
    const int tig  = lane & 3;
    const int warpM = wid & 1;
    const int warpN = wid >> 1;

    const int rr = tid >> 2;
    const int cc = (tid & 3) * 8;

    const size_t aoff = (size_t)(tileM + rr) * Kd + cc;
    const size_t boff = (size_t)(tileN + rr) * Kd + cc;
    const size_t rstep = (size_t)64 * Kd;

    float acc [4][4][4];
    float accx[4][4][4];
#pragma unroll
    for (int i = 0; i < 4; i++)
#pragma unroll
        for (int j = 0; j < 4; j++)
#pragma unroll
            for (int r = 0; r < 4; r++) { acc[i][j][r] = 0.f; accx[i][j][r] = 0.f; }

    const int KT = Kd / SBK;

    auto load_tile = [&](int k0, int buf) {
#pragma unroll
        for (int it = 0; it < 2; it++) {
            cp16(&S[0][buf][rr + it * 64][cc], Ahi + aoff + it * rstep + k0, true);
            cp16(&S[1][buf][rr + it * 64][cc], Alo + aoff + it * rstep + k0, true);
            cp16(&S[2][buf][rr + it * 64][cc], Whi + boff + it * rstep + k0, true);
            cp16(&S[3][buf][rr + it * 64][cc], Wlo + boff + it * rstep + k0, true);
        }
        asm volatile("cp.async.commit_group;");
    };

    load_tile(0, 0);

    for (int kt = 0; kt < KT; kt++) {
        const int buf = kt & 1;
        if (kt + 1 < KT) {
            load_tile((kt + 1) * SBK, (kt + 1) & 1);
            asm volatile("cp.async.wait_group 1;");
        } else {
            asm volatile("cp.async.wait_group 0;");
        }
        __syncthreads();

#pragma unroll
        for (int ks = 0; ks < 2; ks++) {
            const int k16 = ks * 16;
            uint32_t bh[4][2], bl[4][2];
#pragma unroll
            for (int nf = 0; nf < 4; nf++) {
                int n = warpN * 32 + nf * 8 + g;
                bh[nf][0] = *(const uint32_t*)&S[2][buf][n][k16 + 2 * tig    ];
                bh[nf][1] = *(const uint32_t*)&S[2][buf][n][k16 + 2 * tig + 8];
                bl[nf][0] = *(const uint32_t*)&S[3][buf][n][k16 + 2 * tig    ];
                bl[nf][1] = *(const uint32_t*)&S[3][buf][n][k16 + 2 * tig + 8];
            }
#pragma unroll
            for (int mf = 0; mf < 4; mf++) {
                int m = warpM * 64 + mf * 16 + g;
                uint32_t ah[4], al[4];
                ah[0] = *(const uint32_t*)&S[0][buf][m    ][k16 + 2 * tig    ];
                ah[1] = *(const uint32_t*)&S[0][buf][m + 8][k16 + 2 * tig    ];
                ah[2] = *(const uint32_t*)&S[0][buf][m    ][k16 + 2 * tig + 8];
                ah[3] = *(const uint32_t*)&S[0][buf][m + 8][k16 + 2 * tig + 8];
                al[0] = *(const uint32_t*)&S[1][buf][m    ][k16 + 2 * tig    ];
                al[1] = *(const uint32_t*)&S[1][buf][m + 8][k16 + 2 * tig    ];
                al[2] = *(const uint32_t*)&S[1][buf][m    ][k16 + 2 * tig + 8];
                al[3] = *(const uint32_t*)&S[1][buf][m + 8][k16 + 2 * tig + 8];
#pragma unroll
                for (int nf = 0; nf < 4; nf++) {
                    mma_f16(acc [mf][nf], ah, bh[nf]);
                    mma_f16(accx[mf][nf], ah, bl[nf]);
                    mma_f16(accx[mf][nf], al, bh[nf]);
                }
            }
        }
        __syncthreads();
    }

#pragma unroll
    for (int mf = 0; mf < 4; mf++) {
        int row0 = tileM + warpM * 64 + mf * 16 + g;
        int row1 = row0 + 8;
#pragma unroll
        for (int nf = 0; nf < 4; nf++) {
            int col0 = tileN + warpN * 32 + nf * 8 + tig * 2;
            int col1 = col0 + 1;
            float b0 = Bias[col0];
            float b1 = Bias[col1];
            float v00 = acc[mf][nf][0] + accx[mf][nf][0] * LO_INV + b0;
            float v01 = acc[mf][nf][1] + accx[mf][nf][1] * LO_INV + b1;
            float v10 = acc[mf][nf][2] + accx[mf][nf][2] * LO_INV + b0;
            float v11 = acc[mf][nf][3] + accx[mf][nf][3] * LO_INV + b1;
            if (RELU) {
                v00 = fmaxf(v00, 0.f); v01 = fmaxf(v01, 0.f);
                v10 = fmaxf(v10, 0.f); v11 = fmaxf(v11, 0.f);
            }
            __half* Hi = (STAGE == 0) ? g_hhi : g_wphi;
            __half* Lo = (STAGE == 0) ? g_hlo : g_wplo;
            __half h, l;
            split_f32(v00, h, l);
            Hi[(size_t)row0 * N + col0] = h; Lo[(size_t)row0 * N + col0] = l;
            split_f32(v01, h, l);
            Hi[(size_t)row0 * N + col1] = h; Lo[(size_t)row0 * N + col1] = l;
            split_f32(v10, h, l);
            Hi[(size_t)row1 * N + col0] = h; Lo[(size_t)row1 * N + col0] = l;
            split_f32(v11, h, l);
            Hi[(size_t)row1 * N + col1] = h; Lo[(size_t)row1 * N + col1] = l;
        }
    }
}

// ---------------------------------------------------------------------------
// NEW: stage2 split-GEMM with K split across blockIdx.z (2 halves).
//   pk_partial[z] = h[:, z*1024:(z+1)*1024] @ W'[z*1024:(z+1)*1024, :]
//   z==0 adds b', writes g_pk; z==1 adds 0, writes g_pk2. Router sums.
// Grid (1, 64, 2) = 128 CTAs. Body is the R14 fused12 stage2 path with
// a k-base offset and halved KT.
// ---------------------------------------------------------------------------
__global__ __launch_bounds__(256) void stage2s_k()
{
    extern __shared__ __half smf[];
    __half (*S)[2][128][40] = (__half(*)[2][128][40])smf;

    const int tid  = threadIdx.x;
    const int lane = tid & 31;
    const int wid  = tid >> 5;
    const int g    = lane >> 2;
    const int tig  = lane & 3;
    const int warpM = wid & 1;
    const int warpN = wid >> 1;

    const int N  = KDIM;
    const int Kd = HDIM;
    const int kbase = blockIdx.z * (HDIM / 2);
    const int tileM = blockIdx.y * 128;

    const int rr = tid >> 2;
    const int cc = (tid & 3) * 8;
    const size_t aoff = (size_t)(tileM + rr) * Kd + kbase + cc;
    const size_t boff = (size_t)rr * Kd + kbase + cc;
    const size_t rstep = (size_t)64 * Kd;

    float acc [4][4][4];
    float accx[4][4][4];
#pragma unroll
    for (int i = 0; i < 4; i++)
#pragma unroll
        for (int j = 0; j < 4; j++)
#pragma unroll
            for (int r = 0; r < 4; r++) { acc[i][j][r] = 0.f; accx[i][j][r] = 0.f; }

    const int KT = (HDIM / 2) / SBK;

    auto load_tile = [&](int k0, int buf) {
#pragma unroll
        for (int it = 0; it < 2; it++) {
            cp16(&S[0][buf][rr + it * 64][cc], g_hhi  + aoff + it * rstep + k0, true);
            cp16(&S[1][buf][rr + it * 64][cc], g_hlo  + aoff + it * rstep + k0, true);
            cp16(&S[2][buf][rr + it * 64][cc], g_wphi + boff + it * rstep + k0, true);
            cp16(&S[3][buf][rr + it * 64][cc], g_wplo + boff + it * rstep + k0, true);
        }
        asm volatile("cp.async.commit_group;");
    };

    load_tile(0, 0);

    for (int kt = 0; kt < KT; kt++) {
        const int buf = kt & 1;
        if (kt + 1 < KT) {
            load_tile((kt + 1) * SBK, (kt + 1) & 1);
            asm volatile("cp.async.wait_group 1;");
        } else {
            asm volatile("cp.async.wait_group 0;");
        }
        __syncthreads();

#pragma unroll
        for (int ks = 0; ks < 2; ks++) {
            const int k16 = ks * 16;
            uint32_t bh[4][2], bl[4][2];
#pragma unroll
            for (int nf = 0; nf < 4; nf++) {
                int n = warpN * 32 + nf * 8 + g;
                bh[nf][0] = *(const uint32_t*)&S[2][buf][n][k16 + 2 * tig    ];
                bh[nf][1] = *(const uint32_t*)&S[2][buf][n][k16 + 2 * tig + 8];
                bl[nf][0] = *(const uint32_t*)&S[3][buf][n][k16 + 2 * tig    ];
                bl[nf][1] = *(const uint32_t*)&S[3][buf][n][k16 + 2 * tig + 8];
            }
#pragma unroll
            for (int mf = 0; mf < 4; mf++) {
                int m = warpM * 64 + mf * 16 + g;
                uint32_t ah[4], al[4];
                ah[0] = *(const uint32_t*)&S[0][buf][m    ][k16 + 2 * tig    ];
                ah[1] = *(const uint32_t*)&S[0][buf][m + 8][k16 + 2 * tig    ];
                ah[2] = *(const uint32_t*)&S[0][buf][m    ][k16 + 2 * tig + 8];
                ah[3] = *(const uint32_t*)&S[0][buf][m + 8][k16 + 2 * tig + 8];
                al[0] = *(const uint32_t*)&S[1][buf][m    ][k16 + 2 * tig    ];
                al[1] = *(const uint32_t*)&S[1][buf][m + 8][k16 + 2 * tig    ];
                al[2] = *(const uint32_t*)&S[1][buf][m    ][k16 + 2 * tig + 8];
                al[3] = *(const uint32_t*)&S[1][buf][m + 8][k16 + 2 * tig + 8];
#pragma unroll
                for (int nf = 0; nf < 4; nf++) {
                    mma_f16(acc [mf][nf], ah, bh[nf]);
                    mma_f16(accx[mf][nf], ah, bl[nf]);
                    mma_f16(accx[mf][nf], al, bh[nf]);
                }
            }
        }
        __syncthreads();
    }

    float* outp = (blockIdx.z == 0) ? g_pk : g_pk2;
    const bool addb = (blockIdx.z == 0);
#pragma unroll
    for (int mf = 0; mf < 4; mf++) {
        int row0 = tileM + warpM * 64 + mf * 16 + g;
        int row1 = row0 + 8;
#pragma unroll
        for (int nf = 0; nf < 4; nf++) {
            int col0 = warpN * 32 + nf * 8 + tig * 2;
            int col1 = col0 + 1;
            float b0 = addb ? g_bp[col0] : 0.f;
            float b1 = addb ? g_bp[col1] : 0.f;
            outp[(size_t)row0 * N + col0] = acc[mf][nf][0] + accx[mf][nf][0] * LO_INV + b0;
            outp[(size_t)row0 * N + col1] = acc[mf][nf][1] + accx[mf][nf][1] * LO_INV + b1;
            outp[(size_t)row1 * N + col0] = acc[mf][nf][2] + accx[mf][nf][2] * LO_INV + b0;
            outp[(size_t)row1 * N + col1] = acc[mf][nf][3] + accx[mf][nf][3] * LO_INV + b1;
        }
    }
}

// ---------------------------------------------------------------------------
// Pure fp16 GEMM, 2 CTAs/SM (R14 body + STAGE==1 path restored).
//   STAGE 1: g_hhi@fw2h -> g_featshi       STAGE 3/4/5: experts (grouped)
// ---------------------------------------------------------------------------
#define HBK 64

template<int STAGE, bool RELU>
__global__ __launch_bounds__(256, 2) void hgemm_k(const __half* __restrict__ Wt,
                                                  const float* __restrict__ Biasg,
                                                  int N, int Kd)
{
    extern __shared__ __half smh[];
    __half (*Ah)[128][72] = (__half(*)[128][72])smh;
    __half (*Bh)[128][72] = (__half(*)[128][72])(smh + 2 * 128 * 72);

    int M;
    const __half* B;
    const float* Bias;
    const __half* A;
    __half* Ch = nullptr;
    float*  Cf = nullptr;
    const int* gather = nullptr;

    if (STAGE == 1) {
        M = BDIM; B = Wt; Bias = Biasg;
        A = g_hhi; Ch = g_featshi;
    } else {
        int e  = blockIdx.z;
        int m0 = g_offsets[e];
        M = g_offsets[e + 1] - m0;
        B    = Wt    + (size_t)e * N * Kd;
        Bias = Biasg + (size_t)e * N;
        if (STAGE == 3)      { A = g_featshi; gather = g_list + m0; Ch = g_h1h + (size_t)m0 * N; }
        else if (STAGE == 4) { A = g_h1h + (size_t)m0 * Kd;         Ch = g_h2h + (size_t)m0 * N; }
        else                 { A = g_h2h + (size_t)m0 * Kd;         Cf = g_eout + (size_t)m0 * N; }
    }

    const int tileM = blockIdx.y * 128;
    if (tileM >= M) return;
    const int tileN = blockIdx.x * 128;

    const int tid  = threadIdx.x;
    const int lane = tid & 31;
    const int wid  = tid >> 5;
    const int g    = lane >> 2;
    const int tig  = lane & 3;
    const int warpM = wid & 1;
    const int warpN = wid >> 1;

    const __half* aptr[4];
    bool av[4];
#pragma unroll
    for (int it = 0; it < 4; it++) {
        int r = (tid >> 3) + it * 32;
        int grow = tileM + r;
        av[it] = (grow < M);
        size_t arow = 0;
        if (av[it]) arow = (STAGE == 3) ? (size_t)gather[grow] : (size_t)grow;
        aptr[it] = A + arow * Kd + (tid & 7) * 8;
    }
    const __half* bptr[4];
    bool bvv[4];
#pragma unroll
    for (int it = 0; it < 4; it++) {
        int r = (tid >> 3) + it * 32;
        int gn = tileN + r;
        bvv[it] = (gn < N);
        bptr[it] = B + (size_t)(bvv[it] ? gn : 0) * Kd + (tid & 7) * 8;
    }

    float acc[4][4][4];
#pragma unroll
    for (int i = 0; i < 4; i++)
#pragma unroll
        for (int j = 0; j < 4; j++)
#pragma unroll
            for (int r = 0; r < 4; r++) acc[i][j][r] = 0.f;

    const int KT = Kd / HBK;

    auto load_tile = [&](int k0, int buf) {
#pragma unroll
        for (int it = 0; it < 4; it++) {
            int r = (tid >> 3) + it * 32;
            cp16(&Ah[buf][r][(tid & 7) * 8], aptr[it] + k0, av[it]);
        }
#pragma unroll
        for (int it = 0; it < 4; it++) {
            int r = (tid >> 3) + it * 32;
            cp16(&Bh[buf][r][(tid & 7) * 8], bptr[it] + k0, bvv[it]);
        }
        asm volatile("cp.async.commit_group;");
    };

    load_tile(0, 0);

    for (int kt = 0; kt < KT; kt++) {
        const int buf = kt & 1;
        if (kt + 1 < KT) {
            load_tile((kt + 1) * HBK, (kt + 1) & 1);
            asm volatile("cp.async.wait_group 1;");
        } else {
            asm volatile("cp.async.wait_group 0;");
        }
        __syncthreads();

#pragma unroll
        for (int ks = 0; ks < 4; ks++) {
            const int k16 = ks * 16;
            uint32_t bf[4][2];
#pragma unroll
            for (int nf = 0; nf < 4; nf++) {
                int n = warpN * 32 + nf * 8 + g;
                bf[nf][0] = *(const uint32_t*)&Bh[buf][n][k16 + 2 * tig    ];
                bf[nf][1] = *(const uint32_t*)&Bh[buf][n][k16 + 2 * tig + 8];
            }
#pragma unroll
            for (int mf = 0; mf < 4; mf++) {
                int m = warpM * 64 + mf * 16 + g;
                uint32_t af[4];
                af[0] = *(const uint32_t*)&Ah[buf][m    ][k16 + 2 * tig    ];
                af[1] = *(const uint32_t*)&Ah[buf][m + 8][k16 + 2 * tig    ];
                af[2] = *(const uint32_t*)&Ah[buf][m    ][k16 + 2 * tig + 8];
                af[3] = *(const uint32_t*)&Ah[buf][m + 8][k16 + 2 * tig + 8];
#pragma unroll
                for (int nf = 0; nf < 4; nf++)
                    mma_f16(acc[mf][nf], af, bf[nf]);
            }
        }
        __syncthreads();
    }

#pragma unroll
    for (int mf = 0; mf < 4; mf++) {
        int row0 = tileM + warpM * 64 + mf * 16 + g;
        int row1 = row0 + 8;
#pragma unroll
        for (int nf = 0; nf < 4; nf++) {
            int col0 = tileN + warpN * 32 + nf * 8 + tig * 2;
            int col1 = col0 + 1;
            float b0 = (col0 < N) ? Bias[col0] : 0.f;
            float b1 = (col1 < N) ? Bias[col1] : 0.f;
            float v00 = acc[mf][nf][0] + b0;
            float v01 = acc[mf][nf][1] + b1;
            float v10 = acc[mf][nf][2] + b0;
            float v11 = acc[mf][nf][3] + b1;
            if (RELU) {
                v00 = fmaxf(v00, 0.f); v01 = fmaxf(v01, 0.f);
                v10 = fmaxf(v10, 0.f); v11 = fmaxf(v11, 0.f);
            }
            if (STAGE == 5) {
                if (row0 < M) {
                    if (col0 < N) Cf[(size_t)row0 * N + col0] = v00;
                    if (col1 < N) Cf[(size_t)row0 * N + col1] = v01;
                }
                if (row1 < M) {
                    if (col0 < N) Cf[(size_t)row1 * N + col0] = v10;
                    if (col1 < N) Cf[(size_t)row1 * N + col1] = v11;
                }
            } else {
                if (row0 < M) {
                    if (col0 < N) Ch[(size_t)row0 * N + col0] = __float2half(v00);
                    if (col1 < N) Ch[(size_t)row0 * N + col1] = __float2half(v01);
                }
                if (row1 < M) {
                    if (col0 < N) Ch[(size_t)row1 * N + col0] = __float2half(v10);
                    if (col1 < N) Ch[(size_t)row1 * N + col1] = __float2half(v11);
                }
            }
        }
    }
}

// ---------------------------------------------------------------------------
// keys normalization / routing / grouping / combine
// (router now sums the two pk partials; otherwise R14-verbatim)
// ---------------------------------------------------------------------------
__global__ void keysn_kernel(const float* __restrict__ keys)
{
    int e    = threadIdx.x >> 5;
    int lane = threadIdx.x & 31;
    if (e >= EDIM) return;
    float4 v = *(const float4*)(keys + e * KDIM + lane * 4);
    float ss = v.x * v.x + v.y * v.y + v.z * v.z + v.w * v.w;
#pragma unroll
    for (int o = 16; o; o >>= 1) ss += __shfl_xor_sync(0xffffffffu, ss, o);
    float inv = 1.f / fmaxf(sqrtf(ss), 1e-12f);
    float4 o4 = make_float4(v.x * inv, v.y * inv, v.z * inv, v.w * inv);
    *(float4*)(g_keysn + e * KDIM + lane * 4) = o4;
}

__global__ void zero_counts_kernel()
{
    if (threadIdx.x < EDIM) g_counts[threadIdx.x] = 0;
}

__global__ void router_kernel()
{
    int warp = threadIdx.x >> 5;
    int lane = threadIdx.x & 31;
    int t = blockIdx.x * 8 + warp;
    if (t >= BDIM) return;

    float4 v1 = *(const float4*)(g_pk  + (size_t)t * KDIM + lane * 4);
    float4 v2 = *(const float4*)(g_pk2 + (size_t)t * KDIM + lane * 4);
    float4 v  = make_float4(v1.x + v2.x, v1.y + v2.y, v1.z + v2.z, v1.w + v2.w);
    float ss = v.x * v.x + v.y * v.y + v.z * v.z + v.w * v.w;
#pragma unroll
    for (int o = 16; o; o >>= 1) ss += __shfl_xor_sync(0xffffffffu, ss, o);
    float inv = 1.f / fmaxf(sqrtf(ss), 1e-12f);

    float sims[EDIM];
#pragma unroll
    for (int e = 0; e < EDIM; e++) {
        float4 kv = *(const float4*)(g_keysn + e * KDIM + lane * 4);
        float d = v.x * kv.x + v.y * kv.y + v.z * kv.z + v.w * kv.w;
#pragma unroll
        for (int o = 16; o; o >>= 1) d += __shfl_xor_sync(0xffffffffu, d, o);
        sims[e] = d * inv;
    }

    if (lane == 0) {
        int i0 = 0; float v0 = sims[0];
#pragma unroll
        for (int e = 1; e < EDIM; e++) if (sims[e] > v0) { v0 = sims[e]; i0 = e; }
        int i1 = -1; float v1s = -1e30f;
#pragma unroll
        for (int e = 0; e < EDIM; e++) if (e != i0 && sims[e] > v1s) { v1s = sims[e]; i1 = e; }

        float e1 = expf(v1s - v0);
        float s  = 1.f + e1;
        float w0 = 1.f / s;
        float w1 = e1 / s;

#pragma unroll
        for (int e = 0; e < EDIM; e++) {
            g_sim[t * EDIM + e] = sims[e];
            g_weights[t * EDIM + e] = (e == i0) ? w0 : ((e == i1) ? w1 : 0.f);
        }
        g_topi[t * TOPK + 0] = i0;
        g_topi[t * TOPK + 1] = i1;
        g_wslot[t * TOPK + 0] = w0;
        g_wslot[t * TOPK + 1] = w1;
        atomicAdd(&g_counts[i0], 1);
        atomicAdd(&g_counts[i1], 1);
    }
}

__global__ void scan_kernel()
{
    if (threadIdx.x == 0) {
        int off = 0;
        for (int e = 0; e < EDIM; e++) {
            g_offsets[e] = off;
            g_cursor[e]  = off;
            off += g_counts[e];
        }
        g_offsets[EDIM] = off;
    }
}

__global__ void scatter_kernel()
{
    int t = blockIdx.x * blockDim.x + threadIdx.x;
    if (t >= BDIM) return;
#pragma unroll
    for (int s = 0; s < TOPK; s++) {
        int e = g_topi[t * TOPK + s];
        int pos = atomicAdd(&g_cursor[e], 1);
        g_list[pos] = t;
        g_pos[t * TOPK + s] = pos;
    }
}

__global__ void combine_kernel(float* __restrict__ out)
{
    int t = blockIdx.x;
    float w0 = g_wslot[t * TOPK + 0];
    float w1 = g_wslot[t * TOPK + 1];
    size_t p0 = (size_t)g_pos[t * TOPK + 0];
    size_t p1 = (size_t)g_pos[t * TOPK + 1];
    for (int c = threadIdx.x; c < CDIM; c += blockDim.x)
        out[(size_t)t * CDIM + c] =
            w0 * g_eout[p0 * CDIM + c] + w1 * g_eout[p1 * CDIM + c];
}

__global__ void tail_writer_kernel(float* __restrict__ out, long long out_size)
{
    long long i = (long long)blockIdx.x * blockDim.x + threadIdx.x;
    const long long base_w = (long long)BDIM * CDIM;
    const long long n_w = BDIM * EDIM;
    const long long base_t = base_w + n_w;
    const long long n_t = BDIM * TOPK;
    const long long base_s = base_t + n_t;
    const long long n_s = BDIM * EDIM;
    if (i < n_w && base_w + i < out_size) out[base_w + i] = g_weights[i];
    if (i < n_t && base_t + i < out_size) out[base_t + i] = (float)g_topi[i];
    if (i < n_s && base_s + i < out_size) out[base_s + i] = g_sim[i];
}

// ---------------------------------------------------------------------------
// Launch
// ---------------------------------------------------------------------------
#define SG_SMEM (4 * 2 * 128 * 40 * (int)sizeof(__half))   // 81920 B
#define HG_SMEM (2 * 2 * 128 * 72 * (int)sizeof(__half))   // 73728 B

extern "C" void kernel_launch(void* const* d_in, const int* in_sizes, int n_in,
                              void* d_out, int out_size)
{
    const float* x    = (const float*)d_in[0];
    const float* fw1  = (const float*)d_in[1];
    const float* fb1  = (const float*)d_in[2];
    const float* fw2  = (const float*)d_in[3];
    const float* fb2  = (const float*)d_in[4];
    const float* kw   = (const float*)d_in[5];
    const float* kb   = (const float*)d_in[6];
    const float* keys = (const float*)d_in[7];
    const float* ew1  = (const float*)d_in[8];
    const float* eb1  = (const float*)d_in[9];
    const float* ew2  = (const float*)d_in[10];
    const float* eb2  = (const float*)d_in[11];
    const float* ew3  = (const float*)d_in[12];
    const float* eb3  = (const float*)d_in[13];
    float* out = (float*)d_out;

    cudaFuncSetAttribute(sgemm_k<0, true >, cudaFuncAttributeMaxDynamicSharedMemorySize, SG_SMEM);
    cudaFuncSetAttribute(sgemm_k<7, false>, cudaFuncAttributeMaxDynamicSharedMemorySize, SG_SMEM);
    cudaFuncSetAttribute(stage2s_k,         cudaFuncAttributeMaxDynamicSharedMemorySize, SG_SMEM);
    cudaFuncSetAttribute(hgemm_k<1, false>, cudaFuncAttributeMaxDynamicSharedMemorySize, HG_SMEM);
    cudaFuncSetAttribute(hgemm_k<3, true >, cudaFuncAttributeMaxDynamicSharedMemorySize, HG_SMEM);
    cudaFuncSetAttribute(hgemm_k<4, true >, cudaFuncAttributeMaxDynamicSharedMemorySize, HG_SMEM);
    cudaFuncSetAttribute(hgemm_k<5, false>, cudaFuncAttributeMaxDynamicSharedMemorySize, HG_SMEM);

    dim3 blk(256);
    dim3 tblk(32, 8);

    __half *xhi, *xlo, *fw1hi, *fw1lo, *fw2h, *fw2nhi, *fw2nlo, *kwhi, *kwlo;
    __half *ew1h, *ew2h, *ew3h;
    float  *zbias;
    cudaGetSymbolAddress((void**)&xhi,    g_xhi);
    cudaGetSymbolAddress((void**)&xlo,    g_xlo);
    cudaGetSymbolAddress((void**)&fw1hi,  g_fw1hi);
    cudaGetSymbolAddress((void**)&fw1lo,  g_fw1lo);
    cudaGetSymbolAddress((void**)&fw2h,   g_fw2h);
    cudaGetSymbolAddress((void**)&fw2nhi, g_fw2nhi);
    cudaGetSymbolAddress((void**)&fw2nlo, g_fw2nlo);
    cudaGetSymbolAddress((void**)&kwhi,   g_kwhi);
    cudaGetSymbolAddress((void**)&kwlo,   g_kwlo);
    cudaGetSymbolAddress((void**)&ew1h,   g_ew1h);
    cudaGetSymbolAddress((void**)&ew2h,   g_ew2h);
    cudaGetSymbolAddress((void**)&ew3h,   g_ew3h);
    cudaGetSymbolAddress((void**)&zbias,  g_zbias);

    // one-time conversions (R14-verbatim)
    natsplit_k<<<BDIM * DDIM / 4 / 256, 256>>>(x, xhi, xlo);
    natsplit_k<<<HDIM * HDIM / 4 / 256, 256>>>(fw2, fw2nhi, fw2nlo);
    wsplit_k<<<dim3(HDIM / 32, DDIM / 32), tblk>>>(fw1, fw1hi, fw1lo, DDIM, HDIM);
    wsplit_k<<<dim3(KDIM / 32, HDIM / 32), tblk>>>(kw,  kwhi,  kwlo,  HDIM, KDIM);
    wconv_k<<<dim3(HDIM / 32,        HDIM / 32,  1   ), tblk>>>(fw2, fw2h, HDIM,  HDIM);
    wconv_k<<<dim3(HDIM / 32,        HDIM / 32,  EDIM), tblk>>>(ew1, ew1h, HDIM,  HDIM);
    wconv_k<<<dim3(H2DIM / 32,       HDIM / 32,  EDIM), tblk>>>(ew2, ew2h, HDIM,  H2DIM);
    wconv_k<<<dim3((CDIM + 31) / 32, H2DIM / 32, EDIM), tblk>>>(ew3, ew3h, H2DIM, CDIM);
    bprime_k<<<KDIM, 256>>>(fb2, kw, kb);

    // W'^T = kw^T @ fw2 (fp32-grade split output)
    sgemm_k<7, false><<<dim3(HDIM / 128, 1), blk, SG_SMEM>>>(fw2nhi, fw2nlo, zbias, HDIM, HDIM);

    keysn_kernel<<<1, 256>>>(keys);
    zero_counts_kernel<<<1, 32>>>();

    // stage0: x @ fw1 -> h split (fp32-grade, relu)
    sgemm_k<0, true ><<<dim3(HDIM / 128, BDIM / 128), blk, SG_SMEM>>>(fw1hi, fw1lo, fb1, HDIM, DDIM);

    // stage1: h @ fw2 -> feats (fp16, 2 CTAs/SM)
    hgemm_k<1, false><<<dim3(HDIM / 128, BDIM / 128, 1), blk, HG_SMEM>>>(fw2h, fb2, HDIM, HDIM);

    // stage2: h @ W' -> pk, K split over 2 grid planes (128 CTAs)
    stage2s_k<<<dim3(1, BDIM / 128, 2), blk, SG_SMEM>>>();

    router_kernel<<<BDIM / 8, 256>>>();
    scan_kernel<<<1, 32>>>();
    scatter_kernel<<<(BDIM + 255) / 256, 256>>>();

    // expert MLPs: fp16 HMMA, 2 CTAs/SM
    hgemm_k<3, true ><<<dim3(HDIM / 128,         BDIM / 128, EDIM), blk, HG_SMEM>>>(ew1h, eb1, HDIM,  HDIM);
    hgemm_k<4, true ><<<dim3(H2DIM / 128,        BDIM / 128, EDIM), blk, HG_SMEM>>>(ew2h, eb2, H2DIM, HDIM);
    hgemm_k<5, false><<<dim3((CDIM + 127) / 128, BDIM / 128, EDIM), blk, HG_SMEM>>>(ew3h, eb3, CDIM,  H2DIM);

    combine_kernel<<<BDIM, 256>>>(out);
    tail_writer_kernel<<<(BDIM * EDIM + 255) / 256, 256>>>(out, (long long)out_size);
}

// round 16
// speedup vs baseline: 1.2581x; 1.0097x over previous
#include <cuda_runtime.h>
#include <cuda_fp16.h>
#include <math.h>
#include <stdint.h>

// ---------------------------------------------------------------------------
// Problem constants
// ---------------------------------------------------------------------------
#define BDIM   8192
#define DDIM   1024
#define HDIM   2048
#define H2DIM  1024
#define CDIM   1000
#define KDIM   128
#define EDIM   8
#define TOPK   2
#define MAXROWS (BDIM * TOPK)

// ---------------------------------------------------------------------------
// Scratch (device globals — no allocation allowed)
// ---------------------------------------------------------------------------
__device__ __half g_xhi  [(size_t)BDIM * DDIM];
__device__ __half g_xlo  [(size_t)BDIM * DDIM];
__device__ __half g_hhi  [(size_t)BDIM * HDIM];
__device__ __half g_hlo  [(size_t)BDIM * HDIM];
__device__ __half g_featshi[(size_t)BDIM * HDIM];
__device__ float  g_pk   [(size_t)BDIM * KDIM];
__device__ float  g_pk2  [(size_t)BDIM * KDIM];
__device__ float  g_keysn[EDIM * KDIM];
__device__ float  g_sim  [BDIM * EDIM];
__device__ float  g_weights[BDIM * EDIM];
__device__ float  g_wslot[BDIM * TOPK];
__device__ int    g_topi [BDIM * TOPK];
__device__ int    g_counts[EDIM];
__device__ int    g_offsets[EDIM + 1];
__device__ int    g_cursor[EDIM];
__device__ int    g_list [MAXROWS];
__device__ int    g_pos  [BDIM * TOPK];
__device__ __half g_h1h  [(size_t)MAXROWS * HDIM];
__device__ __half g_h2h  [(size_t)MAXROWS * H2DIM];
__device__ float  g_eout [(size_t)MAXROWS * CDIM];
// converted weights
__device__ __half g_fw1hi[(size_t)HDIM * DDIM];   // fw1^T split  [H][D]
__device__ __half g_fw1lo[(size_t)HDIM * DDIM];
__device__ __half g_fw2h [(size_t)HDIM * HDIM];   // fw2^T single [Hout][Hin]
__device__ __half g_fw2nhi[(size_t)HDIM * HDIM];  // fw2 natural split [Hin][Hout]
__device__ __half g_fw2nlo[(size_t)HDIM * HDIM];
__device__ __half g_kwhi [(size_t)KDIM * HDIM];   // kw^T split   [K][H]
__device__ __half g_kwlo [(size_t)KDIM * HDIM];
__device__ __half g_wphi [(size_t)KDIM * HDIM];   // W'^T split   [K][H]
__device__ __half g_wplo [(size_t)KDIM * HDIM];
__device__ float  g_bp   [KDIM];                  // b' = fb2@kw + kb
__device__ float  g_zbias[HDIM];                  // zeros (static init)
__device__ __half g_ew1h [(size_t)EDIM * HDIM  * HDIM];
__device__ __half g_ew2h [(size_t)EDIM * H2DIM * HDIM];
__device__ __half g_ew3h [(size_t)EDIM * CDIM  * H2DIM];

#define LO_SCALE 4096.0f
#define LO_INV   (1.0f / 4096.0f)

// ---------------------------------------------------------------------------
// helpers
// ---------------------------------------------------------------------------
__device__ __forceinline__ void mma_f16(float c[4],
                                        const uint32_t a[4],
                                        const uint32_t b[2]) {
    asm volatile(
        "mma.sync.aligned.m16n8k16.row.col.f32.f16.f16.f32 "
        "{%0,%1,%2,%3}, {%4,%5,%6,%7}, {%8,%9}, {%0,%1,%2,%3};"
        : "+f"(c[0]), "+f"(c[1]), "+f"(c[2]), "+f"(c[3])
        : "r"(a[0]), "r"(a[1]), "r"(a[2]), "r"(a[3]),
          "r"(b[0]), "r"(b[1]));
}
__device__ __forceinline__ void cp16(void* dst, const void* src, bool valid) {
    uint32_t d = (uint32_t)__cvta_generic_to_shared(dst);
    int sz = valid ? 16 : 0;
    asm volatile("cp.async.cg.shared.global [%0], [%1], 16, %2;"
                 :: "r"(d), "l"(src), "r"(sz));
}
__device__ __forceinline__ void split_f32(float v, __half& hi, __half& lo) {
    hi = __float2half(v);
    lo = __float2half((v - __half2float(hi)) * LO_SCALE);
}

// ---------------------------------------------------------------------------
// One-time conversions (R15-verbatim)
// ---------------------------------------------------------------------------
__global__ void natsplit_k(const float* __restrict__ W,
                           __half* __restrict__ Whi, __half* __restrict__ Wlo)
{
    size_t i = ((size_t)blockIdx.x * 256 + threadIdx.x) * 4;
    float4 v = *(const float4*)(W + i);
    __half h0, l0, h1, l1, h2, l2, h3, l3;
    split_f32(v.x, h0, l0); split_f32(v.y, h1, l1);
    split_f32(v.z, h2, l2); split_f32(v.w, h3, l3);
    *(__half2*)&Whi[i]     = __halves2half2(h0, h1);
    *(__half2*)&Whi[i + 2] = __halves2half2(h2, h3);
    *(__half2*)&Wlo[i]     = __halves2half2(l0, l1);
    *(__half2*)&Wlo[i + 2] = __halves2half2(l2, l3);
}

__global__ void wsplit_k(const float* __restrict__ W,
                         __half* __restrict__ Whi, __half* __restrict__ Wlo,
                         int K, int N)
{
    __shared__ float t[32][33];
    int k0 = blockIdx.y * 32;
    int n0 = blockIdx.x * 32;
#pragma unroll
    for (int j = 0; j < 4; j++)
        t[threadIdx.y + j * 8][threadIdx.x] =
            W[(size_t)(k0 + threadIdx.y + j * 8) * N + n0 + threadIdx.x];
    __syncthreads();
#pragma unroll
    for (int j = 0; j < 4; j++) {
        int n = n0 + threadIdx.y + j * 8;
        int k = k0 + threadIdx.x;
        float val = t[threadIdx.x][threadIdx.y + j * 8];
        __half hi, lo;
        split_f32(val, hi, lo);
        Whi[(size_t)n * K + k] = hi;
        Wlo[(size_t)n * K + k] = lo;
    }
}

__global__ void wconv_k(const float* __restrict__ Wg, __half* __restrict__ Wtg,
                        int K, int N)
{
    const float* W  = Wg  + (size_t)blockIdx.z * K * N;
    __half*      Wt = Wtg + (size_t)blockIdx.z * N * K;
    __shared__ float t[32][33];
    int k0 = blockIdx.y * 32;
    int n0 = blockIdx.x * 32;
#pragma unroll
    for (int j = 0; j < 4; j++) {
        int n = n0 + threadIdx.x;
        if (n < N) t[threadIdx.y + j * 8][threadIdx.x] =
            W[(size_t)(k0 + threadIdx.y + j * 8) * N + n];
    }
    __syncthreads();
#pragma unroll
    for (int j = 0; j < 4; j++) {
        int n = n0 + threadIdx.y + j * 8;
        int k = k0 + threadIdx.x;
        if (n < N) Wt[(size_t)n * K + k] =
            __float2half(t[threadIdx.x][threadIdx.y + j * 8]);
    }
}

__global__ void bprime_k(const float* __restrict__ fb2,
                         const float* __restrict__ kw,
                         const float* __restrict__ kb)
{
    int j = blockIdx.x;
    float s = 0.f;
    for (int m = threadIdx.x; m < HDIM; m += 256)
        s += fb2[m] * kw[(size_t)m * KDIM + j];
    __shared__ float red[8];
#pragma unroll
    for (int o = 16; o; o >>= 1) s += __shfl_xor_sync(0xffffffffu, s, o);
    if ((threadIdx.x & 31) == 0) red[threadIdx.x >> 5] = s;
    __syncthreads();
    if (threadIdx.x == 0) {
        float t = 0.f;
#pragma unroll
        for (int w = 0; w < 8; w++) t += red[w];
        g_bp[j] = t + kb[j];
    }
}

// ---------------------------------------------------------------------------
// fp16 2-term-split GEMM, NEW 128x64 CTA tile, 2 CTAs/SM (STAGE 0 and 7).
// Warp tile 64x16 (acc+accx = 64 floats/thread -> fits 128-reg cap).
// Per-output K-sum order identical to the 128x128 version (bit-identical).
// ---------------------------------------------------------------------------
#define SBK 32

template<int STAGE, bool RELU>
__global__ __launch_bounds__(256, 2) void sgemm_k(const __half* __restrict__ Whi,
                                                  const __half* __restrict__ Wlo,
                                                  const float* __restrict__ Bias,
                                                  int N, int Kd)
{
    extern __shared__ __half sms[];
    __half (*Ahi_s)[128][40] = (__half(*)[128][40])sms;
    __half (*Alo_s)[128][40] = (__half(*)[128][40])(sms + 2 * 128 * 40);
    __half (*Bhi_s)[64][40]  = (__half(*)[64][40]) (sms + 4 * 128 * 40);
    __half (*Blo_s)[64][40]  = (__half(*)[64][40]) (sms + 4 * 128 * 40 + 2 * 64 * 40);

    const __half *Ahi, *Alo;
    if (STAGE == 0)      { Ahi = g_xhi;  Alo = g_xlo;  }
    else                 { Ahi = g_kwhi; Alo = g_kwlo; }

    const int tileM = blockIdx.y * 128;
    const int tileN = blockIdx.x * 64;

    const int tid  = threadIdx.x;
    const int lane = tid & 31;
    const int wid  = tid >> 5;
    const int g    = lane >> 2;
    const int tig  = lane & 3;
    const int warpM = wid & 1;    // 2 x 64 rows
    const int warpN = wid >> 1;   // 4 x 16 cols

    const int rr = tid >> 2;        // 0..63
    const int cc = (tid & 3) * 8;   // 0,8,16,24

    const size_t aoff = (size_t)(tileM + rr) * Kd + cc;
    const size_t boff = (size_t)(tileN + rr) * Kd + cc;
    const size_t rstep = (size_t)64 * Kd;

    float acc [4][2][4];
    float accx[4][2][4];
#pragma unroll
    for (int i = 0; i < 4; i++)
#pragma unroll
        for (int j = 0; j < 2; j++)
#pragma unroll
            for (int r = 0; r < 4; r++) { acc[i][j][r] = 0.f; accx[i][j][r] = 0.f; }

    const int KT = Kd / SBK;

    auto load_tile = [&](int k0, int buf) {
#pragma unroll
        for (int it = 0; it < 2; it++) {
            cp16(&Ahi_s[buf][rr + it * 64][cc], Ahi + aoff + it * rstep + k0, true);
            cp16(&Alo_s[buf][rr + it * 64][cc], Alo + aoff + it * rstep + k0, true);
        }
        cp16(&Bhi_s[buf][rr][cc], Whi + boff + k0, true);
        cp16(&Blo_s[buf][rr][cc], Wlo + boff + k0, true);
        asm volatile("cp.async.commit_group;");
    };

    load_tile(0, 0);

    for (int kt = 0; kt < KT; kt++) {
        const int buf = kt & 1;
        if (kt + 1 < KT) {
            load_tile((kt + 1) * SBK, (kt + 1) & 1);
            asm volatile("cp.async.wait_group 1;");
        } else {
            asm volatile("cp.async.wait_group 0;");
        }
        __syncthreads();

#pragma unroll
        for (int ks = 0; ks < 2; ks++) {
            const int k16 = ks * 16;
            uint32_t bh[2][2], bl[2][2];
#pragma unroll
            for (int nf = 0; nf < 2; nf++) {
                int n = warpN * 16 + nf * 8 + g;
                bh[nf][0] = *(const uint32_t*)&Bhi_s[buf][n][k16 + 2 * tig    ];
                bh[nf][1] = *(const uint32_t*)&Bhi_s[buf][n][k16 + 2 * tig + 8];
                bl[nf][0] = *(const uint32_t*)&Blo_s[buf][n][k16 + 2 * tig    ];
                bl[nf][1] = *(const uint32_t*)&Blo_s[buf][n][k16 + 2 * tig + 8];
            }
#pragma unroll
            for (int mf = 0; mf < 4; mf++) {
                int m = warpM * 64 + mf * 16 + g;
                uint32_t ah[4], al[4];
                ah[0] = *(const uint32_t*)&Ahi_s[buf][m    ][k16 + 2 * tig    ];
                ah[1] = *(const uint32_t*)&Ahi_s[buf][m + 8][k16 + 2 * tig    ];
                ah[2] = *(const uint32_t*)&Ahi_s[buf][m    ][k16 + 2 * tig + 8];
                ah[3] = *(const uint32_t*)&Ahi_s[buf][m + 8][k16 + 2 * tig + 8];
                al[0] = *(const uint32_t*)&Alo_s[buf][m    ][k16 + 2 * tig    ];
                al[1] = *(const uint32_t*)&Alo_s[buf][m + 8][k16 + 2 * tig    ];
                al[2] = *(const uint32_t*)&Alo_s[buf][m    ][k16 + 2 * tig + 8];
                al[3] = *(const uint32_t*)&Alo_s[buf][m + 8][k16 + 2 * tig + 8];
#pragma unroll
                for (int nf = 0; nf < 2; nf++) {
                    mma_f16(acc [mf][nf], ah, bh[nf]);
                    mma_f16(accx[mf][nf], ah, bl[nf]);
                    mma_f16(accx[mf][nf], al, bh[nf]);
                }
            }
        }
        __syncthreads();
    }

#pragma unroll
    for (int mf = 0; mf < 4; mf++) {
        int row0 = tileM + warpM * 64 + mf * 16 + g;
        int row1 = row0 + 8;
#pragma unroll
        for (int nf = 0; nf < 2; nf++) {
            int col0 = tileN + warpN * 16 + nf * 8 + tig * 2;
            int col1 = col0 + 1;
            float b0 = Bias[col0];
            float b1 = Bias[col1];
            float v00 = acc[mf][nf][0] + accx[mf][nf][0] * LO_INV + b0;
            float v01 = acc[mf][nf][1] + accx[mf][nf][1] * LO_INV + b1;
            float v10 = acc[mf][nf][2] + accx[mf][nf][2] * LO_INV + b0;
            float v11 = acc[mf][nf][3] + accx[mf][nf][3] * LO_INV + b1;
            if (RELU) {
                v00 = fmaxf(v00, 0.f); v01 = fmaxf(v01, 0.f);
                v10 = fmaxf(v10, 0.f); v11 = fmaxf(v11, 0.f);
            }
            __half* Hi = (STAGE == 0) ? g_hhi : g_wphi;
            __half* Lo = (STAGE == 0) ? g_hlo : g_wplo;
            __half h, l;
            split_f32(v00, h, l);
            Hi[(size_t)row0 * N + col0] = h; Lo[(size_t)row0 * N + col0] = l;
            split_f32(v01, h, l);
            Hi[(size_t)row0 * N + col1] = h; Lo[(size_t)row0 * N + col1] = l;
            split_f32(v10, h, l);
            Hi[(size_t)row1 * N + col0] = h; Lo[(size_t)row1 * N + col0] = l;
            split_f32(v11, h, l);
            Hi[(size_t)row1 * N + col1] = h; Lo[(size_t)row1 * N + col1] = l;
        }
    }
}

// ---------------------------------------------------------------------------
// stage2 split-GEMM with K split across blockIdx.z (R15-verbatim)
// ---------------------------------------------------------------------------
__global__ __launch_bounds__(256) void stage2s_k()
{
    extern __shared__ __half smf[];
    __half (*S)[2][128][40] = (__half(*)[2][128][40])smf;

    const int tid  = threadIdx.x;
    const int lane = tid & 31;
    const int wid  = tid >> 5;
    const int g    = lane >> 2;
    const int tig  = lane & 3;
    const int warpM = wid & 1;
    const int warpN = wid >> 1;

    const int N  = KDIM;
    const int Kd = HDIM;
    const int kbase = blockIdx.z * (HDIM / 2);
    const int tileM = blockIdx.y * 128;

    const int rr = tid >> 2;
    const int cc = (tid & 3) * 8;
    const size_t aoff = (size_t)(tileM + rr) * Kd + kbase + cc;
    const size_t boff = (size_t)rr * Kd + kbase + cc;
    const size_t rstep = (size_t)64 * Kd;

    float acc [4][4][4];
    float accx[4][4][4];
#pragma unroll
    for (int i = 0; i < 4; i++)
#pragma unroll
        for (int j = 0; j < 4; j++)
#pragma unroll
            for (int r = 0; r < 4; r++) { acc[i][j][r] = 0.f; accx[i][j][r] = 0.f; }

    const int KT = (HDIM / 2) / SBK;

    auto load_tile = [&](int k0, int buf) {
#pragma unroll
        for (int it = 0; it < 2; it++) {
            cp16(&S[0][buf][rr + it * 64][cc], g_hhi  + aoff + it * rstep + k0, true);
            cp16(&S[1][buf][rr + it * 64][cc], g_hlo  + aoff + it * rstep + k0, true);
            cp16(&S[2][buf][rr + it * 64][cc], g_wphi + boff + it * rstep + k0, true);
            cp16(&S[3][buf][rr + it * 64][cc], g_wplo + boff + it * rstep + k0, true);
        }
        asm volatile("cp.async.commit_group;");
    };

    load_tile(0, 0);

    for (int kt = 0; kt < KT; kt++) {
        const int buf = kt & 1;
        if (kt + 1 < KT) {
            load_tile((kt + 1) * SBK, (kt + 1) & 1);
            asm volatile("cp.async.wait_group 1;");
        } else {
            asm volatile("cp.async.wait_group 0;");
        }
        __syncthreads();

#pragma unroll
        for (int ks = 0; ks < 2; ks++) {
            const int k16 = ks * 16;
            uint32_t bh[4][2], bl[4][2];
#pragma unroll
            for (int nf = 0; nf < 4; nf++) {
                int n = warpN * 32 + nf * 8 + g;
                bh[nf][0] = *(const uint32_t*)&S[2][buf][n][k16 + 2 * tig    ];
                bh[nf][1] = *(const uint32_t*)&S[2][buf][n][k16 + 2 * tig + 8];
                bl[nf][0] = *(const uint32_t*)&S[3][buf][n][k16 + 2 * tig    ];
                bl[nf][1] = *(const uint32_t*)&S[3][buf][n][k16 + 2 * tig + 8];
            }
#pragma unroll
            for (int mf = 0; mf < 4; mf++) {
                int m = warpM * 64 + mf * 16 + g;
                uint32_t ah[4], al[4];
                ah[0] = *(const uint32_t*)&S[0][buf][m    ][k16 + 2 * tig    ];
                ah[1] = *(const uint32_t*)&S[0][buf][m + 8][k16 + 2 * tig    ];
                ah[2] = *(const uint32_t*)&S[0][buf][m    ][k16 + 2 * tig + 8];
                ah[3] = *(const uint32_t*)&S[0][buf][m + 8][k16 + 2 * tig + 8];
                al[0] = *(const uint32_t*)&S[1][buf][m    ][k16 + 2 * tig    ];
                al[1] = *(const uint32_t*)&S[1][buf][m + 8][k16 + 2 * tig    ];
                al[2] = *(const uint32_t*)&S[1][buf][m    ][k16 + 2 * tig + 8];
                al[3] = *(const uint32_t*)&S[1][buf][m + 8][k16 + 2 * tig + 8];
#pragma unroll
                for (int nf = 0; nf < 4; nf++) {
                    mma_f16(acc [mf][nf], ah, bh[nf]);
                    mma_f16(accx[mf][nf], ah, bl[nf]);
                    mma_f16(accx[mf][nf], al, bh[nf]);
                }
            }
        }
        __syncthreads();
    }

    float* outp = (blockIdx.z == 0) ? g_pk : g_pk2;
    const bool addb = (blockIdx.z == 0);
#pragma unroll
    for (int mf = 0; mf < 4; mf++) {
        int row0 = tileM + warpM * 64 + mf * 16 + g;
        int row1 = row0 + 8;
#pragma unroll
        for (int nf = 0; nf < 4; nf++) {
            int col0 = warpN * 32 + nf * 8 + tig * 2;
            int col1 = col0 + 1;
            float b0 = addb ? g_bp[col0] : 0.f;
            float b1 = addb ? g_bp[col1] : 0.f;
            outp[(size_t)row0 * N + col0] = acc[mf][nf][0] + accx[mf][nf][0] * LO_INV + b0;
            outp[(size_t)row0 * N + col1] = acc[mf][nf][1] + accx[mf][nf][1] * LO_INV + b1;
            outp[(size_t)row1 * N + col0] = acc[mf][nf][2] + accx[mf][nf][2] * LO_INV + b0;
            outp[(size_t)row1 * N + col1] = acc[mf][nf][3] + accx[mf][nf][3] * LO_INV + b1;
        }
    }
}

// ---------------------------------------------------------------------------
// Pure fp16 GEMM, 2 CTAs/SM (R15-verbatim)
// ---------------------------------------------------------------------------
#define HBK 64

template<int STAGE, bool RELU>
__global__ __launch_bounds__(256, 2) void hgemm_k(const __half* __restrict__ Wt,
                                                  const float* __restrict__ Biasg,
                                                  int N, int Kd)
{
    extern __shared__ __half smh[];
    __half (*Ah)[128][72] = (__half(*)[128][72])smh;
    __half (*Bh)[128][72] = (__half(*)[128][72])(smh + 2 * 128 * 72);

    int M;
    const __half* B;
    const float* Bias;
    const __half* A;
    __half* Ch = nullptr;
    float*  Cf = nullptr;
    const int* gather = nullptr;

    if (STAGE == 1) {
        M = BDIM; B = Wt; Bias = Biasg;
        A = g_hhi; Ch = g_featshi;
    } else {
        int e  = blockIdx.z;
        int m0 = g_offsets[e];
        M = g_offsets[e + 1] - m0;
        B    = Wt    + (size_t)e * N * Kd;
        Bias = Biasg + (size_t)e * N;
        if (STAGE == 3)      { A = g_featshi; gather = g_list + m0; Ch = g_h1h + (size_t)m0 * N; }
        else if (STAGE == 4) { A = g_h1h + (size_t)m0 * Kd;         Ch = g_h2h + (size_t)m0 * N; }
        else                 { A = g_h2h + (size_t)m0 * Kd;         Cf = g_eout + (size_t)m0 * N; }
    }

    const int tileM = blockIdx.y * 128;
    if (tileM >= M) return;
    const int tileN = blockIdx.x * 128;

    const int tid  = threadIdx.x;
    const int lane = tid & 31;
    const int wid  = tid >> 5;
    const int g    = lane >> 2;
    const int tig  = lane & 3;
    const int warpM = wid & 1;
    const int warpN = wid >> 1;

    const __half* aptr[4];
    bool av[4];
#pragma unroll
    for (int it = 0; it < 4; it++) {
        int r = (tid >> 3) + it * 32;
        int grow = tileM + r;
        av[it] = (grow < M);
        size_t arow = 0;
        if (av[it]) arow = (STAGE == 3) ? (size_t)gather[grow] : (size_t)grow;
        aptr[it] = A + arow * Kd + (tid & 7) * 8;
    }
    const __half* bptr[4];
    bool bvv[4];
#pragma unroll
    for (int it = 0; it < 4; it++) {
        int r = (tid >> 3) + it * 32;
        int gn = tileN + r;
        bvv[it] = (gn < N);
        bptr[it] = B + (size_t)(bvv[it] ? gn : 0) * Kd + (tid & 7) * 8;
    }

    float acc[4][4][4];
#pragma unroll
    for (int i = 0; i < 4; i++)
#pragma unroll
        for (int j = 0; j < 4; j++)
#pragma unroll
            for (int r = 0; r < 4; r++) acc[i][j][r] = 0.f;

    const int KT = Kd / HBK;

    auto load_tile = [&](int k0, int buf) {
#pragma unroll
        for (int it = 0; it < 4; it++) {
            int r = (tid >> 3) + it * 32;
            cp16(&Ah[buf][r][(tid & 7) * 8], aptr[it] + k0, av[it]);
        }
#pragma unroll
        for (int it = 0; it < 4; it++) {
            int r = (tid >> 3) + it * 32;
            cp16(&Bh[buf][r][(tid & 7) * 8], bptr[it] + k0, bvv[it]);
        }
        asm volatile("cp.async.commit_group;");
    };

    load_tile(0, 0);

    for (int kt = 0; kt < KT; kt++) {
        const int buf = kt & 1;
        if (kt + 1 < KT) {
            load_tile((kt + 1) * HBK, (kt + 1) & 1);
            asm volatile("cp.async.wait_group 1;");
        } else {
            asm volatile("cp.async.wait_group 0;");
        }
        __syncthreads();

#pragma unroll
        for (int ks = 0; ks < 4; ks++) {
            const int k16 = ks * 16;
            uint32_t bf[4][2];
#pragma unroll
            for (int nf = 0; nf < 4; nf++) {
                int n = warpN * 32 + nf * 8 + g;
                bf[nf][0] = *(const uint32_t*)&Bh[buf][n][k16 + 2 * tig    ];
                bf[nf][1] = *(const uint32_t*)&Bh[buf][n][k16 + 2 * tig + 8];
            }
#pragma unroll
            for (int mf = 0; mf < 4; mf++) {
                int m = warpM * 64 + mf * 16 + g;
                uint32_t af[4];
                af[0] = *(const uint32_t*)&Ah[buf][m    ][k16 + 2 * tig    ];
                af[1] = *(const uint32_t*)&Ah[buf][m + 8][k16 + 2 * tig    ];
                af[2] = *(const uint32_t*)&Ah[buf][m    ][k16 + 2 * tig + 8];
                af[3] = *(const uint32_t*)&Ah[buf][m + 8][k16 + 2 * tig + 8];
#pragma unroll
                for (int nf = 0; nf < 4; nf++)
                    mma_f16(acc[mf][nf], af, bf[nf]);
            }
        }
        __syncthreads();
    }

#pragma unroll
    for (int mf = 0; mf < 4; mf++) {
        int row0 = tileM + warpM * 64 + mf * 16 + g;
        int row1 = row0 + 8;
#pragma unroll
        for (int nf = 0; nf < 4; nf++) {
            int col0 = tileN + warpN * 32 + nf * 8 + tig * 2;
            int col1 = col0 + 1;
            float b0 = (col0 < N) ? Bias[col0] : 0.f;
            float b1 = (col1 < N) ? Bias[col1] : 0.f;
            float v00 = acc[mf][nf][0] + b0;
            float v01 = acc[mf][nf][1] + b1;
            float v10 = acc[mf][nf][2] + b0;
            float v11 = acc[mf][nf][3] + b1;
            if (RELU) {
                v00 = fmaxf(v00, 0.f); v01 = fmaxf(v01, 0.f);
                v10 = fmaxf(v10, 0.f); v11 = fmaxf(v11, 0.f);
            }
            if (STAGE == 5) {
                if (row0 < M) {
                    if (col0 < N) Cf[(size_t)row0 * N + col0] = v00;
                    if (col1 < N) Cf[(size_t)row0 * N + col1] = v01;
                }
                if (row1 < M) {
                    if (col0 < N) Cf[(size_t)row1 * N + col0] = v10;
                    if (col1 < N) Cf[(size_t)row1 * N + col1] = v11;
                }
            } else {
                if (row0 < M) {
                    if (col0 < N) Ch[(size_t)row0 * N + col0] = __float2half(v00);
                    if (col1 < N) Ch[(size_t)row0 * N + col1] = __float2half(v01);
                }
                if (row1 < M) {
                    if (col0 < N) Ch[(size_t)row1 * N + col0] = __float2half(v10);
                    if (col1 < N) Ch[(size_t)row1 * N + col1] = __float2half(v11);
                }
            }
        }
    }
}

// ---------------------------------------------------------------------------
// keys normalization / routing / grouping / combine (R15-verbatim)
// ---------------------------------------------------------------------------
__global__ void keysn_kernel(const float* __restrict__ keys)
{
    int e    = threadIdx.x >> 5;
    int lane = threadIdx.x & 31;
    if (e >= EDIM) return;
    float4 v = *(const float4*)(keys + e * KDIM + lane * 4);
    float ss = v.x * v.x + v.y * v.y + v.z * v.z + v.w * v.w;
#pragma unroll
    for (int o = 16; o; o >>= 1) ss += __shfl_xor_sync(0xffffffffu, ss, o);
    float inv = 1.f / fmaxf(sqrtf(ss), 1e-12f);
    float4 o4 = make_float4(v.x * inv, v.y * inv, v.z * inv, v.w * inv);
    *(float4*)(g_keysn + e * KDIM + lane * 4) = o4;
}

__global__ void zero_counts_kernel()
{
    if (threadIdx.x < EDIM) g_counts[threadIdx.x] = 0;
}

__global__ void router_kernel()
{
    int warp = threadIdx.x >> 5;
    int lane = threadIdx.x & 31;
    int t = blockIdx.x * 8 + warp;
    if (t >= BDIM) return;

    float4 v1 = *(const float4*)(g_pk  + (size_t)t * KDIM + lane * 4);
    float4 v2 = *(const float4*)(g_pk2 + (size_t)t * KDIM + lane * 4);
    float4 v  = make_float4(v1.x + v2.x, v1.y + v2.y, v1.z + v2.z, v1.w + v2.w);
    float ss = v.x * v.x + v.y * v.y + v.z * v.z + v.w * v.w;
#pragma unroll
    for (int o = 16; o; o >>= 1) ss += __shfl_xor_sync(0xffffffffu, ss, o);
    float inv = 1.f / fmaxf(sqrtf(ss), 1e-12f);

    float sims[EDIM];
#pragma unroll
    for (int e = 0; e < EDIM; e++) {
        float4 kv = *(const float4*)(g_keysn + e * KDIM + lane * 4);
        float d = v.x * kv.x + v.y * kv.y + v.z * kv.z + v.w * kv.w;
#pragma unroll
        for (int o = 16; o; o >>= 1) d += __shfl_xor_sync(0xffffffffu, d, o);
        sims[e] = d * inv;
    }

    if (lane == 0) {
        int i0 = 0; float v0 = sims[0];
#pragma unroll
        for (int e = 1; e < EDIM; e++) if (sims[e] > v0) { v0 = sims[e]; i0 = e; }
        int i1 = -1; float v1s = -1e30f;
#pragma unroll
        for (int e = 0; e < EDIM; e++) if (e != i0 && sims[e] > v1s) { v1s = sims[e]; i1 = e; }

        float e1 = expf(v1s - v0);
        float s  = 1.f + e1;
        float w0 = 1.f / s;
        float w1 = e1 / s;

#pragma unroll
        for (int e = 0; e < EDIM; e++) {
            g_sim[t * EDIM + e] = sims[e];
            g_weights[t * EDIM + e] = (e == i0) ? w0 : ((e == i1) ? w1 : 0.f);
        }
        g_topi[t * TOPK + 0] = i0;
        g_topi[t * TOPK + 1] = i1;
        g_wslot[t * TOPK + 0] = w0;
        g_wslot[t * TOPK + 1] = w1;
        atomicAdd(&g_counts[i0], 1);
        atomicAdd(&g_counts[i1], 1);
    }
}

__global__ void scan_kernel()
{
    if (threadIdx.x == 0) {
        int off = 0;
        for (int e = 0; e < EDIM; e++) {
            g_offsets[e] = off;
            g_cursor[e]  = off;
            off += g_counts[e];
        }
        g_offsets[EDIM] = off;
    }
}

__global__ void scatter_kernel()
{
    int t = blockIdx.x * blockDim.x + threadIdx.x;
    if (t >= BDIM) return;
#pragma unroll
    for (int s = 0; s < TOPK; s++) {
        int e = g_topi[t * TOPK + s];
        int pos = atomicAdd(&g_cursor[e], 1);
        g_list[pos] = t;
        g_pos[t * TOPK + s] = pos;
    }
}

__global__ void combine_kernel(float* __restrict__ out)
{
    int t = blockIdx.x;
    float w0 = g_wslot[t * TOPK + 0];
    float w1 = g_wslot[t * TOPK + 1];
    size_t p0 = (size_t)g_pos[t * TOPK + 0];
    size_t p1 = (size_t)g_pos[t * TOPK + 1];
    for (int c = threadIdx.x; c < CDIM; c += blockDim.x)
        out[(size_t)t * CDIM + c] =
            w0 * g_eout[p0 * CDIM + c] + w1 * g_eout[p1 * CDIM + c];
}

__global__ void tail_writer_kernel(float* __restrict__ out, long long out_size)
{
    long long i = (long long)blockIdx.x * blockDim.x + threadIdx.x;
    const long long base_w = (long long)BDIM * CDIM;
    const long long n_w = BDIM * EDIM;
    const long long base_t = base_w + n_w;
    const long long n_t = BDIM * TOPK;
    const long long base_s = base_t + n_t;
    const long long n_s = BDIM * EDIM;
    if (i < n_w && base_w + i < out_size) out[base_w + i] = g_weights[i];
    if (i < n_t && base_t + i < out_size) out[base_t + i] = (float)g_topi[i];
    if (i < n_s && base_s + i < out_size) out[base_s + i] = g_sim[i];
}

// ---------------------------------------------------------------------------
// Launch
// ---------------------------------------------------------------------------
#define SG2_SMEM ((4 * 128 * 40 + 4 * 64 * 40) * (int)sizeof(__half))  // 61440 B
#define ST2_SMEM (4 * 2 * 128 * 40 * (int)sizeof(__half))              // 81920 B
#define HG_SMEM  (2 * 2 * 128 * 72 * (int)sizeof(__half))              // 73728 B

extern "C" void kernel_launch(void* const* d_in, const int* in_sizes, int n_in,
                              void* d_out, int out_size)
{
    const float* x    = (const float*)d_in[0];
    const float* fw1  = (const float*)d_in[1];
    const float* fb1  = (const float*)d_in[2];
    const float* fw2  = (const float*)d_in[3];
    const float* fb2  = (const float*)d_in[4];
    const float* kw   = (const float*)d_in[5];
    const float* kb   = (const float*)d_in[6];
    const float* keys = (const float*)d_in[7];
    const float* ew1  = (const float*)d_in[8];
    const float* eb1  = (const float*)d_in[9];
    const float* ew2  = (const float*)d_in[10];
    const float* eb2  = (const float*)d_in[11];
    const float* ew3  = (const float*)d_in[12];
    const float* eb3  = (const float*)d_in[13];
    float* out = (float*)d_out;

    cudaFuncSetAttribute(sgemm_k<0, true >, cudaFuncAttributeMaxDynamicSharedMemorySize, SG2_SMEM);
    cudaFuncSetAttribute(sgemm_k<7, false>, cudaFuncAttributeMaxDynamicSharedMemorySize, SG2_SMEM);
    cudaFuncSetAttribute(stage2s_k,         cudaFuncAttributeMaxDynamicSharedMemorySize, ST2_SMEM);
    cudaFuncSetAttribute(hgemm_k<1, false>, cudaFuncAttributeMaxDynamicSharedMemorySize, HG_SMEM);
    cudaFuncSetAttribute(hgemm_k<3, true >, cudaFuncAttributeMaxDynamicSharedMemorySize, HG_SMEM);
    cudaFuncSetAttribute(hgemm_k<4, true >, cudaFuncAttributeMaxDynamicSharedMemorySize, HG_SMEM);
    cudaFuncSetAttribute(hgemm_k<5, false>, cudaFuncAttributeMaxDynamicSharedMemorySize, HG_SMEM);

    dim3 blk(256);
    dim3 tblk(32, 8);

    __half *xhi, *xlo, *fw1hi, *fw1lo, *fw2h, *fw2nhi, *fw2nlo, *kwhi, *kwlo;
    __half *ew1h, *ew2h, *ew3h;
    float  *zbias;
    cudaGetSymbolAddress((void**)&xhi,    g_xhi);
    cudaGetSymbolAddress((void**)&xlo,    g_xlo);
    cudaGetSymbolAddress((void**)&fw1hi,  g_fw1hi);
    cudaGetSymbolAddress((void**)&fw1lo,  g_fw1lo);
    cudaGetSymbolAddress((void**)&fw2h,   g_fw2h);
    cudaGetSymbolAddress((void**)&fw2nhi, g_fw2nhi);
    cudaGetSymbolAddress((void**)&fw2nlo, g_fw2nlo);
    cudaGetSymbolAddress((void**)&kwhi,   g_kwhi);
    cudaGetSymbolAddress((void**)&kwlo,   g_kwlo);
    cudaGetSymbolAddress((void**)&ew1h,   g_ew1h);
    cudaGetSymbolAddress((void**)&ew2h,   g_ew2h);
    cudaGetSymbolAddress((void**)&ew3h,   g_ew3h);
    cudaGetSymbolAddress((void**)&zbias,  g_zbias);

    // one-time conversions (R15-verbatim)
    natsplit_k<<<BDIM * DDIM / 4 / 256, 256>>>(x, xhi, xlo);
    natsplit_k<<<HDIM * HDIM / 4 / 256, 256>>>(fw2, fw2nhi, fw2nlo);
    wsplit_k<<<dim3(HDIM / 32, DDIM / 32), tblk>>>(fw1, fw1hi, fw1lo, DDIM, HDIM);
    wsplit_k<<<dim3(KDIM / 32, HDIM / 32), tblk>>>(kw,  kwhi,  kwlo,  HDIM, KDIM);
    wconv_k<<<dim3(HDIM / 32,        HDIM / 32,  1   ), tblk>>>(fw2, fw2h, HDIM,  HDIM);
    wconv_k<<<dim3(HDIM / 32,        HDIM / 32,  EDIM), tblk>>>(ew1, ew1h, HDIM,  HDIM);
    wconv_k<<<dim3(H2DIM / 32,       HDIM / 32,  EDIM), tblk>>>(ew2, ew2h, HDIM,  H2DIM);
    wconv_k<<<dim3((CDIM + 31) / 32, H2DIM / 32, EDIM), tblk>>>(ew3, ew3h, H2DIM, CDIM);
    bprime_k<<<KDIM, 256>>>(fb2, kw, kb);

    // W'^T = kw^T @ fw2 (fp32-grade split output)
    sgemm_k<7, false><<<dim3(HDIM / 64, 1), blk, SG2_SMEM>>>(fw2nhi, fw2nlo, zbias, HDIM, HDIM);

    keysn_kernel<<<1, 256>>>(keys);
    zero_counts_kernel<<<1, 32>>>();

    // stage0: x @ fw1 -> h split (fp32-grade, relu), 128x64 tiles, 2 CTAs/SM
    sgemm_k<0, true ><<<dim3(HDIM / 64, BDIM / 128), blk, SG2_SMEM>>>(fw1hi, fw1lo, fb1, HDIM, DDIM);

    // stage1: h @ fw2 -> feats (fp16, 2 CTAs/SM)
    hgemm_k<1, false><<<dim3(HDIM / 128, BDIM / 128, 1), blk, HG_SMEM>>>(fw2h, fb2, HDIM, HDIM);

    // stage2: h @ W' -> pk, K split over 2 grid planes (128 CTAs)
    stage2s_k<<<dim3(1, BDIM / 128, 2), blk, ST2_SMEM>>>();

    router_kernel<<<BDIM / 8, 256>>>();
    scan_kernel<<<1, 32>>>();
    scatter_kernel<<<(BDIM + 255) / 256, 256>>>();

    // expert MLPs: fp16 HMMA, 2 CTAs/SM
    hgemm_k<3, true ><<<dim3(HDIM / 128,         BDIM / 128, EDIM), blk, HG_SMEM>>>(ew1h, eb1, HDIM,  HDIM);
    hgemm_k<4, true ><<<dim3(H2DIM / 128,        BDIM / 128, EDIM), blk, HG_SMEM>>>(ew2h, eb2, H2DIM, HDIM);
    hgemm_k<5, false><<<dim3((CDIM + 127) / 128, BDIM / 128, EDIM), blk, HG_SMEM>>>(ew3h, eb3, CDIM,  H2DIM);

    combine_kernel<<<BDIM, 256>>>(out);
    tail_writer_kernel<<<(BDIM * EDIM + 255) / 256, 256>>>(out, (long long)out_size);
}

// round 17
// speedup vs baseline: 1.2804x; 1.0177x over previous
#include <cuda_runtime.h>
#include <cuda_fp16.h>
#include <math.h>
#include <stdint.h>

// ---------------------------------------------------------------------------
// Problem constants
// ---------------------------------------------------------------------------
#define BDIM   8192
#define DDIM   1024
#define HDIM   2048
#define H2DIM  1024
#define CDIM   1000
#define KDIM   128
#define EDIM   8
#define TOPK   2
#define MAXROWS (BDIM * TOPK)

// ---------------------------------------------------------------------------
// Scratch (device globals — no allocation allowed)
// ---------------------------------------------------------------------------
__device__ __half g_xhi  [(size_t)BDIM * DDIM];
__device__ __half g_xlo  [(size_t)BDIM * DDIM];
__device__ __half g_hhi  [(size_t)BDIM * HDIM];
__device__ __half g_hlo  [(size_t)BDIM * HDIM];
__device__ __half g_featshi[(size_t)BDIM * HDIM];
__device__ float  g_pk   [(size_t)BDIM * KDIM];
__device__ float  g_pk2  [(size_t)BDIM * KDIM];
__device__ float  g_keysn[EDIM * KDIM];
__device__ float  g_sim  [BDIM * EDIM];
__device__ float  g_weights[BDIM * EDIM];
__device__ float  g_wslot[BDIM * TOPK];
__device__ int    g_topi [BDIM * TOPK];
__device__ int    g_counts[EDIM];
__device__ int    g_offsets[EDIM + 1];
__device__ int    g_cursor[EDIM];
__device__ int    g_list [MAXROWS];
__device__ int    g_pos  [BDIM * TOPK];
__device__ __half g_h1h  [(size_t)MAXROWS * HDIM];
__device__ __half g_h2h  [(size_t)MAXROWS * H2DIM];
__device__ float  g_eout [(size_t)MAXROWS * CDIM];
// converted weights
__device__ __half g_fw1hi[(size_t)HDIM * DDIM];   // fw1^T split  [H][D]
__device__ __half g_fw1lo[(size_t)HDIM * DDIM];
__device__ __half g_fw2h [(size_t)HDIM * HDIM];   // fw2^T single [Hout][Hin]
__device__ __half g_fw2nhi[(size_t)HDIM * HDIM];  // fw2 natural split [Hin][Hout]
__device__ __half g_fw2nlo[(size_t)HDIM * HDIM];
__device__ __half g_kwhi [(size_t)KDIM * HDIM];   // kw^T split   [K][H]
__device__ __half g_kwlo [(size_t)KDIM * HDIM];
__device__ __half g_wphi [(size_t)KDIM * HDIM];   // W'^T split   [K][H]
__device__ __half g_wplo [(size_t)KDIM * HDIM];
__device__ float  g_bp   [KDIM];                  // b' = fb2@kw + kb
__device__ float  g_zbias[HDIM];                  // zeros (static init)
__device__ __half g_ew1h [(size_t)EDIM * HDIM  * HDIM];
__device__ __half g_ew2h [(size_t)EDIM * H2DIM * HDIM];
__device__ __half g_ew3h [(size_t)EDIM * CDIM  * H2DIM];

#define LO_SCALE 4096.0f
#define LO_INV   (1.0f / 4096.0f)

// ---------------------------------------------------------------------------
// helpers
// ---------------------------------------------------------------------------
__device__ __forceinline__ void mma_f16(float c[4],
                                        const uint32_t a[4],
                                        const uint32_t b[2]) {
    asm volatile(
        "mma.sync.aligned.m16n8k16.row.col.f32.f16.f16.f32 "
        "{%0,%1,%2,%3}, {%4,%5,%6,%7}, {%8,%9}, {%0,%1,%2,%3};"
        : "+f"(c[0]), "+f"(c[1]), "+f"(c[2]), "+f"(c[3])
        : "r"(a[0]), "r"(a[1]), "r"(a[2]), "r"(a[3]),
          "r"(b[0]), "r"(b[1]));
}
__device__ __forceinline__ void cp16(void* dst, const void* src, bool valid) {
    uint32_t d = (uint32_t)__cvta_generic_to_shared(dst);
    int sz = valid ? 16 : 0;
    asm volatile("cp.async.cg.shared.global [%0], [%1], 16, %2;"
                 :: "r"(d), "l"(src), "r"(sz));
}
__device__ __forceinline__ void split_f32(float v, __half& hi, __half& lo) {
    hi = __float2half(v);
    lo = __float2half((v - __half2float(hi)) * LO_SCALE);
}

// ---------------------------------------------------------------------------
// One-time conversions (R16-verbatim)
// ---------------------------------------------------------------------------
__global__ void natsplit_k(const float* __restrict__ W,
                           __half* __restrict__ Whi, __half* __restrict__ Wlo)
{
    size_t i = ((size_t)blockIdx.x * 256 + threadIdx.x) * 4;
    float4 v = *(const float4*)(W + i);
    __half h0, l0, h1, l1, h2, l2, h3, l3;
    split_f32(v.x, h0, l0); split_f32(v.y, h1, l1);
    split_f32(v.z, h2, l2); split_f32(v.w, h3, l3);
    *(__half2*)&Whi[i]     = __halves2half2(h0, h1);
    *(__half2*)&Whi[i + 2] = __halves2half2(h2, h3);
    *(__half2*)&Wlo[i]     = __halves2half2(l0, l1);
    *(__half2*)&Wlo[i + 2] = __halves2half2(l2, l3);
}

__global__ void wsplit_k(const float* __restrict__ W,
                         __half* __restrict__ Whi, __half* __restrict__ Wlo,
                         int K, int N)
{
    __shared__ float t[32][33];
    int k0 = blockIdx.y * 32;
    int n0 = blockIdx.x * 32;
#pragma unroll
    for (int j = 0; j < 4; j++)
        t[threadIdx.y + j * 8][threadIdx.x] =
            W[(size_t)(k0 + threadIdx.y + j * 8) * N + n0 + threadIdx.x];
    __syncthreads();
#pragma unroll
    for (int j = 0; j < 4; j++) {
        int n = n0 + threadIdx.y + j * 8;
        int k = k0 + threadIdx.x;
        float val = t[threadIdx.x][threadIdx.y + j * 8];
        __half hi, lo;
        split_f32(val, hi, lo);
        Whi[(size_t)n * K + k] = hi;
        Wlo[(size_t)n * K + k] = lo;
    }
}

__global__ void wconv_k(const float* __restrict__ Wg, __half* __restrict__ Wtg,
                        int K, int N)
{
    const float* W  = Wg  + (size_t)blockIdx.z * K * N;
    __half*      Wt = Wtg + (size_t)blockIdx.z * N * K;
    __shared__ float t[32][33];
    int k0 = blockIdx.y * 32;
    int n0 = blockIdx.x * 32;
#pragma unroll
    for (int j = 0; j < 4; j++) {
        int n = n0 + threadIdx.x;
        if (n < N) t[threadIdx.y + j * 8][threadIdx.x] =
            W[(size_t)(k0 + threadIdx.y + j * 8) * N + n];
    }
    __syncthreads();
#pragma unroll
    for (int j = 0; j < 4; j++) {
        int n = n0 + threadIdx.y + j * 8;
        int k = k0 + threadIdx.x;
        if (n < N) Wt[(size_t)n * K + k] =
            __float2half(t[threadIdx.x][threadIdx.y + j * 8]);
    }
}

__global__ void bprime_k(const float* __restrict__ fb2,
                         const float* __restrict__ kw,
                         const float* __restrict__ kb)
{
    int j = blockIdx.x;
    float s = 0.f;
    for (int m = threadIdx.x; m < HDIM; m += 256)
        s += fb2[m] * kw[(size_t)m * KDIM + j];
    __shared__ float red[8];
#pragma unroll
    for (int o = 16; o; o >>= 1) s += __shfl_xor_sync(0xffffffffu, s, o);
    if ((threadIdx.x & 31) == 0) red[threadIdx.x >> 5] = s;
    __syncthreads();
    if (threadIdx.x == 0) {
        float t = 0.f;
#pragma unroll
        for (int w = 0; w < 8; w++) t += red[w];
        g_bp[j] = t + kb[j];
    }
}

// ---------------------------------------------------------------------------
// fp16 2-term-split GEMM, 128x64 CTA tile, 2 CTAs/SM (R16-verbatim; STAGE 0,7)
// ---------------------------------------------------------------------------
#define SBK 32

template<int STAGE, bool RELU>
__global__ __launch_bounds__(256, 2) void sgemm_k(const __half* __restrict__ Whi,
                                                  const __half* __restrict__ Wlo,
                                                  const float* __restrict__ Bias,
                                                  int N, int Kd)
{
    extern __shared__ __half sms[];
    __half (*Ahi_s)[128][40] = (__half(*)[128][40])sms;
    __half (*Alo_s)[128][40] = (__half(*)[128][40])(sms + 2 * 128 * 40);
    __half (*Bhi_s)[64][40]  = (__half(*)[64][40]) (sms + 4 * 128 * 40);
    __half (*Blo_s)[64][40]  = (__half(*)[64][40]) (sms + 4 * 128 * 40 + 2 * 64 * 40);

    const __half *Ahi, *Alo;
    if (STAGE == 0)      { Ahi = g_xhi;  Alo = g_xlo;  }
    else                 { Ahi = g_kwhi; Alo = g_kwlo; }

    const int tileM = blockIdx.y * 128;
    const int tileN = blockIdx.x * 64;

    const int tid  = threadIdx.x;
    const int lane = tid & 31;
    const int wid  = tid >> 5;
    const int g    = lane >> 2;
    const int tig  = lane & 3;
    const int warpM = wid & 1;
    const int warpN = wid >> 1;

    const int rr = tid >> 2;
    const int cc = (tid & 3) * 8;

    const size_t aoff = (size_t)(tileM + rr) * Kd + cc;
    const size_t boff = (size_t)(tileN + rr) * Kd + cc;
    const size_t rstep = (size_t)64 * Kd;

    float acc [4][2][4];
    float accx[4][2][4];
#pragma unroll
    for (int i = 0; i < 4; i++)
#pragma unroll
        for (int j = 0; j < 2; j++)
#pragma unroll
            for (int r = 0; r < 4; r++) { acc[i][j][r] = 0.f; accx[i][j][r] = 0.f; }

    const int KT = Kd / SBK;

    auto load_tile = [&](int k0, int buf) {
#pragma unroll
        for (int it = 0; it < 2; it++) {
            cp16(&Ahi_s[buf][rr + it * 64][cc], Ahi + aoff + it * rstep + k0, true);
            cp16(&Alo_s[buf][rr + it * 64][cc], Alo + aoff + it * rstep + k0, true);
        }
        cp16(&Bhi_s[buf][rr][cc], Whi + boff + k0, true);
        cp16(&Blo_s[buf][rr][cc], Wlo + boff + k0, true);
        asm volatile("cp.async.commit_group;");
    };

    load_tile(0, 0);

    for (int kt = 0; kt < KT; kt++) {
        const int buf = kt & 1;
        if (kt + 1 < KT) {
            load_tile((kt + 1) * SBK, (kt + 1) & 1);
            asm volatile("cp.async.wait_group 1;");
        } else {
            asm volatile("cp.async.wait_group 0;");
        }
        __syncthreads();

#pragma unroll
        for (int ks = 0; ks < 2; ks++) {
            const int k16 = ks * 16;
            uint32_t bh[2][2], bl[2][2];
#pragma unroll
            for (int nf = 0; nf < 2; nf++) {
                int n = warpN * 16 + nf * 8 + g;
                bh[nf][0] = *(const uint32_t*)&Bhi_s[buf][n][k16 + 2 * tig    ];
                bh[nf][1] = *(const uint32_t*)&Bhi_s[buf][n][k16 + 2 * tig + 8];
                bl[nf][0] = *(const uint32_t*)&Blo_s[buf][n][k16 + 2 * tig    ];
                bl[nf][1] = *(const uint32_t*)&Blo_s[buf][n][k16 + 2 * tig + 8];
            }
#pragma unroll
            for (int mf = 0; mf < 4; mf++) {
                int m = warpM * 64 + mf * 16 + g;
                uint32_t ah[4], al[4];
                ah[0] = *(const uint32_t*)&Ahi_s[buf][m    ][k16 + 2 * tig    ];
                ah[1] = *(const uint32_t*)&Ahi_s[buf][m + 8][k16 + 2 * tig    ];
                ah[2] = *(const uint32_t*)&Ahi_s[buf][m    ][k16 + 2 * tig + 8];
                ah[3] = *(const uint32_t*)&Ahi_s[buf][m + 8][k16 + 2 * tig + 8];
                al[0] = *(const uint32_t*)&Alo_s[buf][m    ][k16 + 2 * tig    ];
                al[1] = *(const uint32_t*)&Alo_s[buf][m + 8][k16 + 2 * tig    ];
                al[2] = *(const uint32_t*)&Alo_s[buf][m    ][k16 + 2 * tig + 8];
                al[3] = *(const uint32_t*)&Alo_s[buf][m + 8][k16 + 2 * tig + 8];
#pragma unroll
                for (int nf = 0; nf < 2; nf++) {
                    mma_f16(acc [mf][nf], ah, bh[nf]);
                    mma_f16(accx[mf][nf], ah, bl[nf]);
                    mma_f16(accx[mf][nf], al, bh[nf]);
                }
            }
        }
        __syncthreads();
    }

#pragma unroll
    for (int mf = 0; mf < 4; mf++) {
        int row0 = tileM + warpM * 64 + mf * 16 + g;
        int row1 = row0 + 8;
#pragma unroll
        for (int nf = 0; nf < 2; nf++) {
            int col0 = tileN + warpN * 16 + nf * 8 + tig * 2;
            int col1 = col0 + 1;
            float b0 = Bias[col0];
            float b1 = Bias[col1];
            float v00 = acc[mf][nf][0] + accx[mf][nf][0] * LO_INV + b0;
            float v01 = acc[mf][nf][1] + accx[mf][nf][1] * LO_INV + b1;
            float v10 = acc[mf][nf][2] + accx[mf][nf][2] * LO_INV + b0;
            float v11 = acc[mf][nf][3] + accx[mf][nf][3] * LO_INV + b1;
            if (RELU) {
                v00 = fmaxf(v00, 0.f); v01 = fmaxf(v01, 0.f);
                v10 = fmaxf(v10, 0.f); v11 = fmaxf(v11, 0.f);
            }
            __half* Hi = (STAGE == 0) ? g_hhi : g_wphi;
            __half* Lo = (STAGE == 0) ? g_hlo : g_wplo;
            __half h, l;
            split_f32(v00, h, l);
            Hi[(size_t)row0 * N + col0] = h; Lo[(size_t)row0 * N + col0] = l;
            split_f32(v01, h, l);
            Hi[(size_t)row0 * N + col1] = h; Lo[(size_t)row0 * N + col1] = l;
            split_f32(v10, h, l);
            Hi[(size_t)row1 * N + col0] = h; Lo[(size_t)row1 * N + col0] = l;
            split_f32(v11, h, l);
            Hi[(size_t)row1 * N + col1] = h; Lo[(size_t)row1 * N + col1] = l;
        }
    }
}

// ---------------------------------------------------------------------------
// stage2 split-GEMM with K split across blockIdx.z (R16-verbatim)
// ---------------------------------------------------------------------------
__global__ __launch_bounds__(256) void stage2s_k()
{
    extern __shared__ __half smf[];
    __half (*S)[2][128][40] = (__half(*)[2][128][40])smf;

    const int tid  = threadIdx.x;
    const int lane = tid & 31;
    const int wid  = tid >> 5;
    const int g    = lane >> 2;
    const int tig  = lane & 3;
    const int warpM = wid & 1;
    const int warpN = wid >> 1;

    const int N  = KDIM;
    const int Kd = HDIM;
    const int kbase = blockIdx.z * (HDIM / 2);
    const int tileM = blockIdx.y * 128;

    const int rr = tid >> 2;
    const int cc = (tid & 3) * 8;
    const size_t aoff = (size_t)(tileM + rr) * Kd + kbase + cc;
    const size_t boff = (size_t)rr * Kd + kbase + cc;
    const size_t rstep = (size_t)64 * Kd;

    float acc [4][4][4];
    float accx[4][4][4];
#pragma unroll
    for (int i = 0; i < 4; i++)
#pragma unroll
        for (int j = 0; j < 4; j++)
#pragma unroll
            for (int r = 0; r < 4; r++) { acc[i][j][r] = 0.f; accx[i][j][r] = 0.f; }

    const int KT = (HDIM / 2) / SBK;

    auto load_tile = [&](int k0, int buf) {
#pragma unroll
        for (int it = 0; it < 2; it++) {
            cp16(&S[0][buf][rr + it * 64][cc], g_hhi  + aoff + it * rstep + k0, true);
            cp16(&S[1][buf][rr + it * 64][cc], g_hlo  + aoff + it * rstep + k0, true);
            cp16(&S[2][buf][rr + it * 64][cc], g_wphi + boff + it * rstep + k0, true);
            cp16(&S[3][buf][rr + it * 64][cc], g_wplo + boff + it * rstep + k0, true);
        }
        asm volatile("cp.async.commit_group;");
    };

    load_tile(0, 0);

    for (int kt = 0; kt < KT; kt++) {
        const int buf = kt & 1;
        if (kt + 1 < KT) {
            load_tile((kt + 1) * SBK, (kt + 1) & 1);
            asm volatile("cp.async.wait_group 1;");
        } else {
            asm volatile("cp.async.wait_group 0;");
        }
        __syncthreads();

#pragma unroll
        for (int ks = 0; ks < 2; ks++) {
            const int k16 = ks * 16;
            uint32_t bh[4][2], bl[4][2];
#pragma unroll
            for (int nf = 0; nf < 4; nf++) {
                int n = warpN * 32 + nf * 8 + g;
                bh[nf][0] = *(const uint32_t*)&S[2][buf][n][k16 + 2 * tig    ];
                bh[nf][1] = *(const uint32_t*)&S[2][buf][n][k16 + 2 * tig + 8];
                bl[nf][0] = *(const uint32_t*)&S[3][buf][n][k16 + 2 * tig    ];
                bl[nf][1] = *(const uint32_t*)&S[3][buf][n][k16 + 2 * tig + 8];
            }
#pragma unroll
            for (int mf = 0; mf < 4; mf++) {
                int m = warpM * 64 + mf * 16 + g;
                uint32_t ah[4], al[4];
                ah[0] = *(const uint32_t*)&S[0][buf][m    ][k16 + 2 * tig    ];
                ah[1] = *(const uint32_t*)&S[0][buf][m + 8][k16 + 2 * tig    ];
                ah[2] = *(const uint32_t*)&S[0][buf][m    ][k16 + 2 * tig + 8];
                ah[3] = *(const uint32_t*)&S[0][buf][m + 8][k16 + 2 * tig + 8];
                al[0] = *(const uint32_t*)&S[1][buf][m    ][k16 + 2 * tig    ];
                al[1] = *(const uint32_t*)&S[1][buf][m + 8][k16 + 2 * tig    ];
                al[2] = *(const uint32_t*)&S[1][buf][m    ][k16 + 2 * tig + 8];
                al[3] = *(const uint32_t*)&S[1][buf][m + 8][k16 + 2 * tig + 8];
#pragma unroll
                for (int nf = 0; nf < 4; nf++) {
                    mma_f16(acc [mf][nf], ah, bh[nf]);
                    mma_f16(accx[mf][nf], ah, bl[nf]);
                    mma_f16(accx[mf][nf], al, bh[nf]);
                }
            }
        }
        __syncthreads();
    }

    float* outp = (blockIdx.z == 0) ? g_pk : g_pk2;
    const bool addb = (blockIdx.z == 0);
#pragma unroll
    for (int mf = 0; mf < 4; mf++) {
        int row0 = tileM + warpM * 64 + mf * 16 + g;
        int row1 = row0 + 8;
#pragma unroll
        for (int nf = 0; nf < 4; nf++) {
            int col0 = warpN * 32 + nf * 8 + tig * 2;
            int col1 = col0 + 1;
            float b0 = addb ? g_bp[col0] : 0.f;
            float b1 = addb ? g_bp[col1] : 0.f;
            outp[(size_t)row0 * N + col0] = acc[mf][nf][0] + accx[mf][nf][0] * LO_INV + b0;
            outp[(size_t)row0 * N + col1] = acc[mf][nf][1] + accx[mf][nf][1] * LO_INV + b1;
            outp[(size_t)row1 * N + col0] = acc[mf][nf][2] + accx[mf][nf][2] * LO_INV + b0;
            outp[(size_t)row1 * N + col1] = acc[mf][nf][3] + accx[mf][nf][3] * LO_INV + b1;
        }
    }
}

// ---------------------------------------------------------------------------
// Pure fp16 GEMM, 2 CTAs/SM (R16-verbatim)
// ---------------------------------------------------------------------------
#define HBK 64

template<int STAGE, bool RELU>
__global__ __launch_bounds__(256, 2) void hgemm_k(const __half* __restrict__ Wt,
                                                  const float* __restrict__ Biasg,
                                                  int N, int Kd)
{
    extern __shared__ __half smh[];
    __half (*Ah)[128][72] = (__half(*)[128][72])smh;
    __half (*Bh)[128][72] = (__half(*)[128][72])(smh + 2 * 128 * 72);

    int M;
    const __half* B;
    const float* Bias;
    const __half* A;
    __half* Ch = nullptr;
    float*  Cf = nullptr;
    const int* gather = nullptr;

    if (STAGE == 1) {
        M = BDIM; B = Wt; Bias = Biasg;
        A = g_hhi; Ch = g_featshi;
    } else {
        int e  = blockIdx.z;
        int m0 = g_offsets[e];
        M = g_offsets[e + 1] - m0;
        B    = Wt    + (size_t)e * N * Kd;
        Bias = Biasg + (size_t)e * N;
        if (STAGE == 3)      { A = g_featshi; gather = g_list + m0; Ch = g_h1h + (size_t)m0 * N; }
        else if (STAGE == 4) { A = g_h1h + (size_t)m0 * Kd;         Ch = g_h2h + (size_t)m0 * N; }
        else                 { A = g_h2h + (size_t)m0 * Kd;         Cf = g_eout + (size_t)m0 * N; }
    }

    const int tileM = blockIdx.y * 128;
    if (tileM >= M) return;
    const int tileN = blockIdx.x * 128;

    const int tid  = threadIdx.x;
    const int lane = tid & 31;
    const int wid  = tid >> 5;
    const int g    = lane >> 2;
    const int tig  = lane & 3;
    const int warpM = wid & 1;
    const int warpN = wid >> 1;

    const __half* aptr[4];
    bool av[4];
#pragma unroll
    for (int it = 0; it < 4; it++) {
        int r = (tid >> 3) + it * 32;
        int grow = tileM + r;
        av[it] = (grow < M);
        size_t arow = 0;
        if (av[it]) arow = (STAGE == 3) ? (size_t)gather[grow] : (size_t)grow;
        aptr[it] = A + arow * Kd + (tid & 7) * 8;
    }
    const __half* bptr[4];
    bool bvv[4];
#pragma unroll
    for (int it = 0; it < 4; it++) {
        int r = (tid >> 3) + it * 32;
        int gn = tileN + r;
        bvv[it] = (gn < N);
        bptr[it] = B + (size_t)(bvv[it] ? gn : 0) * Kd + (tid & 7) * 8;
    }

    float acc[4][4][4];
#pragma unroll
    for (int i = 0; i < 4; i++)
#pragma unroll
        for (int j = 0; j < 4; j++)
#pragma unroll
            for (int r = 0; r < 4; r++) acc[i][j][r] = 0.f;

    const int KT = Kd / HBK;

    auto load_tile = [&](int k0, int buf) {
#pragma unroll
        for (int it = 0; it < 4; it++) {
            int r = (tid >> 3) + it * 32;
            cp16(&Ah[buf][r][(tid & 7) * 8], aptr[it] + k0, av[it]);
        }
#pragma unroll
        for (int it = 0; it < 4; it++) {
            int r = (tid >> 3) + it * 32;
            cp16(&Bh[buf][r][(tid & 7) * 8], bptr[it] + k0, bvv[it]);
        }
        asm volatile("cp.async.commit_group;");
    };

    load_tile(0, 0);

    for (int kt = 0; kt < KT; kt++) {
        const int buf = kt & 1;
        if (kt + 1 < KT) {
            load_tile((kt + 1) * HBK, (kt + 1) & 1);
            asm volatile("cp.async.wait_group 1;");
        } else {
            asm volatile("cp.async.wait_group 0;");
        }
        __syncthreads();

#pragma unroll
        for (int ks = 0; ks < 4; ks++) {
            const int k16 = ks * 16;
            uint32_t bf[4][2];
#pragma unroll
            for (int nf = 0; nf < 4; nf++) {
                int n = warpN * 32 + nf * 8 + g;
                bf[nf][0] = *(const uint32_t*)&Bh[buf][n][k16 + 2 * tig    ];
                bf[nf][1] = *(const uint32_t*)&Bh[buf][n][k16 + 2 * tig + 8];
            }
#pragma unroll
            for (int mf = 0; mf < 4; mf++) {
                int m = warpM * 64 + mf * 16 + g;
                uint32_t af[4];
                af[0] = *(const uint32_t*)&Ah[buf][m    ][k16 + 2 * tig    ];
                af[1] = *(const uint32_t*)&Ah[buf][m + 8][k16 + 2 * tig    ];
                af[2] = *(const uint32_t*)&Ah[buf][m    ][k16 + 2 * tig + 8];
                af[3] = *(const uint32_t*)&Ah[buf][m + 8][k16 + 2 * tig + 8];
#pragma unroll
                for (int nf = 0; nf < 4; nf++)
                    mma_f16(acc[mf][nf], af, bf[nf]);
            }
        }
        __syncthreads();
    }

#pragma unroll
    for (int mf = 0; mf < 4; mf++) {
        int row0 = tileM + warpM * 64 + mf * 16 + g;
        int row1 = row0 + 8;
#pragma unroll
        for (int nf = 0; nf < 4; nf++) {
            int col0 = tileN + warpN * 32 + nf * 8 + tig * 2;
            int col1 = col0 + 1;
            float b0 = (col0 < N) ? Bias[col0] : 0.f;
            float b1 = (col1 < N) ? Bias[col1] : 0.f;
            float v00 = acc[mf][nf][0] + b0;
            float v01 = acc[mf][nf][1] + b1;
            float v10 = acc[mf][nf][2] + b0;
            float v11 = acc[mf][nf][3] + b1;
            if (RELU) {
                v00 = fmaxf(v00, 0.f); v01 = fmaxf(v01, 0.f);
                v10 = fmaxf(v10, 0.f); v11 = fmaxf(v11, 0.f);
            }
            if (STAGE == 5) {
                if (row0 < M) {
                    if (col0 < N) Cf[(size_t)row0 * N + col0] = v00;
                    if (col1 < N) Cf[(size_t)row0 * N + col1] = v01;
                }
                if (row1 < M) {
                    if (col0 < N) Cf[(size_t)row1 * N + col0] = v10;
                    if (col1 < N) Cf[(size_t)row1 * N + col1] = v11;
                }
            } else {
                if (row0 < M) {
                    if (col0 < N) Ch[(size_t)row0 * N + col0] = __float2half(v00);
                    if (col1 < N) Ch[(size_t)row0 * N + col1] = __float2half(v01);
                }
                if (row1 < M) {
                    if (col0 < N) Ch[(size_t)row1 * N + col0] = __float2half(v10);
                    if (col1 < N) Ch[(size_t)row1 * N + col1] = __float2half(v11);
                }
            }
        }
    }
}

// ---------------------------------------------------------------------------
// keys normalization / routing / grouping / combine (R16-verbatim)
// ---------------------------------------------------------------------------
__global__ void keysn_kernel(const float* __restrict__ keys)
{
    int e    = threadIdx.x >> 5;
    int lane = threadIdx.x & 31;
    if (e >= EDIM) return;
    float4 v = *(const float4*)(keys + e * KDIM + lane * 4);
    float ss = v.x * v.x + v.y * v.y + v.z * v.z + v.w * v.w;
#pragma unroll
    for (int o = 16; o; o >>= 1) ss += __shfl_xor_sync(0xffffffffu, ss, o);
    float inv = 1.f / fmaxf(sqrtf(ss), 1e-12f);
    float4 o4 = make_float4(v.x * inv, v.y * inv, v.z * inv, v.w * inv);
    *(float4*)(g_keysn + e * KDIM + lane * 4) = o4;
}

__global__ void zero_counts_kernel()
{
    if (threadIdx.x < EDIM) g_counts[threadIdx.x] = 0;
}

__global__ void router_kernel()
{
    int warp = threadIdx.x >> 5;
    int lane = threadIdx.x & 31;
    int t = blockIdx.x * 8 + warp;
    if (t >= BDIM) return;

    float4 v1 = *(const float4*)(g_pk  + (size_t)t * KDIM + lane * 4);
    float4 v2 = *(const float4*)(g_pk2 + (size_t)t * KDIM + lane * 4);
    float4 v  = make_float4(v1.x + v2.x, v1.y + v2.y, v1.z + v2.z, v1.w + v2.w);
    float ss = v.x * v.x + v.y * v.y + v.z * v.z + v.w * v.w;
#pragma unroll
    for (int o = 16; o; o >>= 1) ss += __shfl_xor_sync(0xffffffffu, ss, o);
    float inv = 1.f / fmaxf(sqrtf(ss), 1e-12f);

    float sims[EDIM];
#pragma unroll
    for (int e = 0; e < EDIM; e++) {
        float4 kv = *(const float4*)(g_keysn + e * KDIM + lane * 4);
        float d = v.x * kv.x + v.y * kv.y + v.z * kv.z + v.w * kv.w;
#pragma unroll
        for (int o = 16; o; o >>= 1) d += __shfl_xor_sync(0xffffffffu, d, o);
        sims[e] = d * inv;
    }

    if (lane == 0) {
        int i0 = 0; float v0 = sims[0];
#pragma unroll
        for (int e = 1; e < EDIM; e++) if (sims[e] > v0) { v0 = sims[e]; i0 = e; }
        int i1 = -1; float v1s = -1e30f;
#pragma unroll
        for (int e = 0; e < EDIM; e++) if (e != i0 && sims[e] > v1s) { v1s = sims[e]; i1 = e; }

        float e1 = expf(v1s - v0);
        float s  = 1.f + e1;
        float w0 = 1.f / s;
        float w1 = e1 / s;

#pragma unroll
        for (int e = 0; e < EDIM; e++) {
            g_sim[t * EDIM + e] = sims[e];
            g_weights[t * EDIM + e] = (e == i0) ? w0 : ((e == i1) ? w1 : 0.f);
        }
        g_topi[t * TOPK + 0] = i0;
        g_topi[t * TOPK + 1] = i1;
        g_wslot[t * TOPK + 0] = w0;
        g_wslot[t * TOPK + 1] = w1;
        atomicAdd(&g_counts[i0], 1);
        atomicAdd(&g_counts[i1], 1);
    }
}

__global__ void scan_kernel()
{
    if (threadIdx.x == 0) {
        int off = 0;
        for (int e = 0; e < EDIM; e++) {
            g_offsets[e] = off;
            g_cursor[e]  = off;
            off += g_counts[e];
        }
        g_offsets[EDIM] = off;
    }
}

__global__ void scatter_kernel()
{
    int t = blockIdx.x * blockDim.x + threadIdx.x;
    if (t >= BDIM) return;
#pragma unroll
    for (int s = 0; s < TOPK; s++) {
        int e = g_topi[t * TOPK + s];
        int pos = atomicAdd(&g_cursor[e], 1);
        g_list[pos] = t;
        g_pos[t * TOPK + s] = pos;
    }
}

__global__ void combine_kernel(float* __restrict__ out)
{
    int t = blockIdx.x;
    float w0 = g_wslot[t * TOPK + 0];
    float w1 = g_wslot[t * TOPK + 1];
    size_t p0 = (size_t)g_pos[t * TOPK + 0];
    size_t p1 = (size_t)g_pos[t * TOPK + 1];
    for (int c = threadIdx.x; c < CDIM; c += blockDim.x)
        out[(size_t)t * CDIM + c] =
            w0 * g_eout[p0 * CDIM + c] + w1 * g_eout[p1 * CDIM + c];
}

__global__ void tail_writer_kernel(float* __restrict__ out, long long out_size)
{
    long long i = (long long)blockIdx.x * blockDim.x + threadIdx.x;
    const long long base_w = (long long)BDIM * CDIM;
    const long long n_w = BDIM * EDIM;
    const long long base_t = base_w + n_w;
    const long long n_t = BDIM * TOPK;
    const long long base_s = base_t + n_t;
    const long long n_s = BDIM * EDIM;
    if (i < n_w && base_w + i < out_size) out[base_w + i] = g_weights[i];
    if (i < n_t && base_t + i < out_size) out[base_t + i] = (float)g_topi[i];
    if (i < n_s && base_s + i < out_size) out[base_s + i] = g_sim[i];
}

// ---------------------------------------------------------------------------
// Launch — NEW vs R16: side stream (captured fork) hides the conversion
// prologue + stage7 + keysn/zero under stage0's compute wave.
// ---------------------------------------------------------------------------
#define SG2_SMEM ((4 * 128 * 40 + 4 * 64 * 40) * (int)sizeof(__half))  // 61440 B
#define ST2_SMEM (4 * 2 * 128 * 40 * (int)sizeof(__half))              // 81920 B
#define HG_SMEM  (2 * 2 * 128 * 72 * (int)sizeof(__half))              // 73728 B

extern "C" void kernel_launch(void* const* d_in, const int* in_sizes, int n_in,
                              void* d_out, int out_size)
{
    const float* x    = (const float*)d_in[0];
    const float* fw1  = (const float*)d_in[1];
    const float* fb1  = (const float*)d_in[2];
    const float* fw2  = (const float*)d_in[3];
    const float* fb2  = (const float*)d_in[4];
    const float* kw   = (const float*)d_in[5];
    const float* kb   = (const float*)d_in[6];
    const float* keys = (const float*)d_in[7];
    const float* ew1  = (const float*)d_in[8];
    const float* eb1  = (const float*)d_in[9];
    const float* ew2  = (const float*)d_in[10];
    const float* eb2  = (const float*)d_in[11];
    const float* ew3  = (const float*)d_in[12];
    const float* eb3  = (const float*)d_in[13];
    float* out = (float*)d_out;

    cudaFuncSetAttribute(sgemm_k<0, true >, cudaFuncAttributeMaxDynamicSharedMemorySize, SG2_SMEM);
    cudaFuncSetAttribute(sgemm_k<7, false>, cudaFuncAttributeMaxDynamicSharedMemorySize, SG2_SMEM);
    cudaFuncSetAttribute(stage2s_k,         cudaFuncAttributeMaxDynamicSharedMemorySize, ST2_SMEM);
    cudaFuncSetAttribute(hgemm_k<1, false>, cudaFuncAttributeMaxDynamicSharedMemorySize, HG_SMEM);
    cudaFuncSetAttribute(hgemm_k<3, true >, cudaFuncAttributeMaxDynamicSharedMemorySize, HG_SMEM);
    cudaFuncSetAttribute(hgemm_k<4, true >, cudaFuncAttributeMaxDynamicSharedMemorySize, HG_SMEM);
    cudaFuncSetAttribute(hgemm_k<5, false>, cudaFuncAttributeMaxDynamicSharedMemorySize, HG_SMEM);

    dim3 blk(256);
    dim3 tblk(32, 8);

    __half *xhi, *xlo, *fw1hi, *fw1lo, *fw2h, *fw2nhi, *fw2nlo, *kwhi, *kwlo;
    __half *ew1h, *ew2h, *ew3h;
    float  *zbias;
    cudaGetSymbolAddress((void**)&xhi,    g_xhi);
    cudaGetSymbolAddress((void**)&xlo,    g_xlo);
    cudaGetSymbolAddress((void**)&fw1hi,  g_fw1hi);
    cudaGetSymbolAddress((void**)&fw1lo,  g_fw1lo);
    cudaGetSymbolAddress((void**)&fw2h,   g_fw2h);
    cudaGetSymbolAddress((void**)&fw2nhi, g_fw2nhi);
    cudaGetSymbolAddress((void**)&fw2nlo, g_fw2nlo);
    cudaGetSymbolAddress((void**)&kwhi,   g_kwhi);
    cudaGetSymbolAddress((void**)&kwlo,   g_kwlo);
    cudaGetSymbolAddress((void**)&ew1h,   g_ew1h);
    cudaGetSymbolAddress((void**)&ew2h,   g_ew2h);
    cudaGetSymbolAddress((void**)&ew3h,   g_ew3h);
    cudaGetSymbolAddress((void**)&zbias,  g_zbias);

    // side stream + events (created fresh each call; host-side objects only)
    cudaStream_t s2;
    cudaStreamCreateWithFlags(&s2, cudaStreamNonBlocking);
    cudaEvent_t evFork, evJoin;
    cudaEventCreateWithFlags(&evFork, cudaEventDisableTiming);
    cudaEventCreateWithFlags(&evJoin, cudaEventDisableTiming);

    // fork: s2 branches off the (captured) default stream
    cudaEventRecord(evFork, 0);
    cudaStreamWaitEvent(s2, evFork, 0);

    // ---- side stream: everything not needed by stage0 ----
    natsplit_k<<<HDIM * HDIM / 4 / 256, 256, 0, s2>>>(fw2, fw2nhi, fw2nlo);
    wsplit_k<<<dim3(KDIM / 32, HDIM / 32), tblk, 0, s2>>>(kw, kwhi, kwlo, HDIM, KDIM);
    bprime_k<<<KDIM, 256, 0, s2>>>(fb2, kw, kb);
    wconv_k<<<dim3(HDIM / 32,        HDIM / 32,  1   ), tblk, 0, s2>>>(fw2, fw2h, HDIM,  HDIM);
    sgemm_k<7, false><<<dim3(HDIM / 64, 1), blk, SG2_SMEM, s2>>>(fw2nhi, fw2nlo, zbias, HDIM, HDIM);
    wconv_k<<<dim3(HDIM / 32,        HDIM / 32,  EDIM), tblk, 0, s2>>>(ew1, ew1h, HDIM,  HDIM);
    wconv_k<<<dim3(H2DIM / 32,       HDIM / 32,  EDIM), tblk, 0, s2>>>(ew2, ew2h, HDIM,  H2DIM);
    wconv_k<<<dim3((CDIM + 31) / 32, H2DIM / 32, EDIM), tblk, 0, s2>>>(ew3, ew3h, H2DIM, CDIM);
    keysn_kernel<<<1, 256, 0, s2>>>(keys);
    zero_counts_kernel<<<1, 32, 0, s2>>>();
    cudaEventRecord(evJoin, s2);

    // ---- main stream: stage0 dependency chain ----
    natsplit_k<<<BDIM * DDIM / 4 / 256, 256>>>(x, xhi, xlo);
    wsplit_k<<<dim3(HDIM / 32, DDIM / 32), tblk>>>(fw1, fw1hi, fw1lo, DDIM, HDIM);

    // stage0: x @ fw1 -> h split (fp32-grade, relu), 128x64 tiles, 2 CTAs/SM
    sgemm_k<0, true ><<<dim3(HDIM / 64, BDIM / 128), blk, SG2_SMEM>>>(fw1hi, fw1lo, fb1, HDIM, DDIM);

    // join: stage1/stage2/router/experts need the side-stream results
    cudaStreamWaitEvent(0, evJoin, 0);

    // stage1: h @ fw2 -> feats (fp16, 2 CTAs/SM)
    hgemm_k<1, false><<<dim3(HDIM / 128, BDIM / 128, 1), blk, HG_SMEM>>>(fw2h, fb2, HDIM, HDIM);

    // stage2: h @ W' -> pk, K split over 2 grid planes (128 CTAs)
    stage2s_k<<<dim3(1, BDIM / 128, 2), blk, ST2_SMEM>>>();

    router_kernel<<<BDIM / 8, 256>>>();
    scan_kernel<<<1, 32>>>();
    scatter_kernel<<<(BDIM + 255) / 256, 256>>>();

    // expert MLPs: fp16 HMMA, 2 CTAs/SM
    hgemm_k<3, true ><<<dim3(HDIM / 128,         BDIM / 128, EDIM), blk, HG_SMEM>>>(ew1h, eb1, HDIM,  HDIM);
    hgemm_k<4, true ><<<dim3(H2DIM / 128,        BDIM / 128, EDIM), blk, HG_SMEM>>>(ew2h, eb2, H2DIM, HDIM);
    hgemm_k<5, false><<<dim3((CDIM + 127) / 128, BDIM / 128, EDIM), blk, HG_SMEM>>>(ew3h, eb3, CDIM,  H2DIM);

    combine_kernel<<<BDIM, 256>>>(out);
    tail_writer_kernel<<<(BDIM * EDIM + 255) / 256, 256>>>(out, (long long)out_size);
}